// round 1
// baseline (speedup 1.0000x reference)
#include <cuda_runtime.h>
#include <math_constants.h>
#include <cstddef>

#define S_LEN  2048
#define DIMM   2048
#define NHEADS 16
#define HD     128
#define QKV_W  6144      // (16 + 2*16) * 128
#define BATCH  2

#define BQ  64           // query tile
#define BKV 64           // key/value tile
#define PS_K 68          // padded stride for transposed q/k tiles (must be %4==0)
#define PS_P 66          // padded stride for score tile

// Scratch (allocation-free rule: __device__ globals)
__device__ float g_qkv[(size_t)BATCH * S_LEN * QKV_W];   // ~100.7 MB
__device__ float g_att[(size_t)BATCH * S_LEN * DIMM];    // ~33.6 MB

// ---------------------------------------------------------------------------
// Classic SGEMM: C[M,N] = A[M,K] @ B[K,N], all row-major, fp32.
// 128x128 block, BK=8, 256 threads, 8x8 per thread, register prefetch.
// Assumes M%128==0, N%128==0, K%8==0 (true for all shapes here).
// ---------------------------------------------------------------------------
__global__ __launch_bounds__(256, 2) void sgemm128(
    const float* __restrict__ A, const float* __restrict__ B,
    float* __restrict__ C, int M, int N, int K)
{
    __shared__ float As[8][128];   // A transposed: As[k][m]
    __shared__ float Bs[8][128];   // Bs[k][n]

    const int tid = threadIdx.x;
    const int bm = blockIdx.y * 128;
    const int bn = blockIdx.x * 128;

    const int aRow = tid >> 1;            // 0..127
    const int aCol = (tid & 1) * 4;       // 0 or 4
    const int bRow = tid >> 5;            // 0..7
    const int bCol = (tid & 31) * 4;      // 0..124

    const float* Abase = A + (size_t)(bm + aRow) * K + aCol;
    const float* Bbase = B + (size_t)bRow * N + bn + bCol;

    const int ty = tid >> 4;              // 0..15 (m dir)
    const int tx = tid & 15;              // 0..15 (n dir)

    float4 aReg = *(const float4*)(Abase);
    float4 bReg = *(const float4*)(Bbase);

    float acc[8][8];
    #pragma unroll
    for (int i = 0; i < 8; i++)
        #pragma unroll
        for (int j = 0; j < 8; j++) acc[i][j] = 0.0f;

    for (int k0 = 0; k0 < K; k0 += 8) {
        // store current tile to smem
        As[aCol + 0][aRow] = aReg.x;
        As[aCol + 1][aRow] = aReg.y;
        As[aCol + 2][aRow] = aReg.z;
        As[aCol + 3][aRow] = aReg.w;
        *(float4*)&Bs[bRow][bCol] = bReg;
        __syncthreads();

        // prefetch next tile into registers (overlaps with compute)
        if (k0 + 8 < K) {
            aReg = *(const float4*)(Abase + k0 + 8);
            bReg = *(const float4*)(Bbase + (size_t)(k0 + 8) * N);
        }

        #pragma unroll
        for (int kk = 0; kk < 8; kk++) {
            float4 a0 = *(const float4*)&As[kk][ty * 8];
            float4 a1 = *(const float4*)&As[kk][ty * 8 + 4];
            float4 b0 = *(const float4*)&Bs[kk][tx * 8];
            float4 b1 = *(const float4*)&Bs[kk][tx * 8 + 4];
            float av[8] = {a0.x, a0.y, a0.z, a0.w, a1.x, a1.y, a1.z, a1.w};
            float bv[8] = {b0.x, b0.y, b0.z, b0.w, b1.x, b1.y, b1.z, b1.w};
            #pragma unroll
            for (int i = 0; i < 8; i++)
                #pragma unroll
                for (int j = 0; j < 8; j++)
                    acc[i][j] += av[i] * bv[j];
        }
        __syncthreads();
    }

    #pragma unroll
    for (int i = 0; i < 8; i++) {
        float* crow = C + (size_t)(bm + ty * 8 + i) * N + bn + tx * 8;
        *(float4*)(crow)     = make_float4(acc[i][0], acc[i][1], acc[i][2], acc[i][3]);
        *(float4*)(crow + 4) = make_float4(acc[i][4], acc[i][5], acc[i][6], acc[i][7]);
    }
}

// ---------------------------------------------------------------------------
// Flash attention, fp32. One block per (b, h, 64-query tile). 256 threads.
// qkv layout: [b][s][48*128], heads 0..15 = Q, 16..31 = K, 32..47 = V.
// Output: att[b][s][h*128 + d]  (row-major [4096][2048])
// ---------------------------------------------------------------------------
__global__ __launch_bounds__(256, 1) void attn_kernel(
    const float* __restrict__ qkv, float* __restrict__ out)
{
    extern __shared__ float sm[];
    float* qT = sm;                        // [128][PS_K]  (qT[d][q], pre-scaled)
    float* kT = qT + 128 * PS_K;           // [128][PS_K]  (kT[d][t])
    float* vs = kT + 128 * PS_K;           // [BKV][128]   (natural)
    float* ps = vs + BKV * HD;             // [BQ][PS_P]   (probabilities)

    const int tid = threadIdx.x;
    const int q0  = blockIdx.x * BQ;
    const int h   = blockIdx.y;
    const int b   = blockIdx.z;
    const int ty  = tid >> 4;              // 0..15 (query dir, 4 rows each)
    const int tx  = tid & 15;              // 0..15 (key / out-col dir)
    const float scale = 0.08838834764831845f;  // 1/sqrt(128)

    const float* qbase = qkv + (size_t)b * S_LEN * QKV_W + h * HD;
    const float* kbase = qbase + NHEADS * HD;
    const float* vbase = qbase + 2 * NHEADS * HD;

    // Load Q tile transposed, folded scale
    {
        const int d = tid & 127, half = tid >> 7;
        #pragma unroll 8
        for (int r = 0; r < BQ / 2; r++) {
            int t = half + 2 * r;
            qT[d * PS_K + t] = qbase[(size_t)(q0 + t) * QKV_W + d] * scale;
        }
    }

    float o[4][8];
    float mrun[4], lrun[4];
    #pragma unroll
    for (int i = 0; i < 4; i++) {
        mrun[i] = -CUDART_INF_F;
        lrun[i] = 0.0f;
        #pragma unroll
        for (int j = 0; j < 8; j++) o[i][j] = 0.0f;
    }

    for (int kt = 0; kt < S_LEN / BKV; kt++) {
        __syncthreads();   // prev tile's P·V done (also covers the Q load on iter 0)

        // Load K tile transposed
        {
            const int d = tid & 127, half = tid >> 7;
            #pragma unroll 8
            for (int r = 0; r < BKV / 2; r++) {
                int t = half + 2 * r;
                kT[d * PS_K + t] = kbase[(size_t)(kt * BKV + t) * QKV_W + d];
            }
        }
        // Load V tile natural (float4)
        {
            const int d4 = (tid & 31) * 4;
            const int tr = tid >> 5;
            #pragma unroll
            for (int r = 0; r < BKV / 8; r++) {
                int t = tr + 8 * r;
                *(float4*)&vs[t * HD + d4] =
                    *(const float4*)&vbase[(size_t)(kt * BKV + t) * QKV_W + d4];
            }
        }
        __syncthreads();

        // S = Q·K^T : 4x4 per thread, over d=0..127
        float s[4][4];
        #pragma unroll
        for (int i = 0; i < 4; i++)
            #pragma unroll
            for (int j = 0; j < 4; j++) s[i][j] = 0.0f;

        #pragma unroll 8
        for (int d = 0; d < HD; d++) {
            float4 qv = *(const float4*)&qT[d * PS_K + ty * 4];
            float4 kv = *(const float4*)&kT[d * PS_K + tx * 4];
            float qa[4] = {qv.x, qv.y, qv.z, qv.w};
            float ka[4] = {kv.x, kv.y, kv.z, kv.w};
            #pragma unroll
            for (int i = 0; i < 4; i++)
                #pragma unroll
                for (int j = 0; j < 4; j++)
                    s[i][j] += qa[i] * ka[j];
        }

        // Online softmax (row stats shared by the 16 lanes of each ty group)
        #pragma unroll
        for (int i = 0; i < 4; i++) {
            float m = fmaxf(fmaxf(s[i][0], s[i][1]), fmaxf(s[i][2], s[i][3]));
            #pragma unroll
            for (int off = 8; off >= 1; off >>= 1)
                m = fmaxf(m, __shfl_xor_sync(0xffffffffu, m, off));
            float mnew  = fmaxf(mrun[i], m);
            float alpha = __expf(mrun[i] - mnew);
            mrun[i] = mnew;

            float lsum = 0.0f;
            #pragma unroll
            for (int j = 0; j < 4; j++) {
                float p = __expf(s[i][j] - mnew);
                ps[(ty * 4 + i) * PS_P + tx * 4 + j] = p;
                lsum += p;
            }
            #pragma unroll
            for (int off = 8; off >= 1; off >>= 1)
                lsum += __shfl_xor_sync(0xffffffffu, lsum, off);
            lrun[i] = lrun[i] * alpha + lsum;
            #pragma unroll
            for (int jj = 0; jj < 8; jj++) o[i][jj] *= alpha;
        }
        __syncthreads();

        // O += P·V : 4 rows x 8 cols per thread (cols at tx*8)
        #pragma unroll 4
        for (int kk = 0; kk < BKV; kk++) {
            float4 v0 = *(const float4*)&vs[kk * HD + tx * 8];
            float4 v1 = *(const float4*)&vs[kk * HD + tx * 8 + 4];
            #pragma unroll
            for (int i = 0; i < 4; i++) {
                float p = ps[(ty * 4 + i) * PS_P + kk];
                o[i][0] += p * v0.x; o[i][1] += p * v0.y;
                o[i][2] += p * v0.z; o[i][3] += p * v0.w;
                o[i][4] += p * v1.x; o[i][5] += p * v1.y;
                o[i][6] += p * v1.z; o[i][7] += p * v1.w;
            }
        }
    }

    // Epilogue: normalize and write att[b][q][h*128 + c]
    #pragma unroll
    for (int i = 0; i < 4; i++) {
        float inv = 1.0f / lrun[i];
        size_t row = (size_t)b * S_LEN + q0 + ty * 4 + i;
        float* op = out + row * DIMM + h * HD + tx * 8;
        *(float4*)(op)     = make_float4(o[i][0] * inv, o[i][1] * inv,
                                         o[i][2] * inv, o[i][3] * inv);
        *(float4*)(op + 4) = make_float4(o[i][4] * inv, o[i][5] * inv,
                                         o[i][6] * inv, o[i][7] * inv);
    }
}

// ---------------------------------------------------------------------------
extern "C" void kernel_launch(void* const* d_in, const int* in_sizes, int n_in,
                              void* d_out, int out_size)
{
    const float* x     = (const float*)d_in[0];   // [2,2048,2048]
    const float* w_qkv = (const float*)d_in[1];   // [2048,6144]
    const float* w_out = (const float*)d_in[2];   // [2048,2048]
    float* out = (float*)d_out;                   // [2,2048,2048]

    float *qkv_ptr, *att_ptr;
    cudaGetSymbolAddress((void**)&qkv_ptr, g_qkv);
    cudaGetSymbolAddress((void**)&att_ptr, g_att);

    // 1) QKV projection: [4096,2048] @ [2048,6144]
    {
        dim3 grid(QKV_W / 128, (BATCH * S_LEN) / 128);
        sgemm128<<<grid, 256>>>(x, w_qkv, qkv_ptr, BATCH * S_LEN, QKV_W, DIMM);
    }

    // 2) Attention
    {
        int smem = (2 * 128 * PS_K + BKV * HD + BQ * PS_P) * (int)sizeof(float);
        cudaFuncSetAttribute(attn_kernel,
                             cudaFuncAttributeMaxDynamicSharedMemorySize, smem);
        dim3 grid(S_LEN / BQ, NHEADS, BATCH);
        attn_kernel<<<grid, 256, smem>>>(qkv_ptr, att_ptr);
    }

    // 3) Output projection: [4096,2048] @ [2048,2048]
    {
        dim3 grid(DIMM / 128, (BATCH * S_LEN) / 128);
        sgemm128<<<grid, 256>>>(att_ptr, w_out, out, BATCH * S_LEN, DIMM, DIMM);
    }
}

// round 3
// speedup vs baseline: 1.2946x; 1.2946x over previous
#include <cuda_runtime.h>
#include <cuda_bf16.h>
#include <math_constants.h>
#include <cstdint>
#include <cstddef>

#define S_LEN  2048
#define DIMM   2048
#define NHEADS 16
#define HD     128
#define QKV_W  6144
#define BATCH  2
#define MROWS  (BATCH * S_LEN)   // 4096

// attention tiling
#define BQ  64
#define BKV 64
#define PS_K 68
#define PS_P 66

// ---------------------------------------------------------------------------
// Scratch (__device__ globals: allocation-free rule)
// ---------------------------------------------------------------------------
__device__ float          g_qkv[(size_t)MROWS * QKV_W];
__device__ float          g_att[(size_t)MROWS * DIMM];
__device__ __nv_bfloat16  g_xh[(size_t)MROWS * DIMM];
__device__ __nv_bfloat16  g_xl[(size_t)MROWS * DIMM];
__device__ __nv_bfloat16  g_wqT_h[(size_t)QKV_W * DIMM];   // [6144,2048] K-major (B^T)
__device__ __nv_bfloat16  g_wqT_l[(size_t)QKV_W * DIMM];
__device__ __nv_bfloat16  g_woT_h[(size_t)DIMM * DIMM];    // [2048,2048] K-major
__device__ __nv_bfloat16  g_woT_l[(size_t)DIMM * DIMM];
__device__ __nv_bfloat16  g_ah[(size_t)MROWS * DIMM];
__device__ __nv_bfloat16  g_al[(size_t)MROWS * DIMM];

// ---------------------------------------------------------------------------
// helpers
// ---------------------------------------------------------------------------
__device__ __forceinline__ uint32_t smem_u32(const void* p) {
    uint32_t a;
    asm("{ .reg .u64 t; cvta.to.shared.u64 t, %1; cvt.u32.u64 %0, t; }"
        : "=r"(a) : "l"(p));
    return a;
}
__device__ __forceinline__ void cp16(uint32_t dst, const void* src) {
    asm volatile("cp.async.cg.shared.global [%0], [%1], 16;"
                 :: "r"(dst), "l"(src) : "memory");
}
__device__ __forceinline__ void cp_commit() {
    asm volatile("cp.async.commit_group;" ::: "memory");
}
__device__ __forceinline__ void cp_wait1() {
    asm volatile("cp.async.wait_group 1;" ::: "memory");
}
__device__ __forceinline__ void cp_wait0() {
    asm volatile("cp.async.wait_group 0;" ::: "memory");
}
__device__ __forceinline__ void mma_bf16(float* d, const uint32_t* a,
                                         const uint32_t* b) {
    asm volatile(
        "mma.sync.aligned.m16n8k16.row.col.f32.bf16.bf16.f32 "
        "{%0,%1,%2,%3}, {%4,%5,%6,%7}, {%8,%9}, {%0,%1,%2,%3};"
        : "+f"(d[0]), "+f"(d[1]), "+f"(d[2]), "+f"(d[3])
        : "r"(a[0]), "r"(a[1]), "r"(a[2]), "r"(a[3]), "r"(b[0]), "r"(b[1]));
}

// ---------------------------------------------------------------------------
// Conversion kernels
// ---------------------------------------------------------------------------
__global__ void split_kernel(const float* __restrict__ in,
                             __nv_bfloat16* __restrict__ hi,
                             __nv_bfloat16* __restrict__ lo, int n4)
{
    int i = blockIdx.x * blockDim.x + threadIdx.x;
    if (i >= n4) return;
    float4 v = ((const float4*)in)[i];
    __nv_bfloat16 h0 = __float2bfloat16_rn(v.x);
    __nv_bfloat16 h1 = __float2bfloat16_rn(v.y);
    __nv_bfloat16 h2 = __float2bfloat16_rn(v.z);
    __nv_bfloat16 h3 = __float2bfloat16_rn(v.w);
    __nv_bfloat162* H = (__nv_bfloat162*)(hi) + i * 2;
    __nv_bfloat162* L = (__nv_bfloat162*)(lo) + i * 2;
    H[0] = __nv_bfloat162(h0, h1);
    H[1] = __nv_bfloat162(h2, h3);
    L[0] = __nv_bfloat162(__float2bfloat16_rn(v.x - __bfloat162float(h0)),
                          __float2bfloat16_rn(v.y - __bfloat162float(h1)));
    L[1] = __nv_bfloat162(__float2bfloat16_rn(v.z - __bfloat162float(h2)),
                          __float2bfloat16_rn(v.w - __bfloat162float(h3)));
}

// in [R,C] fp32 -> out [C,R] bf16 hi/lo
__global__ void transpose_split(const float* __restrict__ in,
                                __nv_bfloat16* __restrict__ oh,
                                __nv_bfloat16* __restrict__ ol, int R, int C)
{
    __shared__ float t[32][33];
    int bx = blockIdx.x * 32, by = blockIdx.y * 32;
    int x = threadIdx.x, y = threadIdx.y;           // 32 x 8
    #pragma unroll
    for (int i = 0; i < 32; i += 8)
        t[y + i][x] = in[(size_t)(by + y + i) * C + bx + x];
    __syncthreads();
    #pragma unroll
    for (int i = 0; i < 32; i += 8) {
        float v = t[x][y + i];
        size_t o = (size_t)(bx + y + i) * R + by + x;
        __nv_bfloat16 h = __float2bfloat16_rn(v);
        oh[o] = h;
        ol[o] = __float2bfloat16_rn(v - __bfloat162float(h));
    }
}

// ---------------------------------------------------------------------------
// mma.sync bf16-split GEMM: C[M,N] fp32 = A[M,K] @ B^T
//   A (hi/lo): [M,K] K-major bf16;  Bt (hi/lo): [N,K] K-major bf16.
// CTA: 128x128 tile, BK=32, 256 threads (8 warps, 2x4 -> warp tile 64x32).
// 2-stage cp.async pipeline. 3-term split: Ah*Bh + Al*Bh + Ah*Bl.
// ---------------------------------------------------------------------------
#define PADB 80                    // padded row stride in bytes (40 bf16)
#define TILE_B (128 * PADB)        // 10240 B per operand tile
#define STAGE_B (4 * TILE_B)       // Ah, Al, Bh, Bl
#define GEMM_SMEM (2 * STAGE_B)    // 81920 B

__global__ __launch_bounds__(256, 1) void gemm_mma(
    const __nv_bfloat16* __restrict__ Ah, const __nv_bfloat16* __restrict__ Al,
    const __nv_bfloat16* __restrict__ Bh, const __nv_bfloat16* __restrict__ Bl,
    float* __restrict__ C, int M, int N, int K)
{
    extern __shared__ char smem[];
    const uint32_t smem_base = smem_u32(smem);
    const int tid  = threadIdx.x;
    const int wid  = tid >> 5;
    const int lane = tid & 31;
    const int wm   = wid & 1;          // 0..1  (m dir, 64 rows)
    const int wn   = wid >> 1;         // 0..3  (n dir, 32 cols)
    const int bm = blockIdx.y * 128;
    const int bn = blockIdx.x * 128;

    const int lr = tid >> 1;           // load row 0..127
    const int lc = tid & 1;            // load chunk base 0..1

    const int r0 = lane >> 2;          // 0..7
    const int c0 = (lane & 3) * 2;     // 0,2,4,6

    float acc[4][4][4];
    #pragma unroll
    for (int mt = 0; mt < 4; mt++)
        #pragma unroll
        for (int nt = 0; nt < 4; nt++)
            #pragma unroll
            for (int j = 0; j < 4; j++) acc[mt][nt][j] = 0.0f;

    const int NC = K / 32;

    // async-load one 128x32 bf16 tile into smem (padded rows)
    auto issue_tile = [&](const __nv_bfloat16* src, int row0, int k0,
                          uint32_t dstbase) {
        const char* g = (const char*)(src + (size_t)(row0 + lr) * K + k0)
                        + lc * 16;
        uint32_t d = dstbase + lr * PADB + lc * 16;
        cp16(d, g);
        cp16(d + 32, g + 32);
    };
    auto issue_stage = [&](int c, int st) {
        uint32_t base = smem_base + st * STAGE_B;
        int k0 = c * 32;
        issue_tile(Ah, bm, k0, base);
        issue_tile(Al, bm, k0, base + TILE_B);
        issue_tile(Bh, bn, k0, base + 2 * TILE_B);
        issue_tile(Bl, bn, k0, base + 3 * TILE_B);
    };

    issue_stage(0, 0);
    cp_commit();

    for (int c = 0; c < NC; c++) {
        if (c + 1 < NC) {
            issue_stage(c + 1, (c + 1) & 1);
            cp_commit();
            cp_wait1();
        } else {
            cp_wait0();
        }
        __syncthreads();

        const char* sAh = smem + (c & 1) * STAGE_B;
        const char* sAl = sAh + TILE_B;
        const char* sBh = sAh + 2 * TILE_B;
        const char* sBl = sAh + 3 * TILE_B;

        #pragma unroll
        for (int ks = 0; ks < 2; ks++) {
            uint32_t ah[4][4], al[4][4], bh[4][2], bl[4][2];
            const int kb = (ks * 16 + c0) * 2;   // byte offset in row

            #pragma unroll
            for (int mt = 0; mt < 4; mt++) {
                int row = wm * 64 + mt * 16 + r0;
                const char* ph = sAh + row * PADB + kb;
                const char* pl = sAl + row * PADB + kb;
                ah[mt][0] = *(const uint32_t*)(ph);
                ah[mt][1] = *(const uint32_t*)(ph + 8 * PADB);
                ah[mt][2] = *(const uint32_t*)(ph + 16);
                ah[mt][3] = *(const uint32_t*)(ph + 8 * PADB + 16);
                al[mt][0] = *(const uint32_t*)(pl);
                al[mt][1] = *(const uint32_t*)(pl + 8 * PADB);
                al[mt][2] = *(const uint32_t*)(pl + 16);
                al[mt][3] = *(const uint32_t*)(pl + 8 * PADB + 16);
            }
            #pragma unroll
            for (int nt = 0; nt < 4; nt++) {
                int n = wn * 32 + nt * 8 + r0;
                const char* ph = sBh + n * PADB + kb;
                const char* pl = sBl + n * PADB + kb;
                bh[nt][0] = *(const uint32_t*)(ph);
                bh[nt][1] = *(const uint32_t*)(ph + 16);
                bl[nt][0] = *(const uint32_t*)(pl);
                bl[nt][1] = *(const uint32_t*)(pl + 16);
            }

            #pragma unroll
            for (int mt = 0; mt < 4; mt++)
                #pragma unroll
                for (int nt = 0; nt < 4; nt++)
                    mma_bf16(acc[mt][nt], ah[mt], bh[nt]);
            #pragma unroll
            for (int mt = 0; mt < 4; mt++)
                #pragma unroll
                for (int nt = 0; nt < 4; nt++)
                    mma_bf16(acc[mt][nt], al[mt], bh[nt]);
            #pragma unroll
            for (int mt = 0; mt < 4; mt++)
                #pragma unroll
                for (int nt = 0; nt < 4; nt++)
                    mma_bf16(acc[mt][nt], ah[mt], bl[nt]);
        }
        __syncthreads();
    }

    // epilogue
    #pragma unroll
    for (int mt = 0; mt < 4; mt++) {
        int row = bm + wm * 64 + mt * 16 + r0;
        #pragma unroll
        for (int nt = 0; nt < 4; nt++) {
            int col = bn + wn * 32 + nt * 8 + c0;
            float* p0 = C + (size_t)row * N + col;
            float* p1 = p0 + 8 * (size_t)N;
            *(float2*)p0 = make_float2(acc[mt][nt][0], acc[mt][nt][1]);
            *(float2*)p1 = make_float2(acc[mt][nt][2], acc[mt][nt][3]);
        }
    }
}

// ---------------------------------------------------------------------------
// Flash attention, fp32 (unchanged from R1)
// ---------------------------------------------------------------------------
__global__ __launch_bounds__(256, 1) void attn_kernel(
    const float* __restrict__ qkv, float* __restrict__ out)
{
    extern __shared__ float sm[];
    float* qT = sm;
    float* kT = qT + 128 * PS_K;
    float* vs = kT + 128 * PS_K;
    float* ps = vs + BKV * HD;

    const int tid = threadIdx.x;
    const int q0  = blockIdx.x * BQ;
    const int h   = blockIdx.y;
    const int b   = blockIdx.z;
    const int ty  = tid >> 4;
    const int tx  = tid & 15;
    const float scale = 0.08838834764831845f;

    const float* qbase = qkv + (size_t)b * S_LEN * QKV_W + h * HD;
    const float* kbase = qbase + NHEADS * HD;
    const float* vbase = qbase + 2 * NHEADS * HD;

    {
        const int d = tid & 127, half = tid >> 7;
        #pragma unroll 8
        for (int r = 0; r < BQ / 2; r++) {
            int t = half + 2 * r;
            qT[d * PS_K + t] = qbase[(size_t)(q0 + t) * QKV_W + d] * scale;
        }
    }

    float o[4][8];
    float mrun[4], lrun[4];
    #pragma unroll
    for (int i = 0; i < 4; i++) {
        mrun[i] = -CUDART_INF_F;
        lrun[i] = 0.0f;
        #pragma unroll
        for (int j = 0; j < 8; j++) o[i][j] = 0.0f;
    }

    for (int kt = 0; kt < S_LEN / BKV; kt++) {
        __syncthreads();
        {
            const int d = tid & 127, half = tid >> 7;
            #pragma unroll 8
            for (int r = 0; r < BKV / 2; r++) {
                int t = half + 2 * r;
                kT[d * PS_K + t] = kbase[(size_t)(kt * BKV + t) * QKV_W + d];
            }
        }
        {
            const int d4 = (tid & 31) * 4;
            const int tr = tid >> 5;
            #pragma unroll
            for (int r = 0; r < BKV / 8; r++) {
                int t = tr + 8 * r;
                *(float4*)&vs[t * HD + d4] =
                    *(const float4*)&vbase[(size_t)(kt * BKV + t) * QKV_W + d4];
            }
        }
        __syncthreads();

        float s[4][4];
        #pragma unroll
        for (int i = 0; i < 4; i++)
            #pragma unroll
            for (int j = 0; j < 4; j++) s[i][j] = 0.0f;

        #pragma unroll 8
        for (int d = 0; d < HD; d++) {
            float4 qv = *(const float4*)&qT[d * PS_K + ty * 4];
            float4 kv = *(const float4*)&kT[d * PS_K + tx * 4];
            float qa[4] = {qv.x, qv.y, qv.z, qv.w};
            float ka[4] = {kv.x, kv.y, kv.z, kv.w};
            #pragma unroll
            for (int i = 0; i < 4; i++)
                #pragma unroll
                for (int j = 0; j < 4; j++)
                    s[i][j] += qa[i] * ka[j];
        }

        #pragma unroll
        for (int i = 0; i < 4; i++) {
            float m = fmaxf(fmaxf(s[i][0], s[i][1]), fmaxf(s[i][2], s[i][3]));
            #pragma unroll
            for (int off = 8; off >= 1; off >>= 1)
                m = fmaxf(m, __shfl_xor_sync(0xffffffffu, m, off));
            float mnew  = fmaxf(mrun[i], m);
            float alpha = __expf(mrun[i] - mnew);
            mrun[i] = mnew;

            float lsum = 0.0f;
            #pragma unroll
            for (int j = 0; j < 4; j++) {
                float p = __expf(s[i][j] - mnew);
                ps[(ty * 4 + i) * PS_P + tx * 4 + j] = p;
                lsum += p;
            }
            #pragma unroll
            for (int off = 8; off >= 1; off >>= 1)
                lsum += __shfl_xor_sync(0xffffffffu, lsum, off);
            lrun[i] = lrun[i] * alpha + lsum;
            #pragma unroll
            for (int jj = 0; jj < 8; jj++) o[i][jj] *= alpha;
        }
        __syncthreads();

        #pragma unroll 4
        for (int kk = 0; kk < BKV; kk++) {
            float4 v0 = *(const float4*)&vs[kk * HD + tx * 8];
            float4 v1 = *(const float4*)&vs[kk * HD + tx * 8 + 4];
            #pragma unroll
            for (int i = 0; i < 4; i++) {
                float p = ps[(ty * 4 + i) * PS_P + kk];
                o[i][0] += p * v0.x; o[i][1] += p * v0.y;
                o[i][2] += p * v0.z; o[i][3] += p * v0.w;
                o[i][4] += p * v1.x; o[i][5] += p * v1.y;
                o[i][6] += p * v1.z; o[i][7] += p * v1.w;
            }
        }
    }

    #pragma unroll
    for (int i = 0; i < 4; i++) {
        float inv = 1.0f / lrun[i];
        size_t row = (size_t)b * S_LEN + q0 + ty * 4 + i;
        float* op = out + row * DIMM + h * HD + tx * 8;
        *(float4*)(op)     = make_float4(o[i][0] * inv, o[i][1] * inv,
                                         o[i][2] * inv, o[i][3] * inv);
        *(float4*)(op + 4) = make_float4(o[i][4] * inv, o[i][5] * inv,
                                         o[i][6] * inv, o[i][7] * inv);
    }
}

// ---------------------------------------------------------------------------
extern "C" void kernel_launch(void* const* d_in, const int* in_sizes, int n_in,
                              void* d_out, int out_size)
{
    const float* x     = (const float*)d_in[0];   // [2,2048,2048]
    const float* w_qkv = (const float*)d_in[1];   // [2048,6144]
    const float* w_out = (const float*)d_in[2];   // [2048,2048]
    float* out = (float*)d_out;                   // [2,2048,2048]

    float *qkv_p, *att_p;
    __nv_bfloat16 *xh, *xl, *wqh, *wql, *woh, *wol, *ah, *al;
    cudaGetSymbolAddress((void**)&qkv_p, g_qkv);
    cudaGetSymbolAddress((void**)&att_p, g_att);
    cudaGetSymbolAddress((void**)&xh, g_xh);
    cudaGetSymbolAddress((void**)&xl, g_xl);
    cudaGetSymbolAddress((void**)&wqh, g_wqT_h);
    cudaGetSymbolAddress((void**)&wql, g_wqT_l);
    cudaGetSymbolAddress((void**)&woh, g_woT_h);
    cudaGetSymbolAddress((void**)&wol, g_woT_l);
    cudaGetSymbolAddress((void**)&ah, g_ah);
    cudaGetSymbolAddress((void**)&al, g_al);

    cudaFuncSetAttribute(gemm_mma, cudaFuncAttributeMaxDynamicSharedMemorySize,
                         GEMM_SMEM);

    // split x -> bf16 hi/lo
    {
        int n4 = (MROWS * DIMM) / 4;
        split_kernel<<<(n4 + 255) / 256, 256>>>(x, xh, xl, n4);
    }
    // transpose+split weights
    {
        dim3 t(32, 8);
        transpose_split<<<dim3(QKV_W / 32, DIMM / 32), t>>>(w_qkv, wqh, wql, DIMM, QKV_W);
        transpose_split<<<dim3(DIMM / 32, DIMM / 32), t>>>(w_out, woh, wol, DIMM, DIMM);
    }
    // 1) QKV projection: [4096,2048] @ [2048,6144]
    gemm_mma<<<dim3(QKV_W / 128, MROWS / 128), 256, GEMM_SMEM>>>(
        xh, xl, wqh, wql, qkv_p, MROWS, QKV_W, DIMM);

    // 2) Attention (fp32 SIMT)
    {
        int smem = (2 * 128 * PS_K + BKV * HD + BQ * PS_P) * (int)sizeof(float);
        cudaFuncSetAttribute(attn_kernel, cudaFuncAttributeMaxDynamicSharedMemorySize, smem);
        dim3 grid(S_LEN / BQ, NHEADS, BATCH);
        attn_kernel<<<grid, 256, smem>>>(qkv_p, att_p);
    }

    // split attention output
    {
        int n4 = (MROWS * DIMM) / 4;
        split_kernel<<<(n4 + 255) / 256, 256>>>(att_p, ah, al, n4);
    }
    // 3) Output projection: [4096,2048] @ [2048,2048]
    gemm_mma<<<dim3(DIMM / 128, MROWS / 128), 256, GEMM_SMEM>>>(
        ah, al, woh, wol, out, MROWS, DIMM, DIMM);
}

// round 4
// speedup vs baseline: 1.3136x; 1.0147x over previous
#include <cuda_runtime.h>
#include <cuda_bf16.h>
#include <math_constants.h>
#include <cstdint>
#include <cstddef>

#define S_LEN  2048
#define DIMM   2048
#define NHEADS 16
#define HD     128
#define QKV_W  6144
#define BATCH  2
#define MROWS  (BATCH * S_LEN)   // 4096

// attention tiling
#define BQ  64
#define BKV 64
#define PS_K 68
#define PS_P 66

// ---------------------------------------------------------------------------
// Scratch (__device__ globals: allocation-free rule)
// ---------------------------------------------------------------------------
__device__ float          g_qkv[(size_t)MROWS * QKV_W];
__device__ float          g_att[(size_t)MROWS * DIMM];
__device__ __nv_bfloat16  g_xh[(size_t)MROWS * DIMM];
__device__ __nv_bfloat16  g_xl[(size_t)MROWS * DIMM];
__device__ __nv_bfloat16  g_wqT_h[(size_t)QKV_W * DIMM];   // [6144,2048] K-major (B^T)
__device__ __nv_bfloat16  g_wqT_l[(size_t)QKV_W * DIMM];
__device__ __nv_bfloat16  g_woT_h[(size_t)DIMM * DIMM];    // [2048,2048] K-major
__device__ __nv_bfloat16  g_woT_l[(size_t)DIMM * DIMM];
__device__ __nv_bfloat16  g_ah[(size_t)MROWS * DIMM];
__device__ __nv_bfloat16  g_al[(size_t)MROWS * DIMM];

// ---------------------------------------------------------------------------
// helpers
// ---------------------------------------------------------------------------
__device__ __forceinline__ uint32_t smem_u32(const void* p) {
    uint32_t a;
    asm("{ .reg .u64 t; cvta.to.shared.u64 t, %1; cvt.u32.u64 %0, t; }"
        : "=r"(a) : "l"(p));
    return a;
}
__device__ __forceinline__ void cp16(uint32_t dst, const void* src) {
    asm volatile("cp.async.cg.shared.global [%0], [%1], 16;"
                 :: "r"(dst), "l"(src) : "memory");
}
__device__ __forceinline__ void cp_commit() {
    asm volatile("cp.async.commit_group;" ::: "memory");
}
__device__ __forceinline__ void cp_wait2() {
    asm volatile("cp.async.wait_group 2;" ::: "memory");
}
__device__ __forceinline__ void mma_bf16(float* d, const uint32_t* a,
                                         const uint32_t* b) {
    asm volatile(
        "mma.sync.aligned.m16n8k16.row.col.f32.bf16.bf16.f32 "
        "{%0,%1,%2,%3}, {%4,%5,%6,%7}, {%8,%9}, {%0,%1,%2,%3};"
        : "+f"(d[0]), "+f"(d[1]), "+f"(d[2]), "+f"(d[3])
        : "r"(a[0]), "r"(a[1]), "r"(a[2]), "r"(a[3]), "r"(b[0]), "r"(b[1]));
}
__device__ __forceinline__ void ldsm4(uint32_t* r, uint32_t addr) {
    asm volatile("ldmatrix.sync.aligned.m8n8.x4.shared.b16 {%0,%1,%2,%3}, [%4];"
                 : "=r"(r[0]), "=r"(r[1]), "=r"(r[2]), "=r"(r[3]) : "r"(addr));
}

// ---------------------------------------------------------------------------
// Conversion kernels
// ---------------------------------------------------------------------------
__global__ void split_kernel(const float* __restrict__ in,
                             __nv_bfloat16* __restrict__ hi,
                             __nv_bfloat16* __restrict__ lo, int n4)
{
    int i = blockIdx.x * blockDim.x + threadIdx.x;
    if (i >= n4) return;
    float4 v = ((const float4*)in)[i];
    __nv_bfloat16 h0 = __float2bfloat16_rn(v.x);
    __nv_bfloat16 h1 = __float2bfloat16_rn(v.y);
    __nv_bfloat16 h2 = __float2bfloat16_rn(v.z);
    __nv_bfloat16 h3 = __float2bfloat16_rn(v.w);
    __nv_bfloat162* H = (__nv_bfloat162*)(hi) + i * 2;
    __nv_bfloat162* L = (__nv_bfloat162*)(lo) + i * 2;
    H[0] = __nv_bfloat162(h0, h1);
    H[1] = __nv_bfloat162(h2, h3);
    L[0] = __nv_bfloat162(__float2bfloat16_rn(v.x - __bfloat162float(h0)),
                          __float2bfloat16_rn(v.y - __bfloat162float(h1)));
    L[1] = __nv_bfloat162(__float2bfloat16_rn(v.z - __bfloat162float(h2)),
                          __float2bfloat16_rn(v.w - __bfloat162float(h3)));
}

// in [R,C] fp32 -> out [C,R] bf16 hi/lo
__global__ void transpose_split(const float* __restrict__ in,
                                __nv_bfloat16* __restrict__ oh,
                                __nv_bfloat16* __restrict__ ol, int R, int C)
{
    __shared__ float t[32][33];
    int bx = blockIdx.x * 32, by = blockIdx.y * 32;
    int x = threadIdx.x, y = threadIdx.y;           // 32 x 8
    #pragma unroll
    for (int i = 0; i < 32; i += 8)
        t[y + i][x] = in[(size_t)(by + y + i) * C + bx + x];
    __syncthreads();
    #pragma unroll
    for (int i = 0; i < 32; i += 8) {
        float v = t[x][y + i];
        size_t o = (size_t)(bx + y + i) * R + by + x;
        __nv_bfloat16 h = __float2bfloat16_rn(v);
        oh[o] = h;
        ol[o] = __float2bfloat16_rn(v - __bfloat162float(h));
    }
}

// ---------------------------------------------------------------------------
// mma.sync bf16-split GEMM: C[M,N] fp32 = A[M,K] @ B^T
//   A (hi/lo): [M,K] K-major bf16;  Bt (hi/lo): [N,K] K-major bf16.
// CTA: 128x128 tile, BK=32, 256 threads (8 warps, 2x4 -> warp tile 64x32).
// 3-stage cp.async pipeline, ldmatrix.x4 fragment loads.
// 3-term split: Ah*Bh + Al*Bh + Ah*Bl.
// ---------------------------------------------------------------------------
#define PADB 80                    // padded row stride in bytes (40 bf16)
#define TILE_B (128 * PADB)        // 10240 B per operand tile
#define STAGE_B (4 * TILE_B)       // Ah, Al, Bh, Bl
#define NSTAGE 3
#define GEMM_SMEM (NSTAGE * STAGE_B)   // 122880 B

__global__ __launch_bounds__(256, 1) void gemm_mma(
    const __nv_bfloat16* __restrict__ Ah, const __nv_bfloat16* __restrict__ Al,
    const __nv_bfloat16* __restrict__ Bh, const __nv_bfloat16* __restrict__ Bl,
    float* __restrict__ C, int M, int N, int K)
{
    extern __shared__ char smem[];
    const uint32_t smem_base = smem_u32(smem);
    const int tid  = threadIdx.x;
    const int wid  = tid >> 5;
    const int lane = tid & 31;
    const int wm   = wid & 1;          // 0..1  (m dir, 64 rows)
    const int wn   = wid >> 1;         // 0..3  (n dir, 32 cols)
    const int bm = blockIdx.y * 128;
    const int bn = blockIdx.x * 128;

    const int lr = tid >> 1;           // load row 0..127
    const int lc = tid & 1;            // load chunk base 0..1

    const int r0 = lane >> 2;          // 0..7
    const int c0 = (lane & 3) * 2;     // 0,2,4,6

    // ldmatrix lane address components (byte offsets within a tile)
    // A (16x16 tile): row = lane&15, +16B column for lanes 16-31
    const uint32_t a_lane_off = (uint32_t)((lane & 15) * PADB + ((lane >> 4) << 4));
    // B (two 8-row n-tiles per x4): rows lane&7 (+8 for lanes 16-31),
    // +16B k-column for lanes 8-15 / 24-31
    const uint32_t b_lane_off = (uint32_t)(((lane & 7) + ((lane >> 4) << 3)) * PADB
                                           + (((lane >> 3) & 1) << 4));

    float acc[4][4][4];
    #pragma unroll
    for (int mt = 0; mt < 4; mt++)
        #pragma unroll
        for (int nt = 0; nt < 4; nt++)
            #pragma unroll
            for (int j = 0; j < 4; j++) acc[mt][nt][j] = 0.0f;

    const int NC = K / 32;

    auto issue_tile = [&](const __nv_bfloat16* src, int row0, int k0,
                          uint32_t dstbase) {
        const char* g = (const char*)(src + (size_t)(row0 + lr) * K + k0)
                        + lc * 16;
        uint32_t d = dstbase + lr * PADB + lc * 16;
        cp16(d, g);
        cp16(d + 32, g + 32);
    };
    auto issue_stage = [&](int c) {
        uint32_t base = smem_base + (c % NSTAGE) * STAGE_B;
        int k0 = c * 32;
        issue_tile(Ah, bm, k0, base);
        issue_tile(Al, bm, k0, base + TILE_B);
        issue_tile(Bh, bn, k0, base + 2 * TILE_B);
        issue_tile(Bl, bn, k0, base + 3 * TILE_B);
    };

    #pragma unroll
    for (int s = 0; s < NSTAGE; s++) {
        if (s < NC) issue_stage(s);
        cp_commit();
    }

    for (int c = 0; c < NC; c++) {
        cp_wait2();            // stage c complete (3 groups max in flight)
        __syncthreads();

        const uint32_t sb  = smem_base + (c % NSTAGE) * STAGE_B;
        const uint32_t sAh = sb;
        const uint32_t sAl = sb + TILE_B;
        const uint32_t sBh = sb + 2 * TILE_B;
        const uint32_t sBl = sb + 3 * TILE_B;

        #pragma unroll
        for (int ks = 0; ks < 2; ks++) {
            const uint32_t kb = ks * 32;       // byte offset of k-slice
            uint32_t ah[4][4], al[4][4], bh[4][2], bl[4][2];

            #pragma unroll
            for (int mt = 0; mt < 4; mt++) {
                uint32_t rowoff = (uint32_t)((wm * 64 + mt * 16) * PADB) + kb
                                  + a_lane_off;
                ldsm4(ah[mt], sAh + rowoff);
                ldsm4(al[mt], sAl + rowoff);
            }
            #pragma unroll
            for (int np = 0; np < 2; np++) {
                uint32_t noff = (uint32_t)((wn * 32 + np * 16) * PADB) + kb
                                + b_lane_off;
                uint32_t th[4], tl[4];
                ldsm4(th, sBh + noff);
                ldsm4(tl, sBl + noff);
                bh[np * 2][0] = th[0]; bh[np * 2][1] = th[1];
                bh[np * 2 + 1][0] = th[2]; bh[np * 2 + 1][1] = th[3];
                bl[np * 2][0] = tl[0]; bl[np * 2][1] = tl[1];
                bl[np * 2 + 1][0] = tl[2]; bl[np * 2 + 1][1] = tl[3];
            }

            #pragma unroll
            for (int mt = 0; mt < 4; mt++)
                #pragma unroll
                for (int nt = 0; nt < 4; nt++)
                    mma_bf16(acc[mt][nt], ah[mt], bh[nt]);
            #pragma unroll
            for (int mt = 0; mt < 4; mt++)
                #pragma unroll
                for (int nt = 0; nt < 4; nt++)
                    mma_bf16(acc[mt][nt], al[mt], bh[nt]);
            #pragma unroll
            for (int mt = 0; mt < 4; mt++)
                #pragma unroll
                for (int nt = 0; nt < 4; nt++)
                    mma_bf16(acc[mt][nt], ah[mt], bl[nt]);
        }
        __syncthreads();
        if (c + NSTAGE < NC) issue_stage(c + NSTAGE);
        cp_commit();           // empty group ok -> uniform wait_group 2
    }

    // epilogue
    #pragma unroll
    for (int mt = 0; mt < 4; mt++) {
        int row = bm + wm * 64 + mt * 16 + r0;
        #pragma unroll
        for (int nt = 0; nt < 4; nt++) {
            int col = bn + wn * 32 + nt * 8 + c0;
            float* p0 = C + (size_t)row * N + col;
            float* p1 = p0 + 8 * (size_t)N;
            *(float2*)p0 = make_float2(acc[mt][nt][0], acc[mt][nt][1]);
            *(float2*)p1 = make_float2(acc[mt][nt][2], acc[mt][nt][3]);
        }
    }
}

// ---------------------------------------------------------------------------
// Flash attention, fp32 (unchanged)
// ---------------------------------------------------------------------------
__global__ __launch_bounds__(256, 1) void attn_kernel(
    const float* __restrict__ qkv, float* __restrict__ out)
{
    extern __shared__ float sm[];
    float* qT = sm;
    float* kT = qT + 128 * PS_K;
    float* vs = kT + 128 * PS_K;
    float* ps = vs + BKV * HD;

    const int tid = threadIdx.x;
    const int q0  = blockIdx.x * BQ;
    const int h   = blockIdx.y;
    const int b   = blockIdx.z;
    const int ty  = tid >> 4;
    const int tx  = tid & 15;
    const float scale = 0.08838834764831845f;

    const float* qbase = qkv + (size_t)b * S_LEN * QKV_W + h * HD;
    const float* kbase = qbase + NHEADS * HD;
    const float* vbase = qbase + 2 * NHEADS * HD;

    {
        const int d = tid & 127, half = tid >> 7;
        #pragma unroll 8
        for (int r = 0; r < BQ / 2; r++) {
            int t = half + 2 * r;
            qT[d * PS_K + t] = qbase[(size_t)(q0 + t) * QKV_W + d] * scale;
        }
    }

    float o[4][8];
    float mrun[4], lrun[4];
    #pragma unroll
    for (int i = 0; i < 4; i++) {
        mrun[i] = -CUDART_INF_F;
        lrun[i] = 0.0f;
        #pragma unroll
        for (int j = 0; j < 8; j++) o[i][j] = 0.0f;
    }

    for (int kt = 0; kt < S_LEN / BKV; kt++) {
        __syncthreads();
        {
            const int d = tid & 127, half = tid >> 7;
            #pragma unroll 8
            for (int r = 0; r < BKV / 2; r++) {
                int t = half + 2 * r;
                kT[d * PS_K + t] = kbase[(size_t)(kt * BKV + t) * QKV_W + d];
            }
        }
        {
            const int d4 = (tid & 31) * 4;
            const int tr = tid >> 5;
            #pragma unroll
            for (int r = 0; r < BKV / 8; r++) {
                int t = tr + 8 * r;
                *(float4*)&vs[t * HD + d4] =
                    *(const float4*)&vbase[(size_t)(kt * BKV + t) * QKV_W + d4];
            }
        }
        __syncthreads();

        float s[4][4];
        #pragma unroll
        for (int i = 0; i < 4; i++)
            #pragma unroll
            for (int j = 0; j < 4; j++) s[i][j] = 0.0f;

        #pragma unroll 8
        for (int d = 0; d < HD; d++) {
            float4 qv = *(const float4*)&qT[d * PS_K + ty * 4];
            float4 kv = *(const float4*)&kT[d * PS_K + tx * 4];
            float qa[4] = {qv.x, qv.y, qv.z, qv.w};
            float ka[4] = {kv.x, kv.y, kv.z, kv.w};
            #pragma unroll
            for (int i = 0; i < 4; i++)
                #pragma unroll
                for (int j = 0; j < 4; j++)
                    s[i][j] += qa[i] * ka[j];
        }

        #pragma unroll
        for (int i = 0; i < 4; i++) {
            float m = fmaxf(fmaxf(s[i][0], s[i][1]), fmaxf(s[i][2], s[i][3]));
            #pragma unroll
            for (int off = 8; off >= 1; off >>= 1)
                m = fmaxf(m, __shfl_xor_sync(0xffffffffu, m, off));
            float mnew  = fmaxf(mrun[i], m);
            float alpha = __expf(mrun[i] - mnew);
            mrun[i] = mnew;

            float lsum = 0.0f;
            #pragma unroll
            for (int j = 0; j < 4; j++) {
                float p = __expf(s[i][j] - mnew);
                ps[(ty * 4 + i) * PS_P + tx * 4 + j] = p;
                lsum += p;
            }
            #pragma unroll
            for (int off = 8; off >= 1; off >>= 1)
                lsum += __shfl_xor_sync(0xffffffffu, lsum, off);
            lrun[i] = lrun[i] * alpha + lsum;
            #pragma unroll
            for (int jj = 0; jj < 8; jj++) o[i][jj] *= alpha;
        }
        __syncthreads();

        #pragma unroll 4
        for (int kk = 0; kk < BKV; kk++) {
            float4 v0 = *(const float4*)&vs[kk * HD + tx * 8];
            float4 v1 = *(const float4*)&vs[kk * HD + tx * 8 + 4];
            #pragma unroll
            for (int i = 0; i < 4; i++) {
                float p = ps[(ty * 4 + i) * PS_P + kk];
                o[i][0] += p * v0.x; o[i][1] += p * v0.y;
                o[i][2] += p * v0.z; o[i][3] += p * v0.w;
                o[i][4] += p * v1.x; o[i][5] += p * v1.y;
                o[i][6] += p * v1.z; o[i][7] += p * v1.w;
            }
        }
    }

    #pragma unroll
    for (int i = 0; i < 4; i++) {
        float inv = 1.0f / lrun[i];
        size_t row = (size_t)b * S_LEN + q0 + ty * 4 + i;
        float* op = out + row * DIMM + h * HD + tx * 8;
        *(float4*)(op)     = make_float4(o[i][0] * inv, o[i][1] * inv,
                                         o[i][2] * inv, o[i][3] * inv);
        *(float4*)(op + 4) = make_float4(o[i][4] * inv, o[i][5] * inv,
                                         o[i][6] * inv, o[i][7] * inv);
    }
}

// ---------------------------------------------------------------------------
extern "C" void kernel_launch(void* const* d_in, const int* in_sizes, int n_in,
                              void* d_out, int out_size)
{
    const float* x     = (const float*)d_in[0];   // [2,2048,2048]
    const float* w_qkv = (const float*)d_in[1];   // [2048,6144]
    const float* w_out = (const float*)d_in[2];   // [2048,2048]
    float* out = (float*)d_out;                   // [2,2048,2048]

    float *qkv_p, *att_p;
    __nv_bfloat16 *xh, *xl, *wqh, *wql, *woh, *wol, *ah, *al;
    cudaGetSymbolAddress((void**)&qkv_p, g_qkv);
    cudaGetSymbolAddress((void**)&att_p, g_att);
    cudaGetSymbolAddress((void**)&xh, g_xh);
    cudaGetSymbolAddress((void**)&xl, g_xl);
    cudaGetSymbolAddress((void**)&wqh, g_wqT_h);
    cudaGetSymbolAddress((void**)&wql, g_wqT_l);
    cudaGetSymbolAddress((void**)&woh, g_woT_h);
    cudaGetSymbolAddress((void**)&wol, g_woT_l);
    cudaGetSymbolAddress((void**)&ah, g_ah);
    cudaGetSymbolAddress((void**)&al, g_al);

    cudaFuncSetAttribute(gemm_mma, cudaFuncAttributeMaxDynamicSharedMemorySize,
                         GEMM_SMEM);

    // split x -> bf16 hi/lo
    {
        int n4 = (MROWS * DIMM) / 4;
        split_kernel<<<(n4 + 255) / 256, 256>>>(x, xh, xl, n4);
    }
    // transpose+split weights
    {
        dim3 t(32, 8);
        transpose_split<<<dim3(QKV_W / 32, DIMM / 32), t>>>(w_qkv, wqh, wql, DIMM, QKV_W);
        transpose_split<<<dim3(DIMM / 32, DIMM / 32), t>>>(w_out, woh, wol, DIMM, DIMM);
    }
    // 1) QKV projection: [4096,2048] @ [2048,6144]
    gemm_mma<<<dim3(QKV_W / 128, MROWS / 128), 256, GEMM_SMEM>>>(
        xh, xl, wqh, wql, qkv_p, MROWS, QKV_W, DIMM);

    // 2) Attention (fp32 SIMT)
    {
        int smem = (2 * 128 * PS_K + BKV * HD + BQ * PS_P) * (int)sizeof(float);
        cudaFuncSetAttribute(attn_kernel, cudaFuncAttributeMaxDynamicSharedMemorySize, smem);
        dim3 grid(S_LEN / BQ, NHEADS, BATCH);
        attn_kernel<<<grid, 256, smem>>>(qkv_p, att_p);
    }

    // split attention output
    {
        int n4 = (MROWS * DIMM) / 4;
        split_kernel<<<(n4 + 255) / 256, 256>>>(att_p, ah, al, n4);
    }
    // 3) Output projection: [4096,2048] @ [2048,2048]
    gemm_mma<<<dim3(DIMM / 128, MROWS / 128), 256, GEMM_SMEM>>>(
        ah, al, woh, wol, out, MROWS, DIMM, DIMM);
}

// round 5
// speedup vs baseline: 1.4970x; 1.1397x over previous
#include <cuda_runtime.h>
#include <cuda_bf16.h>
#include <math_constants.h>
#include <cstdint>
#include <cstddef>

#define S_LEN  2048
#define DIMM   2048
#define NHEADS 16
#define HD     128
#define QKV_W  6144
#define BATCH  2
#define MROWS  (BATCH * S_LEN)   // 4096

// attention tiling
#define BQ  64
#define BKV 64

// ---------------------------------------------------------------------------
// Scratch (__device__ globals: allocation-free rule)
// ---------------------------------------------------------------------------
__device__ float          g_qkv[(size_t)MROWS * QKV_W];
__device__ float          g_att[(size_t)MROWS * DIMM];
__device__ __nv_bfloat16  g_xh[(size_t)MROWS * DIMM];
__device__ __nv_bfloat16  g_xl[(size_t)MROWS * DIMM];
__device__ __nv_bfloat16  g_wqT_h[(size_t)QKV_W * DIMM];   // [6144,2048] K-major (B^T)
__device__ __nv_bfloat16  g_wqT_l[(size_t)QKV_W * DIMM];
__device__ __nv_bfloat16  g_woT_h[(size_t)DIMM * DIMM];    // [2048,2048] K-major
__device__ __nv_bfloat16  g_woT_l[(size_t)DIMM * DIMM];
__device__ __nv_bfloat16  g_ah[(size_t)MROWS * DIMM];
__device__ __nv_bfloat16  g_al[(size_t)MROWS * DIMM];

// ---------------------------------------------------------------------------
// helpers
// ---------------------------------------------------------------------------
__device__ __forceinline__ uint32_t smem_u32(const void* p) {
    uint32_t a;
    asm("{ .reg .u64 t; cvta.to.shared.u64 t, %1; cvt.u32.u64 %0, t; }"
        : "=r"(a) : "l"(p));
    return a;
}
__device__ __forceinline__ void cp16(uint32_t dst, const void* src) {
    asm volatile("cp.async.cg.shared.global [%0], [%1], 16;"
                 :: "r"(dst), "l"(src) : "memory");
}
__device__ __forceinline__ void cp_commit() {
    asm volatile("cp.async.commit_group;" ::: "memory");
}
__device__ __forceinline__ void cp_wait1() {
    asm volatile("cp.async.wait_group 1;" ::: "memory");
}
__device__ __forceinline__ void mma_bf16(float* d, const uint32_t* a,
                                         const uint32_t* b) {
    asm volatile(
        "mma.sync.aligned.m16n8k16.row.col.f32.bf16.bf16.f32 "
        "{%0,%1,%2,%3}, {%4,%5,%6,%7}, {%8,%9}, {%0,%1,%2,%3};"
        : "+f"(d[0]), "+f"(d[1]), "+f"(d[2]), "+f"(d[3])
        : "r"(a[0]), "r"(a[1]), "r"(a[2]), "r"(a[3]), "r"(b[0]), "r"(b[1]));
}
__device__ __forceinline__ void ldsm4(uint32_t* r, uint32_t addr) {
    asm volatile("ldmatrix.sync.aligned.m8n8.x4.shared.b16 {%0,%1,%2,%3}, [%4];"
                 : "=r"(r[0]), "=r"(r[1]), "=r"(r[2]), "=r"(r[3]) : "r"(addr));
}

// ---------------------------------------------------------------------------
// Conversion kernels
// ---------------------------------------------------------------------------
__global__ void split_kernel(const float* __restrict__ in,
                             __nv_bfloat16* __restrict__ hi,
                             __nv_bfloat16* __restrict__ lo, int n4)
{
    int i = blockIdx.x * blockDim.x + threadIdx.x;
    if (i >= n4) return;
    float4 v = ((const float4*)in)[i];
    __nv_bfloat16 h0 = __float2bfloat16_rn(v.x);
    __nv_bfloat16 h1 = __float2bfloat16_rn(v.y);
    __nv_bfloat16 h2 = __float2bfloat16_rn(v.z);
    __nv_bfloat16 h3 = __float2bfloat16_rn(v.w);
    __nv_bfloat162* H = (__nv_bfloat162*)(hi) + i * 2;
    __nv_bfloat162* L = (__nv_bfloat162*)(lo) + i * 2;
    H[0] = __nv_bfloat162(h0, h1);
    H[1] = __nv_bfloat162(h2, h3);
    L[0] = __nv_bfloat162(__float2bfloat16_rn(v.x - __bfloat162float(h0)),
                          __float2bfloat16_rn(v.y - __bfloat162float(h1)));
    L[1] = __nv_bfloat162(__float2bfloat16_rn(v.z - __bfloat162float(h2)),
                          __float2bfloat16_rn(v.w - __bfloat162float(h3)));
}

// in [R,C] fp32 -> out [C,R] bf16 hi/lo
__global__ void transpose_split(const float* __restrict__ in,
                                __nv_bfloat16* __restrict__ oh,
                                __nv_bfloat16* __restrict__ ol, int R, int C)
{
    __shared__ float t[32][33];
    int bx = blockIdx.x * 32, by = blockIdx.y * 32;
    int x = threadIdx.x, y = threadIdx.y;           // 32 x 8
    #pragma unroll
    for (int i = 0; i < 32; i += 8)
        t[y + i][x] = in[(size_t)(by + y + i) * C + bx + x];
    __syncthreads();
    #pragma unroll
    for (int i = 0; i < 32; i += 8) {
        float v = t[x][y + i];
        size_t o = (size_t)(bx + y + i) * R + by + x;
        __nv_bfloat16 h = __float2bfloat16_rn(v);
        oh[o] = h;
        ol[o] = __float2bfloat16_rn(v - __bfloat162float(h));
    }
}

// ---------------------------------------------------------------------------
// mma.sync bf16-split GEMM: C[M,N] fp32 = A[M,K] @ B^T
// CTA: 128x128 tile, BK=32, 256 threads (8 warps, 2x4 -> warp tile 64x32).
// 2-stage cp.async pipeline (80KB smem -> 2 CTAs/SM), ldmatrix.x4 loads.
// 3-term split: Ah*Bh + Al*Bh + Ah*Bl.
// ---------------------------------------------------------------------------
#define PADB 80                    // padded row stride in bytes (40 bf16)
#define TILE_B (128 * PADB)        // 10240 B per operand tile
#define STAGE_B (4 * TILE_B)       // Ah, Al, Bh, Bl
#define NSTAGE 2
#define GEMM_SMEM (NSTAGE * STAGE_B)   // 81920 B

__global__ __launch_bounds__(256, 2) void gemm_mma(
    const __nv_bfloat16* __restrict__ Ah, const __nv_bfloat16* __restrict__ Al,
    const __nv_bfloat16* __restrict__ Bh, const __nv_bfloat16* __restrict__ Bl,
    float* __restrict__ C, int M, int N, int K)
{
    extern __shared__ char smem[];
    const uint32_t smem_base = smem_u32(smem);
    const int tid  = threadIdx.x;
    const int wid  = tid >> 5;
    const int lane = tid & 31;
    const int wm   = wid & 1;          // 0..1  (m dir, 64 rows)
    const int wn   = wid >> 1;         // 0..3  (n dir, 32 cols)
    const int bm = blockIdx.y * 128;
    const int bn = blockIdx.x * 128;

    const int lr = tid >> 1;           // load row 0..127
    const int lc = tid & 1;            // load chunk base 0..1

    const int r0 = lane >> 2;          // 0..7
    const int c0 = (lane & 3) * 2;     // 0,2,4,6

    const uint32_t a_lane_off = (uint32_t)((lane & 15) * PADB + ((lane >> 4) << 4));
    const uint32_t b_lane_off = (uint32_t)(((lane & 7) + ((lane >> 4) << 3)) * PADB
                                           + (((lane >> 3) & 1) << 4));

    float acc[4][4][4];
    #pragma unroll
    for (int mt = 0; mt < 4; mt++)
        #pragma unroll
        for (int nt = 0; nt < 4; nt++)
            #pragma unroll
            for (int j = 0; j < 4; j++) acc[mt][nt][j] = 0.0f;

    const int NC = K / 32;

    auto issue_tile = [&](const __nv_bfloat16* src, int row0, int k0,
                          uint32_t dstbase) {
        const char* g = (const char*)(src + (size_t)(row0 + lr) * K + k0)
                        + lc * 16;
        uint32_t d = dstbase + lr * PADB + lc * 16;
        cp16(d, g);
        cp16(d + 32, g + 32);
    };
    auto issue_stage = [&](int c) {
        uint32_t base = smem_base + (c % NSTAGE) * STAGE_B;
        int k0 = c * 32;
        issue_tile(Ah, bm, k0, base);
        issue_tile(Al, bm, k0, base + TILE_B);
        issue_tile(Bh, bn, k0, base + 2 * TILE_B);
        issue_tile(Bl, bn, k0, base + 3 * TILE_B);
    };

    issue_stage(0); cp_commit();
    issue_stage(1); cp_commit();

    for (int c = 0; c < NC; c++) {
        cp_wait1();            // stage c complete
        __syncthreads();

        const uint32_t sb  = smem_base + (c % NSTAGE) * STAGE_B;
        const uint32_t sAh = sb;
        const uint32_t sAl = sb + TILE_B;
        const uint32_t sBh = sb + 2 * TILE_B;
        const uint32_t sBl = sb + 3 * TILE_B;

        #pragma unroll
        for (int ks = 0; ks < 2; ks++) {
            const uint32_t kb = ks * 32;       // byte offset of k-slice
            uint32_t ah[4][4], bx[4][2];

            // pass 1: Ah * Bh
            #pragma unroll
            for (int mt = 0; mt < 4; mt++) {
                uint32_t rowoff = (uint32_t)((wm * 64 + mt * 16) * PADB) + kb
                                  + a_lane_off;
                ldsm4(ah[mt], sAh + rowoff);
            }
            #pragma unroll
            for (int np = 0; np < 2; np++) {
                uint32_t noff = (uint32_t)((wn * 32 + np * 16) * PADB) + kb
                                + b_lane_off;
                uint32_t th[4];
                ldsm4(th, sBh + noff);
                bx[np * 2][0] = th[0]; bx[np * 2][1] = th[1];
                bx[np * 2 + 1][0] = th[2]; bx[np * 2 + 1][1] = th[3];
            }
            #pragma unroll
            for (int mt = 0; mt < 4; mt++)
                #pragma unroll
                for (int nt = 0; nt < 4; nt++)
                    mma_bf16(acc[mt][nt], ah[mt], bx[nt]);

            // pass 2: Al * Bh (reuse bx)
            {
                uint32_t al[4][4];
                #pragma unroll
                for (int mt = 0; mt < 4; mt++) {
                    uint32_t rowoff = (uint32_t)((wm * 64 + mt * 16) * PADB) + kb
                                      + a_lane_off;
                    ldsm4(al[mt], sAl + rowoff);
                }
                #pragma unroll
                for (int mt = 0; mt < 4; mt++)
                    #pragma unroll
                    for (int nt = 0; nt < 4; nt++)
                        mma_bf16(acc[mt][nt], al[mt], bx[nt]);
            }

            // pass 3: Ah * Bl (reuse ah, overwrite bx)
            #pragma unroll
            for (int np = 0; np < 2; np++) {
                uint32_t noff = (uint32_t)((wn * 32 + np * 16) * PADB) + kb
                                + b_lane_off;
                uint32_t tl[4];
                ldsm4(tl, sBl + noff);
                bx[np * 2][0] = tl[0]; bx[np * 2][1] = tl[1];
                bx[np * 2 + 1][0] = tl[2]; bx[np * 2 + 1][1] = tl[3];
            }
            #pragma unroll
            for (int mt = 0; mt < 4; mt++)
                #pragma unroll
                for (int nt = 0; nt < 4; nt++)
                    mma_bf16(acc[mt][nt], ah[mt], bx[nt]);
        }
        __syncthreads();
        if (c + NSTAGE < NC) issue_stage(c + NSTAGE);
        cp_commit();           // empty group ok -> uniform wait_group 1
    }

    // epilogue
    #pragma unroll
    for (int mt = 0; mt < 4; mt++) {
        int row = bm + wm * 64 + mt * 16 + r0;
        #pragma unroll
        for (int nt = 0; nt < 4; nt++) {
            int col = bn + wn * 32 + nt * 8 + c0;
            float* p0 = C + (size_t)row * N + col;
            float* p1 = p0 + 8 * (size_t)N;
            *(float2*)p0 = make_float2(acc[mt][nt][0], acc[mt][nt][1]);
            *(float2*)p1 = make_float2(acc[mt][nt][2], acc[mt][nt][3]);
        }
    }
}

// ---------------------------------------------------------------------------
// Flash attention, fp32. Swizzled exact-64 strides -> 112KB smem -> 2 CTAs/SM.
// SW(r,c): XOR-swizzled index into a [*,64] float tile, float4-safe.
// ---------------------------------------------------------------------------
#define SW(r, c) ((r) * 64 + ((((((c) >> 2) ^ ((r) & 15))) << 2) | ((c) & 3)))
#define ATT_SMEM ((3 * 8192 + 4096) * 4)   // qs + ks + vs + ps = 114688 B

__global__ __launch_bounds__(256, 2) void attn_kernel(
    const float* __restrict__ qkv, float* __restrict__ out)
{
    extern __shared__ float sm[];
    float* qs = sm;                 // [128][64] swizzled: qs[SW(d,t)], pre-scaled
    float* ks = qs + 8192;          // [128][64] swizzled: ks[SW(d,t)]
    float* vs = ks + 8192;          // [64][128] natural
    float* ps = vs + 8192;          // [64][64] swizzled: ps[SW(q,t)]

    const int tid = threadIdx.x;
    const int q0  = blockIdx.x * BQ;
    const int h   = blockIdx.y;
    const int b   = blockIdx.z;
    const int ty  = tid >> 4;
    const int tx  = tid & 15;
    const float scale = 0.08838834764831845f;

    const float* qbase = qkv + (size_t)b * S_LEN * QKV_W + h * HD;
    const float* kbase = qbase + NHEADS * HD;
    const float* vbase = qbase + 2 * NHEADS * HD;

    // Load Q tile transposed+swizzled, folded scale
    {
        const int d = tid & 127, half = tid >> 7;
        #pragma unroll 8
        for (int r = 0; r < BQ / 2; r++) {
            int t = half + 2 * r;
            qs[SW(d, t)] = qbase[(size_t)(q0 + t) * QKV_W + d] * scale;
        }
    }

    float o[4][8];
    float mrun[4], lrun[4];
    #pragma unroll
    for (int i = 0; i < 4; i++) {
        mrun[i] = -CUDART_INF_F;
        lrun[i] = 0.0f;
        #pragma unroll
        for (int j = 0; j < 8; j++) o[i][j] = 0.0f;
    }

    for (int kt = 0; kt < S_LEN / BKV; kt++) {
        __syncthreads();   // prev tile's P·V done (covers Q load on iter 0)

        // Load K tile transposed+swizzled
        {
            const int d = tid & 127, half = tid >> 7;
            #pragma unroll 8
            for (int r = 0; r < BKV / 2; r++) {
                int t = half + 2 * r;
                ks[SW(d, t)] = kbase[(size_t)(kt * BKV + t) * QKV_W + d];
            }
        }
        // Load V tile natural (float4)
        {
            const int d4 = (tid & 31) * 4;
            const int tr = tid >> 5;
            #pragma unroll
            for (int r = 0; r < BKV / 8; r++) {
                int t = tr + 8 * r;
                *(float4*)&vs[t * HD + d4] =
                    *(const float4*)&vbase[(size_t)(kt * BKV + t) * QKV_W + d4];
            }
        }
        __syncthreads();

        // S = Q·K^T : 4x4 per thread
        float s[4][4];
        #pragma unroll
        for (int i = 0; i < 4; i++)
            #pragma unroll
            for (int j = 0; j < 4; j++) s[i][j] = 0.0f;

        #pragma unroll 8
        for (int d = 0; d < HD; d++) {
            float4 qv = *(const float4*)&qs[d * 64 + (((ty ^ (d & 15)) << 2))];
            float4 kv = *(const float4*)&ks[d * 64 + (((tx ^ (d & 15)) << 2))];
            float qa[4] = {qv.x, qv.y, qv.z, qv.w};
            float ka[4] = {kv.x, kv.y, kv.z, kv.w};
            #pragma unroll
            for (int i = 0; i < 4; i++)
                #pragma unroll
                for (int j = 0; j < 4; j++)
                    s[i][j] += qa[i] * ka[j];
        }

        // Online softmax; write P as swizzled float4
        #pragma unroll
        for (int i = 0; i < 4; i++) {
            float m = fmaxf(fmaxf(s[i][0], s[i][1]), fmaxf(s[i][2], s[i][3]));
            #pragma unroll
            for (int off = 8; off >= 1; off >>= 1)
                m = fmaxf(m, __shfl_xor_sync(0xffffffffu, m, off));
            float mnew  = fmaxf(mrun[i], m);
            float alpha = __expf(mrun[i] - mnew);
            mrun[i] = mnew;

            float p0 = __expf(s[i][0] - mnew);
            float p1 = __expf(s[i][1] - mnew);
            float p2 = __expf(s[i][2] - mnew);
            float p3 = __expf(s[i][3] - mnew);
            int qr = ty * 4 + i;
            *(float4*)&ps[qr * 64 + (((tx ^ (qr & 15)) << 2))] =
                make_float4(p0, p1, p2, p3);
            float lsum = p0 + p1 + p2 + p3;
            #pragma unroll
            for (int off = 8; off >= 1; off >>= 1)
                lsum += __shfl_xor_sync(0xffffffffu, lsum, off);
            lrun[i] = lrun[i] * alpha + lsum;
            #pragma unroll
            for (int jj = 0; jj < 8; jj++) o[i][jj] *= alpha;
        }
        __syncthreads();

        // O += P·V : float4 probability loads, 4 rows x 8 cols per thread
        #pragma unroll 2
        for (int kk4 = 0; kk4 < BKV / 4; kk4++) {
            float4 p4[4];
            #pragma unroll
            for (int i = 0; i < 4; i++) {
                int qr = ty * 4 + i;
                p4[i] = *(const float4*)&ps[qr * 64 + (((kk4 ^ (qr & 15)) << 2))];
            }
            #pragma unroll
            for (int j = 0; j < 4; j++) {
                int kk = kk4 * 4 + j;
                float4 v0 = *(const float4*)&vs[kk * HD + tx * 8];
                float4 v1 = *(const float4*)&vs[kk * HD + tx * 8 + 4];
                #pragma unroll
                for (int i = 0; i < 4; i++) {
                    float p = ((const float*)&p4[i])[j];
                    o[i][0] += p * v0.x; o[i][1] += p * v0.y;
                    o[i][2] += p * v0.z; o[i][3] += p * v0.w;
                    o[i][4] += p * v1.x; o[i][5] += p * v1.y;
                    o[i][6] += p * v1.z; o[i][7] += p * v1.w;
                }
            }
        }
    }

    // Epilogue
    #pragma unroll
    for (int i = 0; i < 4; i++) {
        float inv = 1.0f / lrun[i];
        size_t row = (size_t)b * S_LEN + q0 + ty * 4 + i;
        float* op = out + row * DIMM + h * HD + tx * 8;
        *(float4*)(op)     = make_float4(o[i][0] * inv, o[i][1] * inv,
                                         o[i][2] * inv, o[i][3] * inv);
        *(float4*)(op + 4) = make_float4(o[i][4] * inv, o[i][5] * inv,
                                         o[i][6] * inv, o[i][7] * inv);
    }
}

// ---------------------------------------------------------------------------
extern "C" void kernel_launch(void* const* d_in, const int* in_sizes, int n_in,
                              void* d_out, int out_size)
{
    const float* x     = (const float*)d_in[0];   // [2,2048,2048]
    const float* w_qkv = (const float*)d_in[1];   // [2048,6144]
    const float* w_out = (const float*)d_in[2];   // [2048,2048]
    float* out = (float*)d_out;                   // [2,2048,2048]

    float *qkv_p, *att_p;
    __nv_bfloat16 *xh, *xl, *wqh, *wql, *woh, *wol, *ah, *al;
    cudaGetSymbolAddress((void**)&qkv_p, g_qkv);
    cudaGetSymbolAddress((void**)&att_p, g_att);
    cudaGetSymbolAddress((void**)&xh, g_xh);
    cudaGetSymbolAddress((void**)&xl, g_xl);
    cudaGetSymbolAddress((void**)&wqh, g_wqT_h);
    cudaGetSymbolAddress((void**)&wql, g_wqT_l);
    cudaGetSymbolAddress((void**)&woh, g_woT_h);
    cudaGetSymbolAddress((void**)&wol, g_woT_l);
    cudaGetSymbolAddress((void**)&ah, g_ah);
    cudaGetSymbolAddress((void**)&al, g_al);

    cudaFuncSetAttribute(gemm_mma, cudaFuncAttributeMaxDynamicSharedMemorySize,
                         GEMM_SMEM);
    cudaFuncSetAttribute(attn_kernel, cudaFuncAttributeMaxDynamicSharedMemorySize,
                         ATT_SMEM);

    // split x -> bf16 hi/lo
    {
        int n4 = (MROWS * DIMM) / 4;
        split_kernel<<<(n4 + 255) / 256, 256>>>(x, xh, xl, n4);
    }
    // transpose+split weights
    {
        dim3 t(32, 8);
        transpose_split<<<dim3(QKV_W / 32, DIMM / 32), t>>>(w_qkv, wqh, wql, DIMM, QKV_W);
        transpose_split<<<dim3(DIMM / 32, DIMM / 32), t>>>(w_out, woh, wol, DIMM, DIMM);
    }
    // 1) QKV projection: [4096,2048] @ [2048,6144]
    gemm_mma<<<dim3(QKV_W / 128, MROWS / 128), 256, GEMM_SMEM>>>(
        xh, xl, wqh, wql, qkv_p, MROWS, QKV_W, DIMM);

    // 2) Attention (fp32 SIMT, 2 CTAs/SM)
    {
        dim3 grid(S_LEN / BQ, NHEADS, BATCH);
        attn_kernel<<<grid, 256, ATT_SMEM>>>(qkv_p, att_p);
    }

    // split attention output
    {
        int n4 = (MROWS * DIMM) / 4;
        split_kernel<<<(n4 + 255) / 256, 256>>>(att_p, ah, al, n4);
    }
    // 3) Output projection: [4096,2048] @ [2048,2048]
    gemm_mma<<<dim3(DIMM / 128, MROWS / 128), 256, GEMM_SMEM>>>(
        ah, al, woh, wol, out, MROWS, DIMM, DIMM);
}

// round 6
// speedup vs baseline: 2.7121x; 1.8116x over previous
#include <cuda_runtime.h>
#include <cuda_bf16.h>
#include <math_constants.h>
#include <cstdint>
#include <cstddef>

#define S_LEN  2048
#define DIMM   2048
#define NHEADS 16
#define HD     128
#define QKV_W  6144
#define BATCH  2
#define MROWS  (BATCH * S_LEN)   // 4096
#define SCALE_F 0.08838834764831845f

// ---------------------------------------------------------------------------
// Scratch (__device__ globals: allocation-free rule)
// ---------------------------------------------------------------------------
__device__ float          g_qkv[(size_t)MROWS * QKV_W];
__device__ __nv_bfloat16  g_xh[(size_t)MROWS * DIMM];
__device__ __nv_bfloat16  g_xl[(size_t)MROWS * DIMM];
__device__ __nv_bfloat16  g_wqT_h[(size_t)QKV_W * DIMM];
__device__ __nv_bfloat16  g_wqT_l[(size_t)QKV_W * DIMM];
__device__ __nv_bfloat16  g_woT_h[(size_t)DIMM * DIMM];
__device__ __nv_bfloat16  g_woT_l[(size_t)DIMM * DIMM];
__device__ __nv_bfloat16  g_ah[(size_t)MROWS * DIMM];
__device__ __nv_bfloat16  g_al[(size_t)MROWS * DIMM];
// per-(b,h) attention operands [b][h][s][128] bf16 hi/lo
#define HSD ((size_t)BATCH * NHEADS * S_LEN * HD)
__device__ __nv_bfloat16  g_qh[HSD];
__device__ __nv_bfloat16  g_ql[HSD];
__device__ __nv_bfloat16  g_kh[HSD];
__device__ __nv_bfloat16  g_kl[HSD];
__device__ __nv_bfloat16  g_vh[HSD];
__device__ __nv_bfloat16  g_vl[HSD];

// ---------------------------------------------------------------------------
// helpers
// ---------------------------------------------------------------------------
__device__ __forceinline__ uint32_t smem_u32(const void* p) {
    uint32_t a;
    asm("{ .reg .u64 t; cvta.to.shared.u64 t, %1; cvt.u32.u64 %0, t; }"
        : "=r"(a) : "l"(p));
    return a;
}
__device__ __forceinline__ void cp16(uint32_t dst, const void* src) {
    asm volatile("cp.async.cg.shared.global [%0], [%1], 16;"
                 :: "r"(dst), "l"(src) : "memory");
}
__device__ __forceinline__ void cp_commit() {
    asm volatile("cp.async.commit_group;" ::: "memory");
}
__device__ __forceinline__ void cp_wait1() {
    asm volatile("cp.async.wait_group 1;" ::: "memory");
}
__device__ __forceinline__ void mma_bf16(float* d, const uint32_t* a,
                                         const uint32_t* b) {
    asm volatile(
        "mma.sync.aligned.m16n8k16.row.col.f32.bf16.bf16.f32 "
        "{%0,%1,%2,%3}, {%4,%5,%6,%7}, {%8,%9}, {%0,%1,%2,%3};"
        : "+f"(d[0]), "+f"(d[1]), "+f"(d[2]), "+f"(d[3])
        : "r"(a[0]), "r"(a[1]), "r"(a[2]), "r"(a[3]), "r"(b[0]), "r"(b[1]));
}
__device__ __forceinline__ void ldsm4(uint32_t* r, uint32_t addr) {
    asm volatile("ldmatrix.sync.aligned.m8n8.x4.shared.b16 {%0,%1,%2,%3}, [%4];"
                 : "=r"(r[0]), "=r"(r[1]), "=r"(r[2]), "=r"(r[3]) : "r"(addr));
}
__device__ __forceinline__ void ldsm4t(uint32_t* r, uint32_t addr) {
    asm volatile("ldmatrix.sync.aligned.m8n8.x4.trans.shared.b16 {%0,%1,%2,%3}, [%4];"
                 : "=r"(r[0]), "=r"(r[1]), "=r"(r[2]), "=r"(r[3]) : "r"(addr));
}
// pack two floats into bf16x2 hi; residuals into bf16x2 lo
__device__ __forceinline__ uint32_t pack_hl(float x, float y, uint32_t& lo) {
    __nv_bfloat16 hx = __float2bfloat16_rn(x), hy = __float2bfloat16_rn(y);
    float rx = x - __bfloat162float(hx), ry = y - __bfloat162float(hy);
    unsigned short lx = __bfloat16_as_ushort(__float2bfloat16_rn(rx));
    unsigned short ly = __bfloat16_as_ushort(__float2bfloat16_rn(ry));
    lo = ((uint32_t)ly << 16) | lx;
    return ((uint32_t)__bfloat16_as_ushort(hy) << 16) | __bfloat16_as_ushort(hx);
}

// ---------------------------------------------------------------------------
// Conversion kernels
// ---------------------------------------------------------------------------
__global__ void split_kernel(const float* __restrict__ in,
                             __nv_bfloat16* __restrict__ hi,
                             __nv_bfloat16* __restrict__ lo, int n4)
{
    int i = blockIdx.x * blockDim.x + threadIdx.x;
    if (i >= n4) return;
    float4 v = ((const float4*)in)[i];
    uint32_t lo0, lo1;
    uint32_t h0 = pack_hl(v.x, v.y, lo0);
    uint32_t h1 = pack_hl(v.z, v.w, lo1);
    ((uint32_t*)hi)[i * 2]     = h0;
    ((uint32_t*)hi)[i * 2 + 1] = h1;
    ((uint32_t*)lo)[i * 2]     = lo0;
    ((uint32_t*)lo)[i * 2 + 1] = lo1;
}

// in [R,C] fp32 -> out [C,R] bf16 hi/lo
__global__ void transpose_split(const float* __restrict__ in,
                                __nv_bfloat16* __restrict__ oh,
                                __nv_bfloat16* __restrict__ ol, int R, int C)
{
    __shared__ float t[32][33];
    int bx = blockIdx.x * 32, by = blockIdx.y * 32;
    int x = threadIdx.x, y = threadIdx.y;           // 32 x 8
    #pragma unroll
    for (int i = 0; i < 32; i += 8)
        t[y + i][x] = in[(size_t)(by + y + i) * C + bx + x];
    __syncthreads();
    #pragma unroll
    for (int i = 0; i < 32; i += 8) {
        float v = t[x][y + i];
        size_t o = (size_t)(bx + y + i) * R + by + x;
        __nv_bfloat16 h = __float2bfloat16_rn(v);
        oh[o] = h;
        ol[o] = __float2bfloat16_rn(v - __bfloat162float(h));
    }
}

// g_qkv [4096][6144] fp32 -> per-(b,h) Q(scaled)/K/V bf16 hi/lo [b][h][2048][128]
__global__ void qkv_split(const float* __restrict__ qkv,
                          __nv_bfloat16* __restrict__ qh, __nv_bfloat16* __restrict__ ql,
                          __nv_bfloat16* __restrict__ kh, __nv_bfloat16* __restrict__ kl,
                          __nv_bfloat16* __restrict__ vh, __nv_bfloat16* __restrict__ vl)
{
    size_t i4 = (size_t)blockIdx.x * blockDim.x + threadIdx.x;
    if (i4 >= (size_t)MROWS * QKV_W / 4) return;
    size_t e = i4 * 4;
    int row = (int)(e / QKV_W);
    int col = (int)(e % QKV_W);
    int sec = col >> 11;              // 0=Q, 1=K, 2=V
    int hh  = (col >> 7) & 15;
    int d   = col & 127;
    int bb  = row >> 11, ss = row & 2047;
    size_t dst = ((((size_t)bb * NHEADS + hh) * S_LEN) + ss) * HD + d;

    float4 v = *(const float4*)(qkv + e);
    if (sec == 0) { v.x *= SCALE_F; v.y *= SCALE_F; v.z *= SCALE_F; v.w *= SCALE_F; }
    __nv_bfloat16 *H, *L;
    if (sec == 0)      { H = qh; L = ql; }
    else if (sec == 1) { H = kh; L = kl; }
    else               { H = vh; L = vl; }
    uint32_t lo0, lo1;
    uint32_t h0 = pack_hl(v.x, v.y, lo0);
    uint32_t h1 = pack_hl(v.z, v.w, lo1);
    *(uint32_t*)(H + dst)     = h0;
    *(uint32_t*)(H + dst + 2) = h1;
    *(uint32_t*)(L + dst)     = lo0;
    *(uint32_t*)(L + dst + 2) = lo1;
}

// ---------------------------------------------------------------------------
// mma.sync bf16-split GEMM (unchanged from R5): C = A @ B^T, 2 CTAs/SM
// ---------------------------------------------------------------------------
#define PADB 80
#define TILE_B (128 * PADB)
#define STAGE_B (4 * TILE_B)
#define NSTAGE 2
#define GEMM_SMEM (NSTAGE * STAGE_B)   // 81920 B

__global__ __launch_bounds__(256, 2) void gemm_mma(
    const __nv_bfloat16* __restrict__ Ah, const __nv_bfloat16* __restrict__ Al,
    const __nv_bfloat16* __restrict__ Bh, const __nv_bfloat16* __restrict__ Bl,
    float* __restrict__ C, int M, int N, int K)
{
    extern __shared__ char smem[];
    const uint32_t smem_base = smem_u32(smem);
    const int tid  = threadIdx.x;
    const int wid  = tid >> 5;
    const int lane = tid & 31;
    const int wm   = wid & 1;
    const int wn   = wid >> 1;
    const int bm = blockIdx.y * 128;
    const int bn = blockIdx.x * 128;

    const int lr = tid >> 1;
    const int lc = tid & 1;
    const int r0 = lane >> 2;
    const int c0 = (lane & 3) * 2;

    const uint32_t a_lane_off = (uint32_t)((lane & 15) * PADB + ((lane >> 4) << 4));
    const uint32_t b_lane_off = (uint32_t)(((lane & 7) + ((lane >> 4) << 3)) * PADB
                                           + (((lane >> 3) & 1) << 4));

    float acc[4][4][4];
    #pragma unroll
    for (int mt = 0; mt < 4; mt++)
        #pragma unroll
        for (int nt = 0; nt < 4; nt++)
            #pragma unroll
            for (int j = 0; j < 4; j++) acc[mt][nt][j] = 0.0f;

    const int NC = K / 32;

    auto issue_tile = [&](const __nv_bfloat16* src, int row0, int k0,
                          uint32_t dstbase) {
        const char* g = (const char*)(src + (size_t)(row0 + lr) * K + k0)
                        + lc * 16;
        uint32_t d = dstbase + lr * PADB + lc * 16;
        cp16(d, g);
        cp16(d + 32, g + 32);
    };
    auto issue_stage = [&](int c) {
        uint32_t base = smem_base + (c % NSTAGE) * STAGE_B;
        int k0 = c * 32;
        issue_tile(Ah, bm, k0, base);
        issue_tile(Al, bm, k0, base + TILE_B);
        issue_tile(Bh, bn, k0, base + 2 * TILE_B);
        issue_tile(Bl, bn, k0, base + 3 * TILE_B);
    };

    issue_stage(0); cp_commit();
    issue_stage(1); cp_commit();

    for (int c = 0; c < NC; c++) {
        cp_wait1();
        __syncthreads();

        const uint32_t sb  = smem_base + (c % NSTAGE) * STAGE_B;
        const uint32_t sAh = sb;
        const uint32_t sAl = sb + TILE_B;
        const uint32_t sBh = sb + 2 * TILE_B;
        const uint32_t sBl = sb + 3 * TILE_B;

        #pragma unroll
        for (int ks = 0; ks < 2; ks++) {
            const uint32_t kb = ks * 32;
            uint32_t ah[4][4], bx[4][2];

            #pragma unroll
            for (int mt = 0; mt < 4; mt++) {
                uint32_t rowoff = (uint32_t)((wm * 64 + mt * 16) * PADB) + kb
                                  + a_lane_off;
                ldsm4(ah[mt], sAh + rowoff);
            }
            #pragma unroll
            for (int np = 0; np < 2; np++) {
                uint32_t noff = (uint32_t)((wn * 32 + np * 16) * PADB) + kb
                                + b_lane_off;
                uint32_t th[4];
                ldsm4(th, sBh + noff);
                bx[np * 2][0] = th[0]; bx[np * 2][1] = th[1];
                bx[np * 2 + 1][0] = th[2]; bx[np * 2 + 1][1] = th[3];
            }
            #pragma unroll
            for (int mt = 0; mt < 4; mt++)
                #pragma unroll
                for (int nt = 0; nt < 4; nt++)
                    mma_bf16(acc[mt][nt], ah[mt], bx[nt]);

            {
                uint32_t al[4][4];
                #pragma unroll
                for (int mt = 0; mt < 4; mt++) {
                    uint32_t rowoff = (uint32_t)((wm * 64 + mt * 16) * PADB) + kb
                                      + a_lane_off;
                    ldsm4(al[mt], sAl + rowoff);
                }
                #pragma unroll
                for (int mt = 0; mt < 4; mt++)
                    #pragma unroll
                    for (int nt = 0; nt < 4; nt++)
                        mma_bf16(acc[mt][nt], al[mt], bx[nt]);
            }

            #pragma unroll
            for (int np = 0; np < 2; np++) {
                uint32_t noff = (uint32_t)((wn * 32 + np * 16) * PADB) + kb
                                + b_lane_off;
                uint32_t tl[4];
                ldsm4(tl, sBl + noff);
                bx[np * 2][0] = tl[0]; bx[np * 2][1] = tl[1];
                bx[np * 2 + 1][0] = tl[2]; bx[np * 2 + 1][1] = tl[3];
            }
            #pragma unroll
            for (int mt = 0; mt < 4; mt++)
                #pragma unroll
                for (int nt = 0; nt < 4; nt++)
                    mma_bf16(acc[mt][nt], ah[mt], bx[nt]);
        }
        __syncthreads();
        if (c + NSTAGE < NC) issue_stage(c + NSTAGE);
        cp_commit();
    }

    #pragma unroll
    for (int mt = 0; mt < 4; mt++) {
        int row = bm + wm * 64 + mt * 16 + r0;
        #pragma unroll
        for (int nt = 0; nt < 4; nt++) {
            int col = bn + wn * 32 + nt * 8 + c0;
            float* p0 = C + (size_t)row * N + col;
            float* p1 = p0 + 8 * (size_t)N;
            *(float2*)p0 = make_float2(acc[mt][nt][0], acc[mt][nt][1]);
            *(float2*)p1 = make_float2(acc[mt][nt][2], acc[mt][nt][3]);
        }
    }
}

// ---------------------------------------------------------------------------
// Tensor-core flash attention (bf16 split). 1 CTA per (b,h,128 queries).
// 8 warps x 16 query rows; BKV=64 double-buffered; P kept in registers.
// Writes bf16 hi/lo outputs directly (feeds out-proj GEMM).
// smem: Qh,Ql [128][128] + 2 stages of {Kh,Kl,Vh,Vl}[64][128] = 192 KB.
// Swizzle: 256B rows, 16B chunk c at offset ((c ^ (row&7))<<4).
// ---------------------------------------------------------------------------
#define ATT_SMEM (65536 + 2 * 65536)   // 196608

__global__ __launch_bounds__(256, 1) void attn_mma(
    const __nv_bfloat16* __restrict__ Qh, const __nv_bfloat16* __restrict__ Ql,
    const __nv_bfloat16* __restrict__ Kh, const __nv_bfloat16* __restrict__ Kl,
    const __nv_bfloat16* __restrict__ Vh, const __nv_bfloat16* __restrict__ Vl,
    __nv_bfloat16* __restrict__ Oh, __nv_bfloat16* __restrict__ Ol)
{
    extern __shared__ char smem[];
    const uint32_t sb0 = smem_u32(smem);
    const uint32_t sQh = sb0, sQl = sb0 + 32768;
    const int tid = threadIdx.x, wid = tid >> 5, lane = tid & 31;
    const int q0 = blockIdx.x * 128, h = blockIdx.y, b = blockIdx.z;

    const size_t hb = ((size_t)(b * NHEADS + h)) * S_LEN * HD;
    const __nv_bfloat16* gqh = Qh + hb + (size_t)q0 * HD;
    const __nv_bfloat16* gql = Ql + hb + (size_t)q0 * HD;
    const __nv_bfloat16* gkh = Kh + hb;
    const __nv_bfloat16* gkl = Kl + hb;
    const __nv_bfloat16* gvh = Vh + hb;
    const __nv_bfloat16* gvl = Vl + hb;

    // Q (128 rows x 256B), both splits
    {
        int r = tid >> 1, cb = (tid & 1) * 8;
        const char* g0 = (const char*)(gqh + (size_t)r * HD);
        const char* g1 = (const char*)(gql + (size_t)r * HD);
        uint32_t d0 = sQh + r * 256, d1 = sQl + r * 256;
        #pragma unroll
        for (int j = 0; j < 8; j++) {
            int c = cb + j;
            uint32_t sw = (uint32_t)((c ^ (r & 7)) << 4);
            cp16(d0 + sw, g0 + c * 16);
            cp16(d1 + sw, g1 + c * 16);
        }
    }
    auto ld_stage = [&](int t) {
        uint32_t base = sb0 + 65536 + (t & 1) * 65536;
        int s0 = t * 64;
        int r = tid >> 2, cb = (tid & 3) * 4;
        const char* g0 = (const char*)(gkh + (size_t)(s0 + r) * HD);
        const char* g1 = (const char*)(gkl + (size_t)(s0 + r) * HD);
        const char* g2 = (const char*)(gvh + (size_t)(s0 + r) * HD);
        const char* g3 = (const char*)(gvl + (size_t)(s0 + r) * HD);
        uint32_t dr = base + r * 256;
        #pragma unroll
        for (int j = 0; j < 4; j++) {
            int c = cb + j;
            uint32_t sw = (uint32_t)((c ^ (r & 7)) << 4);
            cp16(dr + sw,             g0 + c * 16);
            cp16(dr + 16384 + sw,     g1 + c * 16);
            cp16(dr + 32768 + sw,     g2 + c * 16);
            cp16(dr + 49152 + sw,     g3 + c * 16);
        }
    };

    ld_stage(0); cp_commit();
    ld_stage(1); cp_commit();

    // lane-invariant fragment address pieces
    const int aq_row = wid * 16 + (lane & 15);
    const uint32_t aq_base = (uint32_t)(aq_row * 256);
    const int aq_r7 = aq_row & 7;
    const int aq_cx = lane >> 4;
    const int bk_row = (lane & 7) + ((lane >> 4) << 3);      // + np*16
    const int bk_cx = (lane >> 3) & 1;
    const int bv_row = (lane & 7) + (((lane >> 3) & 1) << 3);  // + k2*16
    const int bv_cx = lane >> 4;

    float o[16][4];
    #pragma unroll
    for (int nt = 0; nt < 16; nt++) { o[nt][0]=o[nt][1]=o[nt][2]=o[nt][3]=0.f; }
    float mr1 = -CUDART_INF_F, mr2 = -CUDART_INF_F, lr1 = 0.f, lr2 = 0.f;

    for (int t = 0; t < S_LEN / 64; t++) {
        cp_wait1();
        __syncthreads();
        uint32_t stg = sb0 + 65536 + (t & 1) * 65536;
        uint32_t sK  = stg, sKl_ = stg + 16384, sV = stg + 32768, sVl_ = stg + 49152;

        // ---- S = Q·K^T (3 split terms) ----
        float s[8][4];
        #pragma unroll
        for (int i = 0; i < 8; i++) { s[i][0]=s[i][1]=s[i][2]=s[i][3]=0.f; }

        #pragma unroll
        for (int kt = 0; kt < 8; kt++) {
            uint32_t ah4[4], al4[4];
            {
                int c16 = kt * 2 + aq_cx;
                uint32_t off = aq_base + (uint32_t)(((c16 ^ aq_r7)) << 4);
                ldsm4(ah4, sQh + off);
                ldsm4(al4, sQl + off);
            }
            #pragma unroll
            for (int np = 0; np < 4; np++) {
                int row = np * 16 + bk_row;
                int c16 = kt * 2 + bk_cx;
                uint32_t off = (uint32_t)(row * 256) + (uint32_t)(((c16 ^ (row & 7))) << 4);
                uint32_t bh4[4];
                ldsm4(bh4, sK + off);
                mma_bf16(s[2*np],   ah4, bh4);
                mma_bf16(s[2*np+1], ah4, bh4 + 2);
                mma_bf16(s[2*np],   al4, bh4);
                mma_bf16(s[2*np+1], al4, bh4 + 2);
                uint32_t bl4[4];
                ldsm4(bl4, sKl_ + off);
                mma_bf16(s[2*np],   ah4, bl4);
                mma_bf16(s[2*np+1], ah4, bl4 + 2);
            }
        }

        // ---- online softmax (rows r1 = lane>>2 and r1+8) ----
        float m1 = s[0][0], m2 = s[0][2];
        #pragma unroll
        for (int i = 0; i < 8; i++) {
            m1 = fmaxf(m1, fmaxf(s[i][0], s[i][1]));
            m2 = fmaxf(m2, fmaxf(s[i][2], s[i][3]));
        }
        m1 = fmaxf(m1, __shfl_xor_sync(0xffffffffu, m1, 1));
        m1 = fmaxf(m1, __shfl_xor_sync(0xffffffffu, m1, 2));
        m2 = fmaxf(m2, __shfl_xor_sync(0xffffffffu, m2, 1));
        m2 = fmaxf(m2, __shfl_xor_sync(0xffffffffu, m2, 2));
        float mn1 = fmaxf(mr1, m1), mn2 = fmaxf(mr2, m2);
        float a1 = __expf(mr1 - mn1), a2 = __expf(mr2 - mn2);
        mr1 = mn1; mr2 = mn2;
        float l1 = 0.f, l2 = 0.f;
        #pragma unroll
        for (int i = 0; i < 8; i++) {
            s[i][0] = __expf(s[i][0] - mn1); s[i][1] = __expf(s[i][1] - mn1);
            s[i][2] = __expf(s[i][2] - mn2); s[i][3] = __expf(s[i][3] - mn2);
            l1 += s[i][0] + s[i][1];
            l2 += s[i][2] + s[i][3];
        }
        l1 += __shfl_xor_sync(0xffffffffu, l1, 1);
        l1 += __shfl_xor_sync(0xffffffffu, l1, 2);
        l2 += __shfl_xor_sync(0xffffffffu, l2, 1);
        l2 += __shfl_xor_sync(0xffffffffu, l2, 2);
        lr1 = lr1 * a1 + l1;
        lr2 = lr2 * a2 + l2;
        #pragma unroll
        for (int nt = 0; nt < 16; nt++) {
            o[nt][0] *= a1; o[nt][1] *= a1; o[nt][2] *= a2; o[nt][3] *= a2;
        }

        // ---- pack P -> bf16 hi/lo A-fragments (S accum layout == A layout) ----
        uint32_t ph[4][4], pl[4][4];
        #pragma unroll
        for (int k2 = 0; k2 < 4; k2++) {
            ph[k2][0] = pack_hl(s[2*k2][0],   s[2*k2][1],   pl[k2][0]);
            ph[k2][1] = pack_hl(s[2*k2][2],   s[2*k2][3],   pl[k2][1]);
            ph[k2][2] = pack_hl(s[2*k2+1][0], s[2*k2+1][1], pl[k2][2]);
            ph[k2][3] = pack_hl(s[2*k2+1][2], s[2*k2+1][3], pl[k2][3]);
        }

        // ---- O += P·V (3 split terms), V via ldmatrix.trans ----
        #pragma unroll
        for (int k2 = 0; k2 < 4; k2++) {
            #pragma unroll
            for (int np = 0; np < 8; np++) {
                int row = k2 * 16 + bv_row;
                int c16 = np * 2 + bv_cx;
                uint32_t off = (uint32_t)(row * 256) + (uint32_t)(((c16 ^ (row & 7))) << 4);
                uint32_t v4[4];
                ldsm4t(v4, sV + off);
                mma_bf16(o[2*np],   ph[k2], v4);
                mma_bf16(o[2*np+1], ph[k2], v4 + 2);
                mma_bf16(o[2*np],   pl[k2], v4);
                mma_bf16(o[2*np+1], pl[k2], v4 + 2);
                uint32_t w4[4];
                ldsm4t(w4, sVl_ + off);
                mma_bf16(o[2*np],   ph[k2], w4);
                mma_bf16(o[2*np+1], ph[k2], w4 + 2);
            }
        }

        __syncthreads();
        if (t + 2 < S_LEN / 64) ld_stage(t + 2);
        cp_commit();
    }

    // epilogue: normalize and write bf16 hi/lo
    float i1 = 1.f / lr1, i2 = 1.f / lr2;
    int r1 = lane >> 2, c2 = (lane & 3) * 2;
    size_t row1 = (size_t)b * S_LEN + q0 + wid * 16 + r1;
    size_t row2 = row1 + 8;
    #pragma unroll
    for (int nt = 0; nt < 16; nt++) {
        int col = h * HD + nt * 8 + c2;
        uint32_t lo, hi;
        hi = pack_hl(o[nt][0] * i1, o[nt][1] * i1, lo);
        *(uint32_t*)(Oh + row1 * DIMM + col) = hi;
        *(uint32_t*)(Ol + row1 * DIMM + col) = lo;
        hi = pack_hl(o[nt][2] * i2, o[nt][3] * i2, lo);
        *(uint32_t*)(Oh + row2 * DIMM + col) = hi;
        *(uint32_t*)(Ol + row2 * DIMM + col) = lo;
    }
}

// ---------------------------------------------------------------------------
extern "C" void kernel_launch(void* const* d_in, const int* in_sizes, int n_in,
                              void* d_out, int out_size)
{
    const float* x     = (const float*)d_in[0];   // [2,2048,2048]
    const float* w_qkv = (const float*)d_in[1];   // [2048,6144]
    const float* w_out = (const float*)d_in[2];   // [2048,2048]
    float* out = (float*)d_out;                   // [2,2048,2048]

    float* qkv_p;
    __nv_bfloat16 *xh, *xl, *wqh, *wql, *woh, *wol, *ah, *al;
    __nv_bfloat16 *qh, *ql, *kh, *kl, *vh, *vl;
    cudaGetSymbolAddress((void**)&qkv_p, g_qkv);
    cudaGetSymbolAddress((void**)&xh, g_xh);
    cudaGetSymbolAddress((void**)&xl, g_xl);
    cudaGetSymbolAddress((void**)&wqh, g_wqT_h);
    cudaGetSymbolAddress((void**)&wql, g_wqT_l);
    cudaGetSymbolAddress((void**)&woh, g_woT_h);
    cudaGetSymbolAddress((void**)&wol, g_woT_l);
    cudaGetSymbolAddress((void**)&ah, g_ah);
    cudaGetSymbolAddress((void**)&al, g_al);
    cudaGetSymbolAddress((void**)&qh, g_qh);
    cudaGetSymbolAddress((void**)&ql, g_ql);
    cudaGetSymbolAddress((void**)&kh, g_kh);
    cudaGetSymbolAddress((void**)&kl, g_kl);
    cudaGetSymbolAddress((void**)&vh, g_vh);
    cudaGetSymbolAddress((void**)&vl, g_vl);

    cudaFuncSetAttribute(gemm_mma, cudaFuncAttributeMaxDynamicSharedMemorySize,
                         GEMM_SMEM);
    cudaFuncSetAttribute(attn_mma, cudaFuncAttributeMaxDynamicSharedMemorySize,
                         ATT_SMEM);

    // split x -> bf16 hi/lo
    {
        int n4 = (MROWS * DIMM) / 4;
        split_kernel<<<(n4 + 255) / 256, 256>>>(x, xh, xl, n4);
    }
    // transpose+split weights
    {
        dim3 tb(32, 8);
        transpose_split<<<dim3(QKV_W / 32, DIMM / 32), tb>>>(w_qkv, wqh, wql, DIMM, QKV_W);
        transpose_split<<<dim3(DIMM / 32, DIMM / 32), tb>>>(w_out, woh, wol, DIMM, DIMM);
    }
    // 1) QKV projection: [4096,2048] @ [2048,6144]
    gemm_mma<<<dim3(QKV_W / 128, MROWS / 128), 256, GEMM_SMEM>>>(
        xh, xl, wqh, wql, qkv_p, MROWS, QKV_W, DIMM);

    // reshape+split qkv -> per-(b,h) bf16 hi/lo operands (Q pre-scaled)
    {
        size_t n4 = (size_t)MROWS * QKV_W / 4;
        qkv_split<<<(unsigned)((n4 + 255) / 256), 256>>>(qkv_p, qh, ql, kh, kl, vh, vl);
    }

    // 2) Attention (tensor cores, bf16 split) -> writes ah/al directly
    {
        dim3 grid(S_LEN / 128, NHEADS, BATCH);
        attn_mma<<<grid, 256, ATT_SMEM>>>(qh, ql, kh, kl, vh, vl, ah, al);
    }

    // 3) Output projection: [4096,2048] @ [2048,2048]
    gemm_mma<<<dim3(DIMM / 128, MROWS / 128), 256, GEMM_SMEM>>>(
        ah, al, woh, wol, out, MROWS, DIMM, DIMM);
}

// round 7
// speedup vs baseline: 3.0076x; 1.1090x over previous
#include <cuda_runtime.h>
#include <cuda_bf16.h>
#include <math_constants.h>
#include <cstdint>
#include <cstddef>

#define S_LEN  2048
#define DIMM   2048
#define NHEADS 16
#define HD     128
#define QKV_W  6144
#define BATCH  2
#define MROWS  (BATCH * S_LEN)   // 4096
#define SCALE_F 0.08838834764831845f

// ---------------------------------------------------------------------------
// Scratch (__device__ globals: allocation-free rule)
// ---------------------------------------------------------------------------
__device__ __nv_bfloat16  g_xh[(size_t)MROWS * DIMM];
__device__ __nv_bfloat16  g_xl[(size_t)MROWS * DIMM];
__device__ __nv_bfloat16  g_wqT_h[(size_t)QKV_W * DIMM];
__device__ __nv_bfloat16  g_wqT_l[(size_t)QKV_W * DIMM];
__device__ __nv_bfloat16  g_woT_h[(size_t)DIMM * DIMM];
__device__ __nv_bfloat16  g_woT_l[(size_t)DIMM * DIMM];
__device__ __nv_bfloat16  g_ah[(size_t)MROWS * DIMM];
__device__ __nv_bfloat16  g_al[(size_t)MROWS * DIMM];
// per-(b,h) attention operands [b][h][s][128] bf16 hi/lo
#define HSD ((size_t)BATCH * NHEADS * S_LEN * HD)
__device__ __nv_bfloat16  g_qh[HSD];
__device__ __nv_bfloat16  g_ql[HSD];
__device__ __nv_bfloat16  g_kh[HSD];
__device__ __nv_bfloat16  g_kl[HSD];
__device__ __nv_bfloat16  g_vh[HSD];
__device__ __nv_bfloat16  g_vl[HSD];

// ---------------------------------------------------------------------------
// helpers
// ---------------------------------------------------------------------------
__device__ __forceinline__ uint32_t smem_u32(const void* p) {
    uint32_t a;
    asm("{ .reg .u64 t; cvta.to.shared.u64 t, %1; cvt.u32.u64 %0, t; }"
        : "=r"(a) : "l"(p));
    return a;
}
__device__ __forceinline__ void cp16(uint32_t dst, const void* src) {
    asm volatile("cp.async.cg.shared.global [%0], [%1], 16;"
                 :: "r"(dst), "l"(src) : "memory");
}
__device__ __forceinline__ void cp_commit() {
    asm volatile("cp.async.commit_group;" ::: "memory");
}
__device__ __forceinline__ void cp_wait1() {
    asm volatile("cp.async.wait_group 1;" ::: "memory");
}
__device__ __forceinline__ void mma_bf16(float* d, const uint32_t* a,
                                         const uint32_t* b) {
    asm volatile(
        "mma.sync.aligned.m16n8k16.row.col.f32.bf16.bf16.f32 "
        "{%0,%1,%2,%3}, {%4,%5,%6,%7}, {%8,%9}, {%0,%1,%2,%3};"
        : "+f"(d[0]), "+f"(d[1]), "+f"(d[2]), "+f"(d[3])
        : "r"(a[0]), "r"(a[1]), "r"(a[2]), "r"(a[3]), "r"(b[0]), "r"(b[1]));
}
__device__ __forceinline__ void ldsm4(uint32_t* r, uint32_t addr) {
    asm volatile("ldmatrix.sync.aligned.m8n8.x4.shared.b16 {%0,%1,%2,%3}, [%4];"
                 : "=r"(r[0]), "=r"(r[1]), "=r"(r[2]), "=r"(r[3]) : "r"(addr));
}
__device__ __forceinline__ void ldsm4t(uint32_t* r, uint32_t addr) {
    asm volatile("ldmatrix.sync.aligned.m8n8.x4.trans.shared.b16 {%0,%1,%2,%3}, [%4];"
                 : "=r"(r[0]), "=r"(r[1]), "=r"(r[2]), "=r"(r[3]) : "r"(addr));
}
// pack two floats into bf16x2 hi; residuals into bf16x2 lo
__device__ __forceinline__ uint32_t pack_hl(float x, float y, uint32_t& lo) {
    __nv_bfloat16 hx = __float2bfloat16_rn(x), hy = __float2bfloat16_rn(y);
    float rx = x - __bfloat162float(hx), ry = y - __bfloat162float(hy);
    unsigned short lx = __bfloat16_as_ushort(__float2bfloat16_rn(rx));
    unsigned short ly = __bfloat16_as_ushort(__float2bfloat16_rn(ry));
    lo = ((uint32_t)ly << 16) | lx;
    return ((uint32_t)__bfloat16_as_ushort(hy) << 16) | __bfloat16_as_ushort(hx);
}

// ---------------------------------------------------------------------------
// Conversion kernels
// ---------------------------------------------------------------------------
__global__ void split_kernel(const float* __restrict__ in,
                             __nv_bfloat16* __restrict__ hi,
                             __nv_bfloat16* __restrict__ lo, int n4)
{
    int i = blockIdx.x * blockDim.x + threadIdx.x;
    if (i >= n4) return;
    float4 v = ((const float4*)in)[i];
    uint32_t lo0, lo1;
    uint32_t h0 = pack_hl(v.x, v.y, lo0);
    uint32_t h1 = pack_hl(v.z, v.w, lo1);
    ((uint32_t*)hi)[i * 2]     = h0;
    ((uint32_t*)hi)[i * 2 + 1] = h1;
    ((uint32_t*)lo)[i * 2]     = lo0;
    ((uint32_t*)lo)[i * 2 + 1] = lo1;
}

// in [R,C] fp32 -> out [C,R] bf16 hi/lo
__global__ void transpose_split(const float* __restrict__ in,
                                __nv_bfloat16* __restrict__ oh,
                                __nv_bfloat16* __restrict__ ol, int R, int C)
{
    __shared__ float t[32][33];
    int bx = blockIdx.x * 32, by = blockIdx.y * 32;
    int x = threadIdx.x, y = threadIdx.y;           // 32 x 8
    #pragma unroll
    for (int i = 0; i < 32; i += 8)
        t[y + i][x] = in[(size_t)(by + y + i) * C + bx + x];
    __syncthreads();
    #pragma unroll
    for (int i = 0; i < 32; i += 8) {
        float v = t[x][y + i];
        size_t o = (size_t)(bx + y + i) * R + by + x;
        __nv_bfloat16 h = __float2bfloat16_rn(v);
        oh[o] = h;
        ol[o] = __float2bfloat16_rn(v - __bfloat162float(h));
    }
}

// ---------------------------------------------------------------------------
// mma.sync bf16-split GEMM: C = A @ B^T. 128x128 CTA tile, BK=32, 256 thr,
// 8 warps (2x4 -> warp tile 64x32). 3-stage cp.async pipeline, single sync
// per chunk. Unpadded 64B swizzled rows: slot(r,c) = (c + (r>>1)) & 3.
// SPLIT_OUT: epilogue writes bf16 hi/lo per-(b,h) Q(scaled)/K/V arrays
// instead of fp32 C.
// ---------------------------------------------------------------------------
#define ROWB 64
#define TILE_B (128 * ROWB)        // 8192
#define STAGE_B (4 * TILE_B)       // 32768: Ah, Al, Bh, Bl
#define NSTAGE 3
#define GEMM_SMEM (NSTAGE * STAGE_B)   // 98304

__device__ __forceinline__ uint32_t swoff(int row, int c16) {
    return (uint32_t)(row * ROWB + (((c16 + (row >> 1)) & 3) << 4));
}

template <bool SPLIT_OUT>
__global__ __launch_bounds__(256, 2) void gemm_mma(
    const __nv_bfloat16* __restrict__ Ah, const __nv_bfloat16* __restrict__ Al,
    const __nv_bfloat16* __restrict__ Bh, const __nv_bfloat16* __restrict__ Bl,
    float* __restrict__ C,
    __nv_bfloat16* __restrict__ QH, __nv_bfloat16* __restrict__ QL,
    __nv_bfloat16* __restrict__ KH, __nv_bfloat16* __restrict__ KL,
    __nv_bfloat16* __restrict__ VH, __nv_bfloat16* __restrict__ VL,
    int M, int N, int K)
{
    extern __shared__ char smem[];
    const uint32_t smem_base = smem_u32(smem);
    const int tid  = threadIdx.x;
    const int wid  = tid >> 5;
    const int lane = tid & 31;
    const int wm   = wid & 1;
    const int wn   = wid >> 1;
    const int bm = blockIdx.y * 128;
    const int bn = blockIdx.x * 128;

    const int lr = tid >> 1;            // load row 0..127
    const int lcb = (tid & 1) * 2;      // chunk base 0 or 2
    const int r0 = lane >> 2;
    const int c0 = (lane & 3) * 2;

    const int a_row_l = lane & 15;      // + wm*64 + mt*16
    const int a_cx    = lane >> 4;      // chunk low bit
    const int b_row_l = (lane & 7) + ((lane >> 4) << 3);   // + wn*32 + np*16
    const int b_cx    = (lane >> 3) & 1;

    float acc[4][4][4];
    #pragma unroll
    for (int mt = 0; mt < 4; mt++)
        #pragma unroll
        for (int nt = 0; nt < 4; nt++)
            #pragma unroll
            for (int j = 0; j < 4; j++) acc[mt][nt][j] = 0.0f;

    const int NC = K / 32;

    auto issue_tile = [&](const __nv_bfloat16* src, int row0, int k0,
                          uint32_t dstbase) {
        const char* g = (const char*)(src + (size_t)(row0 + lr) * K + k0);
        cp16(dstbase + swoff(lr, lcb),     g + lcb * 16);
        cp16(dstbase + swoff(lr, lcb + 1), g + lcb * 16 + 16);
    };
    auto issue_stage = [&](int c) {
        uint32_t base = smem_base + (c % NSTAGE) * STAGE_B;
        int k0 = c * 32;
        issue_tile(Ah, bm, k0, base);
        issue_tile(Al, bm, k0, base + TILE_B);
        issue_tile(Bh, bn, k0, base + 2 * TILE_B);
        issue_tile(Bl, bn, k0, base + 3 * TILE_B);
    };

    issue_stage(0); cp_commit();
    issue_stage(1); cp_commit();

    for (int c = 0; c < NC; c++) {
        cp_wait1();            // stage c complete
        __syncthreads();       // single barrier per chunk
        if (c + 2 < NC) issue_stage(c + 2);
        cp_commit();

        const uint32_t sb  = smem_base + (c % NSTAGE) * STAGE_B;
        const uint32_t sAh = sb;
        const uint32_t sAl = sb + TILE_B;
        const uint32_t sBh = sb + 2 * TILE_B;
        const uint32_t sBl = sb + 3 * TILE_B;

        #pragma unroll
        for (int ks = 0; ks < 2; ks++) {
            uint32_t ah[4][4], bx[4][2];

            // pass 1: Ah * Bh
            #pragma unroll
            for (int mt = 0; mt < 4; mt++) {
                int row = wm * 64 + mt * 16 + a_row_l;
                ldsm4(ah[mt], sAh + swoff(row, ks * 2 + a_cx));
            }
            #pragma unroll
            for (int np = 0; np < 2; np++) {
                int row = wn * 32 + np * 16 + b_row_l;
                uint32_t th[4];
                ldsm4(th, sBh + swoff(row, ks * 2 + b_cx));
                bx[np * 2][0] = th[0]; bx[np * 2][1] = th[1];
                bx[np * 2 + 1][0] = th[2]; bx[np * 2 + 1][1] = th[3];
            }
            #pragma unroll
            for (int mt = 0; mt < 4; mt++)
                #pragma unroll
                for (int nt = 0; nt < 4; nt++)
                    mma_bf16(acc[mt][nt], ah[mt], bx[nt]);

            // pass 2: Al * Bh (reuse bx)
            {
                uint32_t al[4][4];
                #pragma unroll
                for (int mt = 0; mt < 4; mt++) {
                    int row = wm * 64 + mt * 16 + a_row_l;
                    ldsm4(al[mt], sAl + swoff(row, ks * 2 + a_cx));
                }
                #pragma unroll
                for (int mt = 0; mt < 4; mt++)
                    #pragma unroll
                    for (int nt = 0; nt < 4; nt++)
                        mma_bf16(acc[mt][nt], al[mt], bx[nt]);
            }

            // pass 3: Ah * Bl (reuse ah)
            #pragma unroll
            for (int np = 0; np < 2; np++) {
                int row = wn * 32 + np * 16 + b_row_l;
                uint32_t tl[4];
                ldsm4(tl, sBl + swoff(row, ks * 2 + b_cx));
                bx[np * 2][0] = tl[0]; bx[np * 2][1] = tl[1];
                bx[np * 2 + 1][0] = tl[2]; bx[np * 2 + 1][1] = tl[3];
            }
            #pragma unroll
            for (int mt = 0; mt < 4; mt++)
                #pragma unroll
                for (int nt = 0; nt < 4; nt++)
                    mma_bf16(acc[mt][nt], ah[mt], bx[nt]);
        }
    }

    // epilogue
    if (!SPLIT_OUT) {
        #pragma unroll
        for (int mt = 0; mt < 4; mt++) {
            int row = bm + wm * 64 + mt * 16 + r0;
            #pragma unroll
            for (int nt = 0; nt < 4; nt++) {
                int col = bn + wn * 32 + nt * 8 + c0;
                float* p0 = C + (size_t)row * N + col;
                float* p1 = p0 + 8 * (size_t)N;
                *(float2*)p0 = make_float2(acc[mt][nt][0], acc[mt][nt][1]);
                *(float2*)p1 = make_float2(acc[mt][nt][2], acc[mt][nt][3]);
            }
        }
    } else {
        // columns map to (sec, head, d); whole CTA tile is inside one head
        const int sec = bn >> 11;
        const int hh  = (bn >> 7) & 15;
        const float sc = (sec == 0) ? SCALE_F : 1.0f;
        __nv_bfloat16 *H, *L;
        if (sec == 0)      { H = QH; L = QL; }
        else if (sec == 1) { H = KH; L = KL; }
        else               { H = VH; L = VL; }
        #pragma unroll
        for (int mt = 0; mt < 4; mt++) {
            int row = bm + wm * 64 + mt * 16 + r0;   // row & row+8
            #pragma unroll
            for (int nt = 0; nt < 4; nt++) {
                int d = (wn * 32 + nt * 8 + c0) & 127;
                #pragma unroll
                for (int half = 0; half < 2; half++) {
                    int rr = row + half * 8;
                    int bb = rr >> 11, ss = rr & 2047;
                    size_t dst = (((size_t)(bb * NHEADS + hh)) * S_LEN + ss) * HD + d;
                    uint32_t lo, hi;
                    hi = pack_hl(acc[mt][nt][half * 2] * sc,
                                 acc[mt][nt][half * 2 + 1] * sc, lo);
                    *(uint32_t*)(H + dst) = hi;
                    *(uint32_t*)(L + dst) = lo;
                }
            }
        }
    }
}

// ---------------------------------------------------------------------------
// Tensor-core flash attention (bf16 split) — unchanged from R6.
// ---------------------------------------------------------------------------
#define ATT_SMEM (65536 + 2 * 65536)   // 196608

__global__ __launch_bounds__(256, 1) void attn_mma(
    const __nv_bfloat16* __restrict__ Qh, const __nv_bfloat16* __restrict__ Ql,
    const __nv_bfloat16* __restrict__ Kh, const __nv_bfloat16* __restrict__ Kl,
    const __nv_bfloat16* __restrict__ Vh, const __nv_bfloat16* __restrict__ Vl,
    __nv_bfloat16* __restrict__ Oh, __nv_bfloat16* __restrict__ Ol)
{
    extern __shared__ char smem[];
    const uint32_t sb0 = smem_u32(smem);
    const uint32_t sQh = sb0, sQl = sb0 + 32768;
    const int tid = threadIdx.x, wid = tid >> 5, lane = tid & 31;
    const int q0 = blockIdx.x * 128, h = blockIdx.y, b = blockIdx.z;

    const size_t hb = ((size_t)(b * NHEADS + h)) * S_LEN * HD;
    const __nv_bfloat16* gqh = Qh + hb + (size_t)q0 * HD;
    const __nv_bfloat16* gql = Ql + hb + (size_t)q0 * HD;
    const __nv_bfloat16* gkh = Kh + hb;
    const __nv_bfloat16* gkl = Kl + hb;
    const __nv_bfloat16* gvh = Vh + hb;
    const __nv_bfloat16* gvl = Vl + hb;

    {
        int r = tid >> 1, cb = (tid & 1) * 8;
        const char* g0 = (const char*)(gqh + (size_t)r * HD);
        const char* g1 = (const char*)(gql + (size_t)r * HD);
        uint32_t d0 = sQh + r * 256, d1 = sQl + r * 256;
        #pragma unroll
        for (int j = 0; j < 8; j++) {
            int c = cb + j;
            uint32_t sw = (uint32_t)((c ^ (r & 7)) << 4);
            cp16(d0 + sw, g0 + c * 16);
            cp16(d1 + sw, g1 + c * 16);
        }
    }
    auto ld_stage = [&](int t) {
        uint32_t base = sb0 + 65536 + (t & 1) * 65536;
        int s0 = t * 64;
        int r = tid >> 2, cb = (tid & 3) * 4;
        const char* g0 = (const char*)(gkh + (size_t)(s0 + r) * HD);
        const char* g1 = (const char*)(gkl + (size_t)(s0 + r) * HD);
        const char* g2 = (const char*)(gvh + (size_t)(s0 + r) * HD);
        const char* g3 = (const char*)(gvl + (size_t)(s0 + r) * HD);
        uint32_t dr = base + r * 256;
        #pragma unroll
        for (int j = 0; j < 4; j++) {
            int c = cb + j;
            uint32_t sw = (uint32_t)((c ^ (r & 7)) << 4);
            cp16(dr + sw,             g0 + c * 16);
            cp16(dr + 16384 + sw,     g1 + c * 16);
            cp16(dr + 32768 + sw,     g2 + c * 16);
            cp16(dr + 49152 + sw,     g3 + c * 16);
        }
    };

    ld_stage(0); cp_commit();
    ld_stage(1); cp_commit();

    const int aq_row = wid * 16 + (lane & 15);
    const uint32_t aq_base = (uint32_t)(aq_row * 256);
    const int aq_r7 = aq_row & 7;
    const int aq_cx = lane >> 4;
    const int bk_row = (lane & 7) + ((lane >> 4) << 3);
    const int bk_cx = (lane >> 3) & 1;
    const int bv_row = (lane & 7) + (((lane >> 3) & 1) << 3);
    const int bv_cx = lane >> 4;

    float o[16][4];
    #pragma unroll
    for (int nt = 0; nt < 16; nt++) { o[nt][0]=o[nt][1]=o[nt][2]=o[nt][3]=0.f; }
    float mr1 = -CUDART_INF_F, mr2 = -CUDART_INF_F, lr1 = 0.f, lr2 = 0.f;

    for (int t = 0; t < S_LEN / 64; t++) {
        cp_wait1();
        __syncthreads();
        uint32_t stg = sb0 + 65536 + (t & 1) * 65536;
        uint32_t sK  = stg, sKl_ = stg + 16384, sV = stg + 32768, sVl_ = stg + 49152;

        float s[8][4];
        #pragma unroll
        for (int i = 0; i < 8; i++) { s[i][0]=s[i][1]=s[i][2]=s[i][3]=0.f; }

        #pragma unroll
        for (int kt = 0; kt < 8; kt++) {
            uint32_t ah4[4], al4[4];
            {
                int c16 = kt * 2 + aq_cx;
                uint32_t off = aq_base + (uint32_t)(((c16 ^ aq_r7)) << 4);
                ldsm4(ah4, sQh + off);
                ldsm4(al4, sQl + off);
            }
            #pragma unroll
            for (int np = 0; np < 4; np++) {
                int row = np * 16 + bk_row;
                int c16 = kt * 2 + bk_cx;
                uint32_t off = (uint32_t)(row * 256) + (uint32_t)(((c16 ^ (row & 7))) << 4);
                uint32_t bh4[4];
                ldsm4(bh4, sK + off);
                mma_bf16(s[2*np],   ah4, bh4);
                mma_bf16(s[2*np+1], ah4, bh4 + 2);
                mma_bf16(s[2*np],   al4, bh4);
                mma_bf16(s[2*np+1], al4, bh4 + 2);
                uint32_t bl4[4];
                ldsm4(bl4, sKl_ + off);
                mma_bf16(s[2*np],   ah4, bl4);
                mma_bf16(s[2*np+1], ah4, bl4 + 2);
            }
        }

        float m1 = s[0][0], m2 = s[0][2];
        #pragma unroll
        for (int i = 0; i < 8; i++) {
            m1 = fmaxf(m1, fmaxf(s[i][0], s[i][1]));
            m2 = fmaxf(m2, fmaxf(s[i][2], s[i][3]));
        }
        m1 = fmaxf(m1, __shfl_xor_sync(0xffffffffu, m1, 1));
        m1 = fmaxf(m1, __shfl_xor_sync(0xffffffffu, m1, 2));
        m2 = fmaxf(m2, __shfl_xor_sync(0xffffffffu, m2, 1));
        m2 = fmaxf(m2, __shfl_xor_sync(0xffffffffu, m2, 2));
        float mn1 = fmaxf(mr1, m1), mn2 = fmaxf(mr2, m2);
        float a1 = __expf(mr1 - mn1), a2 = __expf(mr2 - mn2);
        mr1 = mn1; mr2 = mn2;
        float l1 = 0.f, l2 = 0.f;
        #pragma unroll
        for (int i = 0; i < 8; i++) {
            s[i][0] = __expf(s[i][0] - mn1); s[i][1] = __expf(s[i][1] - mn1);
            s[i][2] = __expf(s[i][2] - mn2); s[i][3] = __expf(s[i][3] - mn2);
            l1 += s[i][0] + s[i][1];
            l2 += s[i][2] + s[i][3];
        }
        l1 += __shfl_xor_sync(0xffffffffu, l1, 1);
        l1 += __shfl_xor_sync(0xffffffffu, l1, 2);
        l2 += __shfl_xor_sync(0xffffffffu, l2, 1);
        l2 += __shfl_xor_sync(0xffffffffu, l2, 2);
        lr1 = lr1 * a1 + l1;
        lr2 = lr2 * a2 + l2;
        #pragma unroll
        for (int nt = 0; nt < 16; nt++) {
            o[nt][0] *= a1; o[nt][1] *= a1; o[nt][2] *= a2; o[nt][3] *= a2;
        }

        uint32_t ph[4][4], pl[4][4];
        #pragma unroll
        for (int k2 = 0; k2 < 4; k2++) {
            ph[k2][0] = pack_hl(s[2*k2][0],   s[2*k2][1],   pl[k2][0]);
            ph[k2][1] = pack_hl(s[2*k2][2],   s[2*k2][3],   pl[k2][1]);
            ph[k2][2] = pack_hl(s[2*k2+1][0], s[2*k2+1][1], pl[k2][2]);
            ph[k2][3] = pack_hl(s[2*k2+1][2], s[2*k2+1][3], pl[k2][3]);
        }

        #pragma unroll
        for (int k2 = 0; k2 < 4; k2++) {
            #pragma unroll
            for (int np = 0; np < 8; np++) {
                int row = k2 * 16 + bv_row;
                int c16 = np * 2 + bv_cx;
                uint32_t off = (uint32_t)(row * 256) + (uint32_t)(((c16 ^ (row & 7))) << 4);
                uint32_t v4[4];
                ldsm4t(v4, sV + off);
                mma_bf16(o[2*np],   ph[k2], v4);
                mma_bf16(o[2*np+1], ph[k2], v4 + 2);
                mma_bf16(o[2*np],   pl[k2], v4);
                mma_bf16(o[2*np+1], pl[k2], v4 + 2);
                uint32_t w4[4];
                ldsm4t(w4, sVl_ + off);
                mma_bf16(o[2*np],   ph[k2], w4);
                mma_bf16(o[2*np+1], ph[k2], w4 + 2);
            }
        }

        __syncthreads();
        if (t + 2 < S_LEN / 64) ld_stage(t + 2);
        cp_commit();
    }

    float i1 = 1.f / lr1, i2 = 1.f / lr2;
    int r1 = lane >> 2, c2 = (lane & 3) * 2;
    size_t row1 = (size_t)b * S_LEN + q0 + wid * 16 + r1;
    size_t row2 = row1 + 8;
    #pragma unroll
    for (int nt = 0; nt < 16; nt++) {
        int col = h * HD + nt * 8 + c2;
        uint32_t lo, hi;
        hi = pack_hl(o[nt][0] * i1, o[nt][1] * i1, lo);
        *(uint32_t*)(Oh + row1 * DIMM + col) = hi;
        *(uint32_t*)(Ol + row1 * DIMM + col) = lo;
        hi = pack_hl(o[nt][2] * i2, o[nt][3] * i2, lo);
        *(uint32_t*)(Oh + row2 * DIMM + col) = hi;
        *(uint32_t*)(Ol + row2 * DIMM + col) = lo;
    }
}

// ---------------------------------------------------------------------------
extern "C" void kernel_launch(void* const* d_in, const int* in_sizes, int n_in,
                              void* d_out, int out_size)
{
    const float* x     = (const float*)d_in[0];   // [2,2048,2048]
    const float* w_qkv = (const float*)d_in[1];   // [2048,6144]
    const float* w_out = (const float*)d_in[2];   // [2048,2048]
    float* out = (float*)d_out;                   // [2,2048,2048]

    __nv_bfloat16 *xh, *xl, *wqh, *wql, *woh, *wol, *ah, *al;
    __nv_bfloat16 *qh, *ql, *kh, *kl, *vh, *vl;
    cudaGetSymbolAddress((void**)&xh, g_xh);
    cudaGetSymbolAddress((void**)&xl, g_xl);
    cudaGetSymbolAddress((void**)&wqh, g_wqT_h);
    cudaGetSymbolAddress((void**)&wql, g_wqT_l);
    cudaGetSymbolAddress((void**)&woh, g_woT_h);
    cudaGetSymbolAddress((void**)&wol, g_woT_l);
    cudaGetSymbolAddress((void**)&ah, g_ah);
    cudaGetSymbolAddress((void**)&al, g_al);
    cudaGetSymbolAddress((void**)&qh, g_qh);
    cudaGetSymbolAddress((void**)&ql, g_ql);
    cudaGetSymbolAddress((void**)&kh, g_kh);
    cudaGetSymbolAddress((void**)&kl, g_kl);
    cudaGetSymbolAddress((void**)&vh, g_vh);
    cudaGetSymbolAddress((void**)&vl, g_vl);

    cudaFuncSetAttribute(gemm_mma<true>,
                         cudaFuncAttributeMaxDynamicSharedMemorySize, GEMM_SMEM);
    cudaFuncSetAttribute(gemm_mma<false>,
                         cudaFuncAttributeMaxDynamicSharedMemorySize, GEMM_SMEM);
    cudaFuncSetAttribute(attn_mma,
                         cudaFuncAttributeMaxDynamicSharedMemorySize, ATT_SMEM);

    // split x -> bf16 hi/lo
    {
        int n4 = (MROWS * DIMM) / 4;
        split_kernel<<<(n4 + 255) / 256, 256>>>(x, xh, xl, n4);
    }
    // transpose+split weights
    {
        dim3 tb(32, 8);
        transpose_split<<<dim3(QKV_W / 32, DIMM / 32), tb>>>(w_qkv, wqh, wql, DIMM, QKV_W);
        transpose_split<<<dim3(DIMM / 32, DIMM / 32), tb>>>(w_out, woh, wol, DIMM, DIMM);
    }
    // 1) QKV projection, fused reshape+split epilogue (Q pre-scaled)
    gemm_mma<true><<<dim3(QKV_W / 128, MROWS / 128), 256, GEMM_SMEM>>>(
        xh, xl, wqh, wql, nullptr, qh, ql, kh, kl, vh, vl, MROWS, QKV_W, DIMM);

    // 2) Attention (tensor cores, bf16 split) -> writes ah/al directly
    {
        dim3 grid(S_LEN / 128, NHEADS, BATCH);
        attn_mma<<<grid, 256, ATT_SMEM>>>(qh, ql, kh, kl, vh, vl, ah, al);
    }

    // 3) Output projection -> fp32 out
    gemm_mma<false><<<dim3(DIMM / 128, MROWS / 128), 256, GEMM_SMEM>>>(
        ah, al, woh, wol, out, nullptr, nullptr, nullptr, nullptr, nullptr,
        nullptr, MROWS, DIMM, DIMM);
}

// round 8
// speedup vs baseline: 4.4980x; 1.4955x over previous
#include <cuda_runtime.h>
#include <cuda_fp16.h>
#include <math_constants.h>
#include <cstdint>
#include <cstddef>

#define S_LEN  2048
#define DIMM   2048
#define NHEADS 16
#define HD     128
#define QKV_W  6144
#define BATCH  2
#define MROWS  (BATCH * S_LEN)   // 4096
#define SCALE_F 0.08838834764831845f

// ---------------------------------------------------------------------------
// Scratch (__device__ globals: allocation-free rule)
// ---------------------------------------------------------------------------
__device__ __half  g_xh[(size_t)MROWS * DIMM];
__device__ __half  g_xl[(size_t)MROWS * DIMM];
__device__ __half  g_wqT_h[(size_t)QKV_W * DIMM];   // [6144,2048] K-major (B^T), hi only
__device__ __half  g_woT_h[(size_t)DIMM * DIMM];    // [2048,2048] K-major, hi only
__device__ __half  g_ah[(size_t)MROWS * DIMM];      // attention out hi
__device__ __half  g_al[(size_t)MROWS * DIMM];      // attention out lo
// per-(b,h) attention operands [b][h][s][128]
#define HSD ((size_t)BATCH * NHEADS * S_LEN * HD)
__device__ __half  g_qh[HSD];
__device__ __half  g_ql[HSD];
__device__ __half  g_kh[HSD];   // hi only
__device__ __half  g_vh[HSD];   // hi only

// ---------------------------------------------------------------------------
// helpers
// ---------------------------------------------------------------------------
__device__ __forceinline__ uint32_t smem_u32(const void* p) {
    uint32_t a;
    asm("{ .reg .u64 t; cvta.to.shared.u64 t, %1; cvt.u32.u64 %0, t; }"
        : "=r"(a) : "l"(p));
    return a;
}
__device__ __forceinline__ void cp16(uint32_t dst, const void* src) {
    asm volatile("cp.async.cg.shared.global [%0], [%1], 16;"
                 :: "r"(dst), "l"(src) : "memory");
}
__device__ __forceinline__ void cp_commit() {
    asm volatile("cp.async.commit_group;" ::: "memory");
}
__device__ __forceinline__ void cp_wait1() {
    asm volatile("cp.async.wait_group 1;" ::: "memory");
}
__device__ __forceinline__ void cp_wait2() {
    asm volatile("cp.async.wait_group 2;" ::: "memory");
}
__device__ __forceinline__ void mma_f16(float* d, const uint32_t* a,
                                        const uint32_t* b) {
    asm volatile(
        "mma.sync.aligned.m16n8k16.row.col.f32.f16.f16.f32 "
        "{%0,%1,%2,%3}, {%4,%5,%6,%7}, {%8,%9}, {%0,%1,%2,%3};"
        : "+f"(d[0]), "+f"(d[1]), "+f"(d[2]), "+f"(d[3])
        : "r"(a[0]), "r"(a[1]), "r"(a[2]), "r"(a[3]), "r"(b[0]), "r"(b[1]));
}
__device__ __forceinline__ void ldsm4(uint32_t* r, uint32_t addr) {
    asm volatile("ldmatrix.sync.aligned.m8n8.x4.shared.b16 {%0,%1,%2,%3}, [%4];"
                 : "=r"(r[0]), "=r"(r[1]), "=r"(r[2]), "=r"(r[3]) : "r"(addr));
}
__device__ __forceinline__ void ldsm4t(uint32_t* r, uint32_t addr) {
    asm volatile("ldmatrix.sync.aligned.m8n8.x4.trans.shared.b16 {%0,%1,%2,%3}, [%4];"
                 : "=r"(r[0]), "=r"(r[1]), "=r"(r[2]), "=r"(r[3]) : "r"(addr));
}
// pack two floats into fp16x2 hi; residuals into fp16x2 lo
__device__ __forceinline__ uint32_t pack_hl(float x, float y, uint32_t& lo) {
    __half hx = __float2half_rn(x), hy = __float2half_rn(y);
    float rx = x - __half2float(hx), ry = y - __half2float(hy);
    unsigned short lx = __half_as_ushort(__float2half_rn(rx));
    unsigned short ly = __half_as_ushort(__float2half_rn(ry));
    lo = ((uint32_t)ly << 16) | lx;
    return ((uint32_t)__half_as_ushort(hy) << 16) | __half_as_ushort(hx);
}
__device__ __forceinline__ uint32_t pack_h(float x, float y) {
    return ((uint32_t)__half_as_ushort(__float2half_rn(y)) << 16)
         | (uint32_t)__half_as_ushort(__float2half_rn(x));
}

// ---------------------------------------------------------------------------
// Conversion kernels
// ---------------------------------------------------------------------------
__global__ void split_kernel(const float* __restrict__ in,
                             __half* __restrict__ hi,
                             __half* __restrict__ lo, int n4)
{
    int i = blockIdx.x * blockDim.x + threadIdx.x;
    if (i >= n4) return;
    float4 v = ((const float4*)in)[i];
    uint32_t lo0, lo1;
    uint32_t h0 = pack_hl(v.x, v.y, lo0);
    uint32_t h1 = pack_hl(v.z, v.w, lo1);
    ((uint32_t*)hi)[i * 2]     = h0;
    ((uint32_t*)hi)[i * 2 + 1] = h1;
    ((uint32_t*)lo)[i * 2]     = lo0;
    ((uint32_t*)lo)[i * 2 + 1] = lo1;
}

// in [R,C] fp32 -> out [C,R] fp16 (hi only)
__global__ void transpose_half(const float* __restrict__ in,
                               __half* __restrict__ oh, int R, int C)
{
    __shared__ float t[32][33];
    int bx = blockIdx.x * 32, by = blockIdx.y * 32;
    int x = threadIdx.x, y = threadIdx.y;           // 32 x 8
    #pragma unroll
    for (int i = 0; i < 32; i += 8)
        t[y + i][x] = in[(size_t)(by + y + i) * C + bx + x];
    __syncthreads();
    #pragma unroll
    for (int i = 0; i < 32; i += 8) {
        float v = t[x][y + i];
        oh[(size_t)(bx + y + i) * R + by + x] = __float2half_rn(v);
    }
}

// ---------------------------------------------------------------------------
// mma.sync fp16 2-term GEMM: C = A @ B^T,  D ~= Ah*Bh + Al*Bh.
// 128x128 CTA tile, BK=32, 256 thr, 8 warps (2x4 -> warp tile 64x32).
// 4-stage cp.async pipeline (96KB -> 2 CTAs/SM), single sync/chunk,
// warp-staggered ks order. SPLIT_OUT: writes Q(hi/lo, scaled), K(hi), V(hi).
// ---------------------------------------------------------------------------
#define ROWB 64
#define TILE_B (128 * ROWB)        // 8192
#define STAGE_B (3 * TILE_B)       // 24576: Ah, Al, Bh
#define NSTAGE 4
#define GEMM_SMEM (NSTAGE * STAGE_B)   // 98304

__device__ __forceinline__ uint32_t swoff(int row, int c16) {
    return (uint32_t)(row * ROWB + (((c16 + (row >> 1)) & 3) << 4));
}

template <bool SPLIT_OUT>
__global__ __launch_bounds__(256, 2) void gemm_mma(
    const __half* __restrict__ Ah, const __half* __restrict__ Al,
    const __half* __restrict__ Bh,
    float* __restrict__ C,
    __half* __restrict__ QH, __half* __restrict__ QL,
    __half* __restrict__ KH, __half* __restrict__ VH,
    int M, int N, int K)
{
    extern __shared__ char smem[];
    const uint32_t smem_base = smem_u32(smem);
    const int tid  = threadIdx.x;
    const int wid  = tid >> 5;
    const int lane = tid & 31;
    const int wm   = wid & 1;
    const int wn   = wid >> 1;
    const int bm = blockIdx.y * 128;
    const int bn = blockIdx.x * 128;

    const int lr = tid >> 1;            // load row 0..127
    const int lcb = (tid & 1) * 2;      // chunk base 0 or 2
    const int r0 = lane >> 2;
    const int c0 = (lane & 3) * 2;

    const int a_row_l = lane & 15;
    const int a_cx    = lane >> 4;
    const int b_row_l = (lane & 7) + ((lane >> 4) << 3);
    const int b_cx    = (lane >> 3) & 1;

    float acc[4][4][4];
    #pragma unroll
    for (int mt = 0; mt < 4; mt++)
        #pragma unroll
        for (int nt = 0; nt < 4; nt++)
            #pragma unroll
            for (int j = 0; j < 4; j++) acc[mt][nt][j] = 0.0f;

    const int NC = K / 32;

    auto issue_tile = [&](const __half* src, int row0, int k0,
                          uint32_t dstbase) {
        const char* g = (const char*)(src + (size_t)(row0 + lr) * K + k0);
        cp16(dstbase + swoff(lr, lcb),     g + lcb * 16);
        cp16(dstbase + swoff(lr, lcb + 1), g + lcb * 16 + 16);
    };
    auto issue_stage = [&](int c) {
        uint32_t base = smem_base + (c % NSTAGE) * STAGE_B;
        int k0 = c * 32;
        issue_tile(Ah, bm, k0, base);
        issue_tile(Al, bm, k0, base + TILE_B);
        issue_tile(Bh, bn, k0, base + 2 * TILE_B);
    };

    issue_stage(0); cp_commit();
    issue_stage(1); cp_commit();
    issue_stage(2); cp_commit();

    for (int c = 0; c < NC; c++) {
        cp_wait2();            // stage c complete
        __syncthreads();
        if (c + 3 < NC) issue_stage(c + 3);
        cp_commit();

        const uint32_t sb  = smem_base + (c % NSTAGE) * STAGE_B;
        const uint32_t sAh = sb;
        const uint32_t sAl = sb + TILE_B;
        const uint32_t sBh = sb + 2 * TILE_B;

        #pragma unroll
        for (int kss = 0; kss < 2; kss++) {
            const int ks = kss ^ (wid & 1);    // warp-staggered phases
            uint32_t ah[4][4], bx[4][2];

            // pass 1: Ah * Bh
            #pragma unroll
            for (int mt = 0; mt < 4; mt++) {
                int row = wm * 64 + mt * 16 + a_row_l;
                ldsm4(ah[mt], sAh + swoff(row, ks * 2 + a_cx));
            }
            #pragma unroll
            for (int np = 0; np < 2; np++) {
                int row = wn * 32 + np * 16 + b_row_l;
                uint32_t th[4];
                ldsm4(th, sBh + swoff(row, ks * 2 + b_cx));
                bx[np * 2][0] = th[0]; bx[np * 2][1] = th[1];
                bx[np * 2 + 1][0] = th[2]; bx[np * 2 + 1][1] = th[3];
            }
            #pragma unroll
            for (int mt = 0; mt < 4; mt++)
                #pragma unroll
                for (int nt = 0; nt < 4; nt++)
                    mma_f16(acc[mt][nt], ah[mt], bx[nt]);

            // pass 2: Al * Bh (reuse bx)
            {
                uint32_t al[4][4];
                #pragma unroll
                for (int mt = 0; mt < 4; mt++) {
                    int row = wm * 64 + mt * 16 + a_row_l;
                    ldsm4(al[mt], sAl + swoff(row, ks * 2 + a_cx));
                }
                #pragma unroll
                for (int mt = 0; mt < 4; mt++)
                    #pragma unroll
                    for (int nt = 0; nt < 4; nt++)
                        mma_f16(acc[mt][nt], al[mt], bx[nt]);
            }
        }
    }

    // epilogue
    if (!SPLIT_OUT) {
        #pragma unroll
        for (int mt = 0; mt < 4; mt++) {
            int row = bm + wm * 64 + mt * 16 + r0;
            #pragma unroll
            for (int nt = 0; nt < 4; nt++) {
                int col = bn + wn * 32 + nt * 8 + c0;
                float* p0 = C + (size_t)row * N + col;
                float* p1 = p0 + 8 * (size_t)N;
                *(float2*)p0 = make_float2(acc[mt][nt][0], acc[mt][nt][1]);
                *(float2*)p1 = make_float2(acc[mt][nt][2], acc[mt][nt][3]);
            }
        }
    } else {
        const int sec = bn >> 11;           // 0=Q, 1=K, 2=V
        const int hh  = (bn >> 7) & 15;
        #pragma unroll
        for (int mt = 0; mt < 4; mt++) {
            int row = bm + wm * 64 + mt * 16 + r0;
            #pragma unroll
            for (int nt = 0; nt < 4; nt++) {
                int d = (wn * 32 + nt * 8 + c0) & 127;
                #pragma unroll
                for (int half = 0; half < 2; half++) {
                    int rr = row + half * 8;
                    int bb = rr >> 11, ss = rr & 2047;
                    size_t dst = (((size_t)(bb * NHEADS + hh)) * S_LEN + ss) * HD + d;
                    float v0 = acc[mt][nt][half * 2];
                    float v1 = acc[mt][nt][half * 2 + 1];
                    if (sec == 0) {
                        uint32_t lo, hi;
                        hi = pack_hl(v0 * SCALE_F, v1 * SCALE_F, lo);
                        *(uint32_t*)(QH + dst) = hi;
                        *(uint32_t*)(QL + dst) = lo;
                    } else if (sec == 1) {
                        *(uint32_t*)(KH + dst) = pack_h(v0, v1);
                    } else {
                        *(uint32_t*)(VH + dst) = pack_h(v0, v1);
                    }
                }
            }
        }
    }
}

// ---------------------------------------------------------------------------
// Tensor-core flash attention, fp16 2-term. 1 CTA per (b,h,128 queries),
// 8 warps x 16 query rows. BKV=32, 3-stage K/V pipeline (hi only).
// smem: Q hi/lo 64KB + 3 x 16KB = 112KB -> 2 CTAs/SM.
// S ~= Qh*Kh + Ql*Kh ; O += Ph*Vh + Pl*Vh. P stays in registers.
// ---------------------------------------------------------------------------
#define BKV 32
#define KV_STAGE_B 16384           // Kh 8KB + Vh 8KB
#define ATT_SMEM (65536 + 3 * KV_STAGE_B)   // 114688

__global__ __launch_bounds__(256, 2) void attn_mma(
    const __half* __restrict__ Qh, const __half* __restrict__ Ql,
    const __half* __restrict__ Kh, const __half* __restrict__ Vh,
    __half* __restrict__ Oh, __half* __restrict__ Ol)
{
    extern __shared__ char smem[];
    const uint32_t sb0 = smem_u32(smem);
    const uint32_t sQh = sb0, sQl = sb0 + 32768;
    const int tid = threadIdx.x, wid = tid >> 5, lane = tid & 31;
    const int q0 = blockIdx.x * 128, h = blockIdx.y, b = blockIdx.z;

    const size_t hb = ((size_t)(b * NHEADS + h)) * S_LEN * HD;
    const __half* gqh = Qh + hb + (size_t)q0 * HD;
    const __half* gql = Ql + hb + (size_t)q0 * HD;
    const __half* gkh = Kh + hb;
    const __half* gvh = Vh + hb;

    // Q (128 rows x 256B), hi + lo
    {
        int r = tid >> 1, cb = (tid & 1) * 8;
        const char* g0 = (const char*)(gqh + (size_t)r * HD);
        const char* g1 = (const char*)(gql + (size_t)r * HD);
        uint32_t d0 = sQh + r * 256, d1 = sQl + r * 256;
        #pragma unroll
        for (int j = 0; j < 8; j++) {
            int c = cb + j;
            uint32_t sw = (uint32_t)((c ^ (r & 7)) << 4);
            cp16(d0 + sw, g0 + c * 16);
            cp16(d1 + sw, g1 + c * 16);
        }
    }
    auto ld_stage = [&](int t) {
        uint32_t base = sb0 + 65536 + (t % 3) * KV_STAGE_B;
        int s0 = t * BKV;
        int r = tid >> 3;          // 0..31
        int cb = (tid & 7) * 2;    // 0..14
        const char* gk = (const char*)(gkh + (size_t)(s0 + r) * HD);
        const char* gv = (const char*)(gvh + (size_t)(s0 + r) * HD);
        uint32_t dr = base + r * 256;
        #pragma unroll
        for (int j = 0; j < 2; j++) {
            int c = cb + j;
            uint32_t sw = (uint32_t)((c ^ (r & 7)) << 4);
            cp16(dr + sw,        gk + c * 16);
            cp16(dr + 8192 + sw, gv + c * 16);
        }
    };

    ld_stage(0); cp_commit();      // Q rides in group 0
    ld_stage(1); cp_commit();

    const int aq_row = wid * 16 + (lane & 15);
    const uint32_t aq_base = (uint32_t)(aq_row * 256);
    const int aq_r7 = aq_row & 7;
    const int aq_cx = lane >> 4;
    const int bk_row = (lane & 7) + ((lane >> 4) << 3);
    const int bk_cx = (lane >> 3) & 1;
    const int bv_row = (lane & 7) + (((lane >> 3) & 1) << 3);
    const int bv_cx = lane >> 4;

    float o[16][4];
    #pragma unroll
    for (int nt = 0; nt < 16; nt++) { o[nt][0]=o[nt][1]=o[nt][2]=o[nt][3]=0.f; }
    float mr1 = -CUDART_INF_F, mr2 = -CUDART_INF_F, lr1 = 0.f, lr2 = 0.f;

    const int NT = S_LEN / BKV;    // 64
    for (int t = 0; t < NT; t++) {
        cp_wait1();
        __syncthreads();
        if (t + 2 < NT) ld_stage(t + 2);
        cp_commit();

        uint32_t sK = sb0 + 65536 + (t % 3) * KV_STAGE_B;
        uint32_t sV = sK + 8192;

        // ---- S = Q.K^T (2 terms) ----
        float s[4][4];
        #pragma unroll
        for (int i = 0; i < 4; i++) { s[i][0]=s[i][1]=s[i][2]=s[i][3]=0.f; }

        #pragma unroll
        for (int kt = 0; kt < 8; kt++) {
            uint32_t ah4[4], al4[4];
            {
                int c16 = kt * 2 + aq_cx;
                uint32_t off = aq_base + (uint32_t)(((c16 ^ aq_r7)) << 4);
                ldsm4(ah4, sQh + off);
                ldsm4(al4, sQl + off);
            }
            #pragma unroll
            for (int np = 0; np < 2; np++) {
                int row = np * 16 + bk_row;
                int c16 = kt * 2 + bk_cx;
                uint32_t off = (uint32_t)(row * 256) + (uint32_t)(((c16 ^ (row & 7))) << 4);
                uint32_t bh4[4];
                ldsm4(bh4, sK + off);
                mma_f16(s[2*np],   ah4, bh4);
                mma_f16(s[2*np+1], ah4, bh4 + 2);
                mma_f16(s[2*np],   al4, bh4);
                mma_f16(s[2*np+1], al4, bh4 + 2);
            }
        }

        // ---- online softmax (rows r1 = lane>>2 and r1+8) ----
        float m1 = s[0][0], m2 = s[0][2];
        #pragma unroll
        for (int i = 0; i < 4; i++) {
            m1 = fmaxf(m1, fmaxf(s[i][0], s[i][1]));
            m2 = fmaxf(m2, fmaxf(s[i][2], s[i][3]));
        }
        m1 = fmaxf(m1, __shfl_xor_sync(0xffffffffu, m1, 1));
        m1 = fmaxf(m1, __shfl_xor_sync(0xffffffffu, m1, 2));
        m2 = fmaxf(m2, __shfl_xor_sync(0xffffffffu, m2, 1));
        m2 = fmaxf(m2, __shfl_xor_sync(0xffffffffu, m2, 2));
        float mn1 = fmaxf(mr1, m1), mn2 = fmaxf(mr2, m2);
        float a1 = __expf(mr1 - mn1), a2 = __expf(mr2 - mn2);
        mr1 = mn1; mr2 = mn2;
        float l1 = 0.f, l2 = 0.f;
        #pragma unroll
        for (int i = 0; i < 4; i++) {
            s[i][0] = __expf(s[i][0] - mn1); s[i][1] = __expf(s[i][1] - mn1);
            s[i][2] = __expf(s[i][2] - mn2); s[i][3] = __expf(s[i][3] - mn2);
            l1 += s[i][0] + s[i][1];
            l2 += s[i][2] + s[i][3];
        }
        l1 += __shfl_xor_sync(0xffffffffu, l1, 1);
        l1 += __shfl_xor_sync(0xffffffffu, l1, 2);
        l2 += __shfl_xor_sync(0xffffffffu, l2, 1);
        l2 += __shfl_xor_sync(0xffffffffu, l2, 2);
        lr1 = lr1 * a1 + l1;
        lr2 = lr2 * a2 + l2;
        #pragma unroll
        for (int nt = 0; nt < 16; nt++) {
            o[nt][0] *= a1; o[nt][1] *= a1; o[nt][2] *= a2; o[nt][3] *= a2;
        }

        // ---- pack P -> fp16 hi/lo A-fragments ----
        uint32_t ph[2][4], pl[2][4];
        #pragma unroll
        for (int k2 = 0; k2 < 2; k2++) {
            ph[k2][0] = pack_hl(s[2*k2][0],   s[2*k2][1],   pl[k2][0]);
            ph[k2][1] = pack_hl(s[2*k2][2],   s[2*k2][3],   pl[k2][1]);
            ph[k2][2] = pack_hl(s[2*k2+1][0], s[2*k2+1][1], pl[k2][2]);
            ph[k2][3] = pack_hl(s[2*k2+1][2], s[2*k2+1][3], pl[k2][3]);
        }

        // ---- O += P.V (2 terms), V via ldmatrix.trans ----
        #pragma unroll
        for (int k2 = 0; k2 < 2; k2++) {
            #pragma unroll
            for (int np = 0; np < 8; np++) {
                int row = k2 * 16 + bv_row;
                int c16 = np * 2 + bv_cx;
                uint32_t off = (uint32_t)(row * 256) + (uint32_t)(((c16 ^ (row & 7))) << 4);
                uint32_t v4[4];
                ldsm4t(v4, sV + off);
                mma_f16(o[2*np],   ph[k2], v4);
                mma_f16(o[2*np+1], ph[k2], v4 + 2);
                mma_f16(o[2*np],   pl[k2], v4);
                mma_f16(o[2*np+1], pl[k2], v4 + 2);
            }
        }
    }

    // epilogue: normalize, write fp16 hi/lo
    float i1 = 1.f / lr1, i2 = 1.f / lr2;
    int r1 = lane >> 2, c2 = (lane & 3) * 2;
    size_t row1 = (size_t)b * S_LEN + q0 + wid * 16 + r1;
    size_t row2 = row1 + 8;
    #pragma unroll
    for (int nt = 0; nt < 16; nt++) {
        int col = h * HD + nt * 8 + c2;
        uint32_t lo, hi;
        hi = pack_hl(o[nt][0] * i1, o[nt][1] * i1, lo);
        *(uint32_t*)(Oh + row1 * DIMM + col) = hi;
        *(uint32_t*)(Ol + row1 * DIMM + col) = lo;
        hi = pack_hl(o[nt][2] * i2, o[nt][3] * i2, lo);
        *(uint32_t*)(Oh + row2 * DIMM + col) = hi;
        *(uint32_t*)(Ol + row2 * DIMM + col) = lo;
    }
}

// ---------------------------------------------------------------------------
extern "C" void kernel_launch(void* const* d_in, const int* in_sizes, int n_in,
                              void* d_out, int out_size)
{
    const float* x     = (const float*)d_in[0];   // [2,2048,2048]
    const float* w_qkv = (const float*)d_in[1];   // [2048,6144]
    const float* w_out = (const float*)d_in[2];   // [2048,2048]
    float* out = (float*)d_out;                   // [2,2048,2048]

    __half *xh, *xl, *wqh, *woh, *ah, *al, *qh, *ql, *kh, *vh;
    cudaGetSymbolAddress((void**)&xh, g_xh);
    cudaGetSymbolAddress((void**)&xl, g_xl);
    cudaGetSymbolAddress((void**)&wqh, g_wqT_h);
    cudaGetSymbolAddress((void**)&woh, g_woT_h);
    cudaGetSymbolAddress((void**)&ah, g_ah);
    cudaGetSymbolAddress((void**)&al, g_al);
    cudaGetSymbolAddress((void**)&qh, g_qh);
    cudaGetSymbolAddress((void**)&ql, g_ql);
    cudaGetSymbolAddress((void**)&kh, g_kh);
    cudaGetSymbolAddress((void**)&vh, g_vh);

    cudaFuncSetAttribute(gemm_mma<true>,
                         cudaFuncAttributeMaxDynamicSharedMemorySize, GEMM_SMEM);
    cudaFuncSetAttribute(gemm_mma<false>,
                         cudaFuncAttributeMaxDynamicSharedMemorySize, GEMM_SMEM);
    cudaFuncSetAttribute(attn_mma,
                         cudaFuncAttributeMaxDynamicSharedMemorySize, ATT_SMEM);

    // split x -> fp16 hi/lo
    {
        int n4 = (MROWS * DIMM) / 4;
        split_kernel<<<(n4 + 255) / 256, 256>>>(x, xh, xl, n4);
    }
    // transpose weights -> fp16 hi only
    {
        dim3 tb(32, 8);
        transpose_half<<<dim3(QKV_W / 32, DIMM / 32), tb>>>(w_qkv, wqh, DIMM, QKV_W);
        transpose_half<<<dim3(DIMM / 32, DIMM / 32), tb>>>(w_out, woh, DIMM, DIMM);
    }
    // 1) QKV projection, fused reshape/split epilogue (Q pre-scaled)
    gemm_mma<true><<<dim3(QKV_W / 128, MROWS / 128), 256, GEMM_SMEM>>>(
        xh, xl, wqh, nullptr, qh, ql, kh, vh, MROWS, QKV_W, DIMM);

    // 2) Attention -> writes ah/al
    {
        dim3 grid(S_LEN / 128, NHEADS, BATCH);
        attn_mma<<<grid, 256, ATT_SMEM>>>(qh, ql, kh, vh, ah, al);
    }

    // 3) Output projection -> fp32 out
    gemm_mma<false><<<dim3(DIMM / 128, MROWS / 128), 256, GEMM_SMEM>>>(
        ah, al, woh, out, nullptr, nullptr, nullptr, nullptr,
        MROWS, DIMM, DIMM);
}

// round 9
// speedup vs baseline: 4.5775x; 1.0177x over previous
#include <cuda_runtime.h>
#include <cuda_fp16.h>
#include <math_constants.h>
#include <cstdint>
#include <cstddef>

#define S_LEN  2048
#define DIMM   2048
#define NHEADS 16
#define HD     128
#define QKV_W  6144
#define BATCH  2
#define MROWS  (BATCH * S_LEN)   // 4096
#define SCALE_F 0.08838834764831845f

// ---------------------------------------------------------------------------
// Scratch (__device__ globals: allocation-free rule)
// ---------------------------------------------------------------------------
__device__ __half  g_xh[(size_t)MROWS * DIMM];
__device__ __half  g_xl[(size_t)MROWS * DIMM];
__device__ __half  g_wqT_h[(size_t)QKV_W * DIMM];   // [6144,2048] K-major (B^T), hi only
__device__ __half  g_woT_h[(size_t)DIMM * DIMM];    // [2048,2048] K-major, hi only
__device__ __half  g_ah[(size_t)MROWS * DIMM];      // attention out hi
__device__ __half  g_al[(size_t)MROWS * DIMM];      // attention out lo
// per-(b,h) attention operands [b][h][s][128]
#define HSD ((size_t)BATCH * NHEADS * S_LEN * HD)
__device__ __half  g_qh[HSD];
__device__ __half  g_ql[HSD];
__device__ __half  g_kh[HSD];   // hi only
__device__ __half  g_vh[HSD];   // hi only

// ---------------------------------------------------------------------------
// helpers
// ---------------------------------------------------------------------------
__device__ __forceinline__ uint32_t smem_u32(const void* p) {
    uint32_t a;
    asm("{ .reg .u64 t; cvta.to.shared.u64 t, %1; cvt.u32.u64 %0, t; }"
        : "=r"(a) : "l"(p));
    return a;
}
__device__ __forceinline__ void cp16(uint32_t dst, const void* src) {
    asm volatile("cp.async.cg.shared.global [%0], [%1], 16;"
                 :: "r"(dst), "l"(src) : "memory");
}
__device__ __forceinline__ void cp_commit() {
    asm volatile("cp.async.commit_group;" ::: "memory");
}
__device__ __forceinline__ void cp_wait1() {
    asm volatile("cp.async.wait_group 1;" ::: "memory");
}
__device__ __forceinline__ void cp_wait2() {
    asm volatile("cp.async.wait_group 2;" ::: "memory");
}
__device__ __forceinline__ void mma_f16(float* d, const uint32_t* a,
                                        const uint32_t* b) {
    asm volatile(
        "mma.sync.aligned.m16n8k16.row.col.f32.f16.f16.f32 "
        "{%0,%1,%2,%3}, {%4,%5,%6,%7}, {%8,%9}, {%0,%1,%2,%3};"
        : "+f"(d[0]), "+f"(d[1]), "+f"(d[2]), "+f"(d[3])
        : "r"(a[0]), "r"(a[1]), "r"(a[2]), "r"(a[3]), "r"(b[0]), "r"(b[1]));
}
__device__ __forceinline__ void ldsm4(uint32_t* r, uint32_t addr) {
    asm volatile("ldmatrix.sync.aligned.m8n8.x4.shared.b16 {%0,%1,%2,%3}, [%4];"
                 : "=r"(r[0]), "=r"(r[1]), "=r"(r[2]), "=r"(r[3]) : "r"(addr));
}
__device__ __forceinline__ void ldsm4t(uint32_t* r, uint32_t addr) {
    asm volatile("ldmatrix.sync.aligned.m8n8.x4.trans.shared.b16 {%0,%1,%2,%3}, [%4];"
                 : "=r"(r[0]), "=r"(r[1]), "=r"(r[2]), "=r"(r[3]) : "r"(addr));
}
// pack two floats into fp16x2 hi; residuals into fp16x2 lo
__device__ __forceinline__ uint32_t pack_hl(float x, float y, uint32_t& lo) {
    __half hx = __float2half_rn(x), hy = __float2half_rn(y);
    float rx = x - __half2float(hx), ry = y - __half2float(hy);
    unsigned short lx = __half_as_ushort(__float2half_rn(rx));
    unsigned short ly = __half_as_ushort(__float2half_rn(ry));
    lo = ((uint32_t)ly << 16) | lx;
    return ((uint32_t)__half_as_ushort(hy) << 16) | __half_as_ushort(hx);
}
__device__ __forceinline__ uint32_t pack_h(float x, float y) {
    return ((uint32_t)__half_as_ushort(__float2half_rn(y)) << 16)
         | (uint32_t)__half_as_ushort(__float2half_rn(x));
}

// ---------------------------------------------------------------------------
// Conversion kernels
// ---------------------------------------------------------------------------
__global__ void split_kernel(const float* __restrict__ in,
                             __half* __restrict__ hi,
                             __half* __restrict__ lo, int n4)
{
    int i = blockIdx.x * blockDim.x + threadIdx.x;
    if (i >= n4) return;
    float4 v = ((const float4*)in)[i];
    uint32_t lo0, lo1;
    uint32_t h0 = pack_hl(v.x, v.y, lo0);
    uint32_t h1 = pack_hl(v.z, v.w, lo1);
    ((uint32_t*)hi)[i * 2]     = h0;
    ((uint32_t*)hi)[i * 2 + 1] = h1;
    ((uint32_t*)lo)[i * 2]     = lo0;
    ((uint32_t*)lo)[i * 2 + 1] = lo1;
}

// in [R,C] fp32 -> out [C,R] fp16 (hi only)
__global__ void transpose_half(const float* __restrict__ in,
                               __half* __restrict__ oh, int R, int C)
{
    __shared__ float t[32][33];
    int bx = blockIdx.x * 32, by = blockIdx.y * 32;
    int x = threadIdx.x, y = threadIdx.y;           // 32 x 8
    #pragma unroll
    for (int i = 0; i < 32; i += 8)
        t[y + i][x] = in[(size_t)(by + y + i) * C + bx + x];
    __syncthreads();
    #pragma unroll
    for (int i = 0; i < 32; i += 8) {
        float v = t[x][y + i];
        oh[(size_t)(bx + y + i) * R + by + x] = __float2half_rn(v);
    }
}

// ---------------------------------------------------------------------------
// mma.sync fp16 2-term GEMM: C = A @ B^T,  D ~= Ah*Bh + Al*Bh.
// 128x128 CTA tile, BK=32, 256 thr, 8 warps in 4x2 -> warp tile 32x64
// (minimizes ldmatrix traffic: 8 ldsm per warp per ks vs 10 for 2x4).
// 4-stage cp.async pipeline (96KB -> 2 CTAs/SM), single sync/chunk.
// SPLIT_OUT: writes Q(hi/lo, scaled), K(hi), V(hi).
// ---------------------------------------------------------------------------
#define ROWB 64
#define TILE_B (128 * ROWB)        // 8192
#define STAGE_B (3 * TILE_B)       // 24576: Ah, Al, Bh
#define NSTAGE 4
#define GEMM_SMEM (NSTAGE * STAGE_B)   // 98304

__device__ __forceinline__ uint32_t swoff(int row, int c16) {
    return (uint32_t)(row * ROWB + (((c16 + (row >> 1)) & 3) << 4));
}

template <bool SPLIT_OUT>
__global__ __launch_bounds__(256, 2) void gemm_mma(
    const __half* __restrict__ Ah, const __half* __restrict__ Al,
    const __half* __restrict__ Bh,
    float* __restrict__ C,
    __half* __restrict__ QH, __half* __restrict__ QL,
    __half* __restrict__ KH, __half* __restrict__ VH,
    int M, int N, int K)
{
    extern __shared__ char smem[];
    const uint32_t smem_base = smem_u32(smem);
    const int tid  = threadIdx.x;
    const int wid  = tid >> 5;
    const int lane = tid & 31;
    const int wm   = wid & 3;          // 0..3  (m dir, 32 rows)
    const int wn   = wid >> 2;         // 0..1  (n dir, 64 cols)
    const int bm = blockIdx.y * 128;
    const int bn = blockIdx.x * 128;

    const int lr = tid >> 1;            // load row 0..127
    const int lcb = (tid & 1) * 2;      // chunk base 0 or 2
    const int r0 = lane >> 2;
    const int c0 = (lane & 3) * 2;

    const int a_row_l = lane & 15;
    const int a_cx    = lane >> 4;
    const int b_row_l = (lane & 7) + ((lane >> 4) << 3);
    const int b_cx    = (lane >> 3) & 1;

    float acc[2][8][4];
    #pragma unroll
    for (int mt = 0; mt < 2; mt++)
        #pragma unroll
        for (int nt = 0; nt < 8; nt++)
            #pragma unroll
            for (int j = 0; j < 4; j++) acc[mt][nt][j] = 0.0f;

    const int NC = K / 32;

    auto issue_tile = [&](const __half* src, int row0, int k0,
                          uint32_t dstbase) {
        const char* g = (const char*)(src + (size_t)(row0 + lr) * K + k0);
        cp16(dstbase + swoff(lr, lcb),     g + lcb * 16);
        cp16(dstbase + swoff(lr, lcb + 1), g + lcb * 16 + 16);
    };
    auto issue_stage = [&](int c) {
        uint32_t base = smem_base + (c % NSTAGE) * STAGE_B;
        int k0 = c * 32;
        issue_tile(Ah, bm, k0, base);
        issue_tile(Al, bm, k0, base + TILE_B);
        issue_tile(Bh, bn, k0, base + 2 * TILE_B);
    };

    issue_stage(0); cp_commit();
    issue_stage(1); cp_commit();
    issue_stage(2); cp_commit();

    for (int c = 0; c < NC; c++) {
        cp_wait2();            // stage c complete
        __syncthreads();
        if (c + 3 < NC) issue_stage(c + 3);
        cp_commit();

        const uint32_t sb  = smem_base + (c % NSTAGE) * STAGE_B;
        const uint32_t sAh = sb;
        const uint32_t sAl = sb + TILE_B;
        const uint32_t sBh = sb + 2 * TILE_B;

        #pragma unroll
        for (int kss = 0; kss < 2; kss++) {
            const int ks = kss ^ (wid & 1);    // warp-staggered phases
            uint32_t ah[2][4], bx[8][2];

            // B fragments (64 n-cols per warp)
            #pragma unroll
            for (int np = 0; np < 4; np++) {
                int row = wn * 64 + np * 16 + b_row_l;
                uint32_t th[4];
                ldsm4(th, sBh + swoff(row, ks * 2 + b_cx));
                bx[np * 2][0] = th[0]; bx[np * 2][1] = th[1];
                bx[np * 2 + 1][0] = th[2]; bx[np * 2 + 1][1] = th[3];
            }
            // pass 1: Ah * Bh
            #pragma unroll
            for (int mt = 0; mt < 2; mt++) {
                int row = wm * 32 + mt * 16 + a_row_l;
                ldsm4(ah[mt], sAh + swoff(row, ks * 2 + a_cx));
            }
            #pragma unroll
            for (int mt = 0; mt < 2; mt++)
                #pragma unroll
                for (int nt = 0; nt < 8; nt++)
                    mma_f16(acc[mt][nt], ah[mt], bx[nt]);

            // pass 2: Al * Bh (reuse bx)
            {
                uint32_t al[2][4];
                #pragma unroll
                for (int mt = 0; mt < 2; mt++) {
                    int row = wm * 32 + mt * 16 + a_row_l;
                    ldsm4(al[mt], sAl + swoff(row, ks * 2 + a_cx));
                }
                #pragma unroll
                for (int mt = 0; mt < 2; mt++)
                    #pragma unroll
                    for (int nt = 0; nt < 8; nt++)
                        mma_f16(acc[mt][nt], al[mt], bx[nt]);
            }
        }
    }

    // epilogue
    if (!SPLIT_OUT) {
        #pragma unroll
        for (int mt = 0; mt < 2; mt++) {
            int row = bm + wm * 32 + mt * 16 + r0;
            #pragma unroll
            for (int nt = 0; nt < 8; nt++) {
                int col = bn + wn * 64 + nt * 8 + c0;
                float* p0 = C + (size_t)row * N + col;
                float* p1 = p0 + 8 * (size_t)N;
                *(float2*)p0 = make_float2(acc[mt][nt][0], acc[mt][nt][1]);
                *(float2*)p1 = make_float2(acc[mt][nt][2], acc[mt][nt][3]);
            }
        }
    } else {
        const int sec = bn >> 11;           // 0=Q, 1=K, 2=V
        const int hh  = (bn >> 7) & 15;
        #pragma unroll
        for (int mt = 0; mt < 2; mt++) {
            int row = bm + wm * 32 + mt * 16 + r0;
            #pragma unroll
            for (int nt = 0; nt < 8; nt++) {
                int d = (wn * 64 + nt * 8 + c0) & 127;
                #pragma unroll
                for (int half = 0; half < 2; half++) {
                    int rr = row + half * 8;
                    int bb = rr >> 11, ss = rr & 2047;
                    size_t dst = (((size_t)(bb * NHEADS + hh)) * S_LEN + ss) * HD + d;
                    float v0 = acc[mt][nt][half * 2];
                    float v1 = acc[mt][nt][half * 2 + 1];
                    if (sec == 0) {
                        uint32_t lo, hi;
                        hi = pack_hl(v0 * SCALE_F, v1 * SCALE_F, lo);
                        *(uint32_t*)(QH + dst) = hi;
                        *(uint32_t*)(QL + dst) = lo;
                    } else if (sec == 1) {
                        *(uint32_t*)(KH + dst) = pack_h(v0, v1);
                    } else {
                        *(uint32_t*)(VH + dst) = pack_h(v0, v1);
                    }
                }
            }
        }
    }
}

// ---------------------------------------------------------------------------
// Tensor-core flash attention, fp16 2-term (unchanged from R8).
// ---------------------------------------------------------------------------
#define BKV 32
#define KV_STAGE_B 16384           // Kh 8KB + Vh 8KB
#define ATT_SMEM (65536 + 3 * KV_STAGE_B)   // 114688

__global__ __launch_bounds__(256, 2) void attn_mma(
    const __half* __restrict__ Qh, const __half* __restrict__ Ql,
    const __half* __restrict__ Kh, const __half* __restrict__ Vh,
    __half* __restrict__ Oh, __half* __restrict__ Ol)
{
    extern __shared__ char smem[];
    const uint32_t sb0 = smem_u32(smem);
    const uint32_t sQh = sb0, sQl = sb0 + 32768;
    const int tid = threadIdx.x, wid = tid >> 5, lane = tid & 31;
    const int q0 = blockIdx.x * 128, h = blockIdx.y, b = blockIdx.z;

    const size_t hb = ((size_t)(b * NHEADS + h)) * S_LEN * HD;
    const __half* gqh = Qh + hb + (size_t)q0 * HD;
    const __half* gql = Ql + hb + (size_t)q0 * HD;
    const __half* gkh = Kh + hb;
    const __half* gvh = Vh + hb;

    // Q (128 rows x 256B), hi + lo
    {
        int r = tid >> 1, cb = (tid & 1) * 8;
        const char* g0 = (const char*)(gqh + (size_t)r * HD);
        const char* g1 = (const char*)(gql + (size_t)r * HD);
        uint32_t d0 = sQh + r * 256, d1 = sQl + r * 256;
        #pragma unroll
        for (int j = 0; j < 8; j++) {
            int c = cb + j;
            uint32_t sw = (uint32_t)((c ^ (r & 7)) << 4);
            cp16(d0 + sw, g0 + c * 16);
            cp16(d1 + sw, g1 + c * 16);
        }
    }
    auto ld_stage = [&](int t) {
        uint32_t base = sb0 + 65536 + (t % 3) * KV_STAGE_B;
        int s0 = t * BKV;
        int r = tid >> 3;          // 0..31
        int cb = (tid & 7) * 2;    // 0..14
        const char* gk = (const char*)(gkh + (size_t)(s0 + r) * HD);
        const char* gv = (const char*)(gvh + (size_t)(s0 + r) * HD);
        uint32_t dr = base + r * 256;
        #pragma unroll
        for (int j = 0; j < 2; j++) {
            int c = cb + j;
            uint32_t sw = (uint32_t)((c ^ (r & 7)) << 4);
            cp16(dr + sw,        gk + c * 16);
            cp16(dr + 8192 + sw, gv + c * 16);
        }
    };

    ld_stage(0); cp_commit();      // Q rides in group 0
    ld_stage(1); cp_commit();

    const int aq_row = wid * 16 + (lane & 15);
    const uint32_t aq_base = (uint32_t)(aq_row * 256);
    const int aq_r7 = aq_row & 7;
    const int aq_cx = lane >> 4;
    const int bk_row = (lane & 7) + ((lane >> 4) << 3);
    const int bk_cx = (lane >> 3) & 1;
    const int bv_row = (lane & 7) + (((lane >> 3) & 1) << 3);
    const int bv_cx = lane >> 4;

    float o[16][4];
    #pragma unroll
    for (int nt = 0; nt < 16; nt++) { o[nt][0]=o[nt][1]=o[nt][2]=o[nt][3]=0.f; }
    float mr1 = -CUDART_INF_F, mr2 = -CUDART_INF_F, lr1 = 0.f, lr2 = 0.f;

    const int NT = S_LEN / BKV;    // 64
    for (int t = 0; t < NT; t++) {
        cp_wait1();
        __syncthreads();
        if (t + 2 < NT) ld_stage(t + 2);
        cp_commit();

        uint32_t sK = sb0 + 65536 + (t % 3) * KV_STAGE_B;
        uint32_t sV = sK + 8192;

        // ---- S = Q.K^T (2 terms) ----
        float s[4][4];
        #pragma unroll
        for (int i = 0; i < 4; i++) { s[i][0]=s[i][1]=s[i][2]=s[i][3]=0.f; }

        #pragma unroll
        for (int kt = 0; kt < 8; kt++) {
            uint32_t ah4[4], al4[4];
            {
                int c16 = kt * 2 + aq_cx;
                uint32_t off = aq_base + (uint32_t)(((c16 ^ aq_r7)) << 4);
                ldsm4(ah4, sQh + off);
                ldsm4(al4, sQl + off);
            }
            #pragma unroll
            for (int np = 0; np < 2; np++) {
                int row = np * 16 + bk_row;
                int c16 = kt * 2 + bk_cx;
                uint32_t off = (uint32_t)(row * 256) + (uint32_t)(((c16 ^ (row & 7))) << 4);
                uint32_t bh4[4];
                ldsm4(bh4, sK + off);
                mma_f16(s[2*np],   ah4, bh4);
                mma_f16(s[2*np+1], ah4, bh4 + 2);
                mma_f16(s[2*np],   al4, bh4);
                mma_f16(s[2*np+1], al4, bh4 + 2);
            }
        }

        // ---- online softmax (rows r1 = lane>>2 and r1+8) ----
        float m1 = s[0][0], m2 = s[0][2];
        #pragma unroll
        for (int i = 0; i < 4; i++) {
            m1 = fmaxf(m1, fmaxf(s[i][0], s[i][1]));
            m2 = fmaxf(m2, fmaxf(s[i][2], s[i][3]));
        }
        m1 = fmaxf(m1, __shfl_xor_sync(0xffffffffu, m1, 1));
        m1 = fmaxf(m1, __shfl_xor_sync(0xffffffffu, m1, 2));
        m2 = fmaxf(m2, __shfl_xor_sync(0xffffffffu, m2, 1));
        m2 = fmaxf(m2, __shfl_xor_sync(0xffffffffu, m2, 2));
        float mn1 = fmaxf(mr1, m1), mn2 = fmaxf(mr2, m2);
        float a1 = __expf(mr1 - mn1), a2 = __expf(mr2 - mn2);
        mr1 = mn1; mr2 = mn2;
        float l1 = 0.f, l2 = 0.f;
        #pragma unroll
        for (int i = 0; i < 4; i++) {
            s[i][0] = __expf(s[i][0] - mn1); s[i][1] = __expf(s[i][1] - mn1);
            s[i][2] = __expf(s[i][2] - mn2); s[i][3] = __expf(s[i][3] - mn2);
            l1 += s[i][0] + s[i][1];
            l2 += s[i][2] + s[i][3];
        }
        l1 += __shfl_xor_sync(0xffffffffu, l1, 1);
        l1 += __shfl_xor_sync(0xffffffffu, l1, 2);
        l2 += __shfl_xor_sync(0xffffffffu, l2, 1);
        l2 += __shfl_xor_sync(0xffffffffu, l2, 2);
        lr1 = lr1 * a1 + l1;
        lr2 = lr2 * a2 + l2;
        #pragma unroll
        for (int nt = 0; nt < 16; nt++) {
            o[nt][0] *= a1; o[nt][1] *= a1; o[nt][2] *= a2; o[nt][3] *= a2;
        }

        // ---- pack P -> fp16 hi/lo A-fragments ----
        uint32_t ph[2][4], pl[2][4];
        #pragma unroll
        for (int k2 = 0; k2 < 2; k2++) {
            ph[k2][0] = pack_hl(s[2*k2][0],   s[2*k2][1],   pl[k2][0]);
            ph[k2][1] = pack_hl(s[2*k2][2],   s[2*k2][3],   pl[k2][1]);
            ph[k2][2] = pack_hl(s[2*k2+1][0], s[2*k2+1][1], pl[k2][2]);
            ph[k2][3] = pack_hl(s[2*k2+1][2], s[2*k2+1][3], pl[k2][3]);
        }

        // ---- O += P.V (2 terms), V via ldmatrix.trans ----
        #pragma unroll
        for (int k2 = 0; k2 < 2; k2++) {
            #pragma unroll
            for (int np = 0; np < 8; np++) {
                int row = k2 * 16 + bv_row;
                int c16 = np * 2 + bv_cx;
                uint32_t off = (uint32_t)(row * 256) + (uint32_t)(((c16 ^ (row & 7))) << 4);
                uint32_t v4[4];
                ldsm4t(v4, sV + off);
                mma_f16(o[2*np],   ph[k2], v4);
                mma_f16(o[2*np+1], ph[k2], v4 + 2);
                mma_f16(o[2*np],   pl[k2], v4);
                mma_f16(o[2*np+1], pl[k2], v4 + 2);
            }
        }
    }

    // epilogue: normalize, write fp16 hi/lo
    float i1 = 1.f / lr1, i2 = 1.f / lr2;
    int r1 = lane >> 2, c2 = (lane & 3) * 2;
    size_t row1 = (size_t)b * S_LEN + q0 + wid * 16 + r1;
    size_t row2 = row1 + 8;
    #pragma unroll
    for (int nt = 0; nt < 16; nt++) {
        int col = h * HD + nt * 8 + c2;
        uint32_t lo, hi;
        hi = pack_hl(o[nt][0] * i1, o[nt][1] * i1, lo);
        *(uint32_t*)(Oh + row1 * DIMM + col) = hi;
        *(uint32_t*)(Ol + row1 * DIMM + col) = lo;
        hi = pack_hl(o[nt][2] * i2, o[nt][3] * i2, lo);
        *(uint32_t*)(Oh + row2 * DIMM + col) = hi;
        *(uint32_t*)(Ol + row2 * DIMM + col) = lo;
    }
}

// ---------------------------------------------------------------------------
extern "C" void kernel_launch(void* const* d_in, const int* in_sizes, int n_in,
                              void* d_out, int out_size)
{
    const float* x     = (const float*)d_in[0];   // [2,2048,2048]
    const float* w_qkv = (const float*)d_in[1];   // [2048,6144]
    const float* w_out = (const float*)d_in[2];   // [2048,2048]
    float* out = (float*)d_out;                   // [2,2048,2048]

    __half *xh, *xl, *wqh, *woh, *ah, *al, *qh, *ql, *kh, *vh;
    cudaGetSymbolAddress((void**)&xh, g_xh);
    cudaGetSymbolAddress((void**)&xl, g_xl);
    cudaGetSymbolAddress((void**)&wqh, g_wqT_h);
    cudaGetSymbolAddress((void**)&woh, g_woT_h);
    cudaGetSymbolAddress((void**)&ah, g_ah);
    cudaGetSymbolAddress((void**)&al, g_al);
    cudaGetSymbolAddress((void**)&qh, g_qh);
    cudaGetSymbolAddress((void**)&ql, g_ql);
    cudaGetSymbolAddress((void**)&kh, g_kh);
    cudaGetSymbolAddress((void**)&vh, g_vh);

    cudaFuncSetAttribute(gemm_mma<true>,
                         cudaFuncAttributeMaxDynamicSharedMemorySize, GEMM_SMEM);
    cudaFuncSetAttribute(gemm_mma<false>,
                         cudaFuncAttributeMaxDynamicSharedMemorySize, GEMM_SMEM);
    cudaFuncSetAttribute(attn_mma,
                         cudaFuncAttributeMaxDynamicSharedMemorySize, ATT_SMEM);

    // split x -> fp16 hi/lo
    {
        int n4 = (MROWS * DIMM) / 4;
        split_kernel<<<(n4 + 255) / 256, 256>>>(x, xh, xl, n4);
    }
    // transpose weights -> fp16 hi only
    {
        dim3 tb(32, 8);
        transpose_half<<<dim3(QKV_W / 32, DIMM / 32), tb>>>(w_qkv, wqh, DIMM, QKV_W);
        transpose_half<<<dim3(DIMM / 32, DIMM / 32), tb>>>(w_out, woh, DIMM, DIMM);
    }
    // 1) QKV projection, fused reshape/split epilogue (Q pre-scaled)
    gemm_mma<true><<<dim3(QKV_W / 128, MROWS / 128), 256, GEMM_SMEM>>>(
        xh, xl, wqh, nullptr, qh, ql, kh, vh, MROWS, QKV_W, DIMM);

    // 2) Attention -> writes ah/al
    {
        dim3 grid(S_LEN / 128, NHEADS, BATCH);
        attn_mma<<<grid, 256, ATT_SMEM>>>(qh, ql, kh, vh, ah, al);
    }

    // 3) Output projection -> fp32 out
    gemm_mma<false><<<dim3(DIMM / 128, MROWS / 128), 256, GEMM_SMEM>>>(
        ah, al, woh, out, nullptr, nullptr, nullptr, nullptr,
        MROWS, DIMM, DIMM);
}

// round 10
// speedup vs baseline: 5.1284x; 1.1204x over previous
#include <cuda_runtime.h>
#include <cuda_fp16.h>
#include <math_constants.h>
#include <cstdint>
#include <cstddef>

#define S_LEN  2048
#define DIMM   2048
#define NHEADS 16
#define HD     128
#define QKV_W  6144
#define BATCH  2
#define MROWS  (BATCH * S_LEN)   // 4096
#define SCALE_F 0.08838834764831845f

// ---------------------------------------------------------------------------
// Scratch (__device__ globals: allocation-free rule)
// ---------------------------------------------------------------------------
__device__ __half  g_xh[(size_t)MROWS * DIMM];
__device__ __half  g_xl[(size_t)MROWS * DIMM];
__device__ __half  g_wqT_h[(size_t)QKV_W * DIMM];   // [6144,2048] K-major (B^T), hi only
__device__ __half  g_woT_h[(size_t)DIMM * DIMM];    // [2048,2048] K-major, hi only
__device__ __half  g_ah[(size_t)MROWS * DIMM];      // attention out hi
__device__ __half  g_al[(size_t)MROWS * DIMM];      // attention out lo
// per-(b,h) attention operands [b][h][s][128]
#define HSD ((size_t)BATCH * NHEADS * S_LEN * HD)
__device__ __half  g_qh[HSD];
__device__ __half  g_ql[HSD];
__device__ __half  g_kh[HSD];   // hi only
__device__ __half  g_vh[HSD];   // hi only

// ---------------------------------------------------------------------------
// helpers
// ---------------------------------------------------------------------------
__device__ __forceinline__ uint32_t smem_u32(const void* p) {
    uint32_t a;
    asm("{ .reg .u64 t; cvta.to.shared.u64 t, %1; cvt.u32.u64 %0, t; }"
        : "=r"(a) : "l"(p));
    return a;
}
__device__ __forceinline__ void cp16(uint32_t dst, const void* src) {
    asm volatile("cp.async.cg.shared.global [%0], [%1], 16;"
                 :: "r"(dst), "l"(src) : "memory");
}
__device__ __forceinline__ void cp_commit() {
    asm volatile("cp.async.commit_group;" ::: "memory");
}
__device__ __forceinline__ void cp_wait1() {
    asm volatile("cp.async.wait_group 1;" ::: "memory");
}
__device__ __forceinline__ void cp_wait2() {
    asm volatile("cp.async.wait_group 2;" ::: "memory");
}
__device__ __forceinline__ void mma_f16(float* d, const uint32_t* a,
                                        const uint32_t* b) {
    asm volatile(
        "mma.sync.aligned.m16n8k16.row.col.f32.f16.f16.f32 "
        "{%0,%1,%2,%3}, {%4,%5,%6,%7}, {%8,%9}, {%0,%1,%2,%3};"
        : "+f"(d[0]), "+f"(d[1]), "+f"(d[2]), "+f"(d[3])
        : "r"(a[0]), "r"(a[1]), "r"(a[2]), "r"(a[3]), "r"(b[0]), "r"(b[1]));
}
__device__ __forceinline__ void ldsm4(uint32_t* r, uint32_t addr) {
    asm volatile("ldmatrix.sync.aligned.m8n8.x4.shared.b16 {%0,%1,%2,%3}, [%4];"
                 : "=r"(r[0]), "=r"(r[1]), "=r"(r[2]), "=r"(r[3]) : "r"(addr));
}
__device__ __forceinline__ void ldsm4t(uint32_t* r, uint32_t addr) {
    asm volatile("ldmatrix.sync.aligned.m8n8.x4.trans.shared.b16 {%0,%1,%2,%3}, [%4];"
                 : "=r"(r[0]), "=r"(r[1]), "=r"(r[2]), "=r"(r[3]) : "r"(addr));
}
// pack two floats into fp16x2 hi; residuals into fp16x2 lo
__device__ __forceinline__ uint32_t pack_hl(float x, float y, uint32_t& lo) {
    __half hx = __float2half_rn(x), hy = __float2half_rn(y);
    float rx = x - __half2float(hx), ry = y - __half2float(hy);
    unsigned short lx = __half_as_ushort(__float2half_rn(rx));
    unsigned short ly = __half_as_ushort(__float2half_rn(ry));
    lo = ((uint32_t)ly << 16) | lx;
    return ((uint32_t)__half_as_ushort(hy) << 16) | __half_as_ushort(hx);
}
__device__ __forceinline__ uint32_t pack_h(float x, float y) {
    return ((uint32_t)__half_as_ushort(__float2half_rn(y)) << 16)
         | (uint32_t)__half_as_ushort(__float2half_rn(x));
}

// ---------------------------------------------------------------------------
// Conversion kernels
// ---------------------------------------------------------------------------
__global__ void split_kernel(const float* __restrict__ in,
                             __half* __restrict__ hi,
                             __half* __restrict__ lo, int n4)
{
    int i = blockIdx.x * blockDim.x + threadIdx.x;
    if (i >= n4) return;
    float4 v = ((const float4*)in)[i];
    uint32_t lo0, lo1;
    uint32_t h0 = pack_hl(v.x, v.y, lo0);
    uint32_t h1 = pack_hl(v.z, v.w, lo1);
    ((uint32_t*)hi)[i * 2]     = h0;
    ((uint32_t*)hi)[i * 2 + 1] = h1;
    ((uint32_t*)lo)[i * 2]     = lo0;
    ((uint32_t*)lo)[i * 2 + 1] = lo1;
}

// in [R,C] fp32 -> out [C,R] fp16 (hi only)
__global__ void transpose_half(const float* __restrict__ in,
                               __half* __restrict__ oh, int R, int C)
{
    __shared__ float t[32][33];
    int bx = blockIdx.x * 32, by = blockIdx.y * 32;
    int x = threadIdx.x, y = threadIdx.y;           // 32 x 8
    #pragma unroll
    for (int i = 0; i < 32; i += 8)
        t[y + i][x] = in[(size_t)(by + y + i) * C + bx + x];
    __syncthreads();
    #pragma unroll
    for (int i = 0; i < 32; i += 8) {
        float v = t[x][y + i];
        oh[(size_t)(bx + y + i) * R + by + x] = __float2half_rn(v);
    }
}

// ---------------------------------------------------------------------------
// mma.sync fp16 GEMM: C = A @ B^T.
// TERMS=2: D ~= Ah*Bh + Al*Bh (full hi/lo precision on A).
// TERMS=1: D ~= Ah*Bh (half the MMA work; for outputs quantized to fp16 anyway)
// 128x128 CTA tile, BK=32, 256 thr, 8 warps 4x2 (warp tile 32x64).
// 4-stage cp.async pipeline, single sync/chunk, 2 CTAs/SM.
// SPLIT_OUT epilogue routes cols (nbase+...) to Q(hi/lo,scaled) / K(hi) / V(hi).
// ---------------------------------------------------------------------------
#define ROWB 64
#define TILE_B (128 * ROWB)        // 8192
#define NSTAGE 4

__device__ __forceinline__ uint32_t swoff(int row, int c16) {
    return (uint32_t)(row * ROWB + (((c16 + (row >> 1)) & 3) << 4));
}

template <int TERMS, bool SPLIT_OUT>
__global__ __launch_bounds__(256, 2) void gemm_mma(
    const __half* __restrict__ Ah, const __half* __restrict__ Al,
    const __half* __restrict__ Bh,
    float* __restrict__ C,
    __half* __restrict__ QH, __half* __restrict__ QL,
    __half* __restrict__ KH, __half* __restrict__ VH,
    int nbase, int M, int N, int K)
{
    constexpr int STAGEB = (TERMS + 1) * TILE_B;   // Ah [, Al], Bh
    extern __shared__ char smem[];
    const uint32_t smem_base = smem_u32(smem);
    const int tid  = threadIdx.x;
    const int wid  = tid >> 5;
    const int lane = tid & 31;
    const int wm   = wid & 3;          // 0..3  (m dir, 32 rows)
    const int wn   = wid >> 2;         // 0..1  (n dir, 64 cols)
    const int bm = blockIdx.y * 128;
    const int bn = blockIdx.x * 128;

    const int lr = tid >> 1;            // load row 0..127
    const int lcb = (tid & 1) * 2;      // chunk base 0 or 2
    const int r0 = lane >> 2;
    const int c0 = (lane & 3) * 2;

    const int a_row_l = lane & 15;
    const int a_cx    = lane >> 4;
    const int b_row_l = (lane & 7) + ((lane >> 4) << 3);
    const int b_cx    = (lane >> 3) & 1;

    float acc[2][8][4];
    #pragma unroll
    for (int mt = 0; mt < 2; mt++)
        #pragma unroll
        for (int nt = 0; nt < 8; nt++)
            #pragma unroll
            for (int j = 0; j < 4; j++) acc[mt][nt][j] = 0.0f;

    const int NC = K / 32;

    auto issue_tile = [&](const __half* src, int row0, int k0,
                          uint32_t dstbase) {
        const char* g = (const char*)(src + (size_t)(row0 + lr) * K + k0);
        cp16(dstbase + swoff(lr, lcb),     g + lcb * 16);
        cp16(dstbase + swoff(lr, lcb + 1), g + lcb * 16 + 16);
    };
    auto issue_stage = [&](int c) {
        uint32_t base = smem_base + (c % NSTAGE) * STAGEB;
        int k0 = c * 32;
        issue_tile(Ah, bm, k0, base);
        if constexpr (TERMS == 2) issue_tile(Al, bm, k0, base + TILE_B);
        issue_tile(Bh, bn, k0, base + (TERMS == 2 ? 2 : 1) * TILE_B);
    };

    issue_stage(0); cp_commit();
    issue_stage(1); cp_commit();
    issue_stage(2); cp_commit();

    for (int c = 0; c < NC; c++) {
        cp_wait2();            // stage c complete
        __syncthreads();
        if (c + 3 < NC) issue_stage(c + 3);
        cp_commit();

        const uint32_t sb  = smem_base + (c % NSTAGE) * STAGEB;
        const uint32_t sAh = sb;
        const uint32_t sAl = sb + TILE_B;
        const uint32_t sBh = sb + (TERMS == 2 ? 2 : 1) * TILE_B;

        #pragma unroll
        for (int kss = 0; kss < 2; kss++) {
            const int ks = kss ^ (wid & 1);    // warp-staggered phases
            uint32_t ah[2][4], bx[8][2];

            // B fragments (64 n-cols per warp)
            #pragma unroll
            for (int np = 0; np < 4; np++) {
                int row = wn * 64 + np * 16 + b_row_l;
                uint32_t th[4];
                ldsm4(th, sBh + swoff(row, ks * 2 + b_cx));
                bx[np * 2][0] = th[0]; bx[np * 2][1] = th[1];
                bx[np * 2 + 1][0] = th[2]; bx[np * 2 + 1][1] = th[3];
            }
            // pass 1: Ah * Bh
            #pragma unroll
            for (int mt = 0; mt < 2; mt++) {
                int row = wm * 32 + mt * 16 + a_row_l;
                ldsm4(ah[mt], sAh + swoff(row, ks * 2 + a_cx));
            }
            #pragma unroll
            for (int mt = 0; mt < 2; mt++)
                #pragma unroll
                for (int nt = 0; nt < 8; nt++)
                    mma_f16(acc[mt][nt], ah[mt], bx[nt]);

            // pass 2: Al * Bh (reuse bx)
            if constexpr (TERMS == 2) {
                uint32_t al[2][4];
                #pragma unroll
                for (int mt = 0; mt < 2; mt++) {
                    int row = wm * 32 + mt * 16 + a_row_l;
                    ldsm4(al[mt], sAl + swoff(row, ks * 2 + a_cx));
                }
                #pragma unroll
                for (int mt = 0; mt < 2; mt++)
                    #pragma unroll
                    for (int nt = 0; nt < 8; nt++)
                        mma_f16(acc[mt][nt], al[mt], bx[nt]);
            }
        }
    }

    // epilogue
    if (!SPLIT_OUT) {
        #pragma unroll
        for (int mt = 0; mt < 2; mt++) {
            int row = bm + wm * 32 + mt * 16 + r0;
            #pragma unroll
            for (int nt = 0; nt < 8; nt++) {
                int col = bn + wn * 64 + nt * 8 + c0;
                float* p0 = C + (size_t)row * N + col;
                float* p1 = p0 + 8 * (size_t)N;
                *(float2*)p0 = make_float2(acc[mt][nt][0], acc[mt][nt][1]);
                *(float2*)p1 = make_float2(acc[mt][nt][2], acc[mt][nt][3]);
            }
        }
    } else {
        const int gcol = nbase + bn;        // global qkv column of tile start
        const int sec = gcol >> 11;         // 0=Q, 1=K, 2=V
        const int hh  = (gcol >> 7) & 15;
        #pragma unroll
        for (int mt = 0; mt < 2; mt++) {
            int row = bm + wm * 32 + mt * 16 + r0;
            #pragma unroll
            for (int nt = 0; nt < 8; nt++) {
                int d = (wn * 64 + nt * 8 + c0) & 127;
                #pragma unroll
                for (int half = 0; half < 2; half++) {
                    int rr = row + half * 8;
                    int bb = rr >> 11, ss = rr & 2047;
                    size_t dst = (((size_t)(bb * NHEADS + hh)) * S_LEN + ss) * HD + d;
                    float v0 = acc[mt][nt][half * 2];
                    float v1 = acc[mt][nt][half * 2 + 1];
                    if (sec == 0) {
                        uint32_t lo, hi;
                        hi = pack_hl(v0 * SCALE_F, v1 * SCALE_F, lo);
                        *(uint32_t*)(QH + dst) = hi;
                        *(uint32_t*)(QL + dst) = lo;
                    } else if (sec == 1) {
                        *(uint32_t*)(KH + dst) = pack_h(v0, v1);
                    } else {
                        *(uint32_t*)(VH + dst) = pack_h(v0, v1);
                    }
                }
            }
        }
    }
}

// ---------------------------------------------------------------------------
// Tensor-core flash attention, fp16 2-term (unchanged from R8/R9).
// ---------------------------------------------------------------------------
#define BKV 32
#define KV_STAGE_B 16384           // Kh 8KB + Vh 8KB
#define ATT_SMEM (65536 + 3 * KV_STAGE_B)   // 114688

__global__ __launch_bounds__(256, 2) void attn_mma(
    const __half* __restrict__ Qh, const __half* __restrict__ Ql,
    const __half* __restrict__ Kh, const __half* __restrict__ Vh,
    __half* __restrict__ Oh, __half* __restrict__ Ol)
{
    extern __shared__ char smem[];
    const uint32_t sb0 = smem_u32(smem);
    const uint32_t sQh = sb0, sQl = sb0 + 32768;
    const int tid = threadIdx.x, wid = tid >> 5, lane = tid & 31;
    const int q0 = blockIdx.x * 128, h = blockIdx.y, b = blockIdx.z;

    const size_t hb = ((size_t)(b * NHEADS + h)) * S_LEN * HD;
    const __half* gqh = Qh + hb + (size_t)q0 * HD;
    const __half* gql = Ql + hb + (size_t)q0 * HD;
    const __half* gkh = Kh + hb;
    const __half* gvh = Vh + hb;

    // Q (128 rows x 256B), hi + lo
    {
        int r = tid >> 1, cb = (tid & 1) * 8;
        const char* g0 = (const char*)(gqh + (size_t)r * HD);
        const char* g1 = (const char*)(gql + (size_t)r * HD);
        uint32_t d0 = sQh + r * 256, d1 = sQl + r * 256;
        #pragma unroll
        for (int j = 0; j < 8; j++) {
            int c = cb + j;
            uint32_t sw = (uint32_t)((c ^ (r & 7)) << 4);
            cp16(d0 + sw, g0 + c * 16);
            cp16(d1 + sw, g1 + c * 16);
        }
    }
    auto ld_stage = [&](int t) {
        uint32_t base = sb0 + 65536 + (t % 3) * KV_STAGE_B;
        int s0 = t * BKV;
        int r = tid >> 3;          // 0..31
        int cb = (tid & 7) * 2;    // 0..14
        const char* gk = (const char*)(gkh + (size_t)(s0 + r) * HD);
        const char* gv = (const char*)(gvh + (size_t)(s0 + r) * HD);
        uint32_t dr = base + r * 256;
        #pragma unroll
        for (int j = 0; j < 2; j++) {
            int c = cb + j;
            uint32_t sw = (uint32_t)((c ^ (r & 7)) << 4);
            cp16(dr + sw,        gk + c * 16);
            cp16(dr + 8192 + sw, gv + c * 16);
        }
    };

    ld_stage(0); cp_commit();      // Q rides in group 0
    ld_stage(1); cp_commit();

    const int aq_row = wid * 16 + (lane & 15);
    const uint32_t aq_base = (uint32_t)(aq_row * 256);
    const int aq_r7 = aq_row & 7;
    const int aq_cx = lane >> 4;
    const int bk_row = (lane & 7) + ((lane >> 4) << 3);
    const int bk_cx = (lane >> 3) & 1;
    const int bv_row = (lane & 7) + (((lane >> 3) & 1) << 3);
    const int bv_cx = lane >> 4;

    float o[16][4];
    #pragma unroll
    for (int nt = 0; nt < 16; nt++) { o[nt][0]=o[nt][1]=o[nt][2]=o[nt][3]=0.f; }
    float mr1 = -CUDART_INF_F, mr2 = -CUDART_INF_F, lr1 = 0.f, lr2 = 0.f;

    const int NT = S_LEN / BKV;    // 64
    for (int t = 0; t < NT; t++) {
        cp_wait1();
        __syncthreads();
        if (t + 2 < NT) ld_stage(t + 2);
        cp_commit();

        uint32_t sK = sb0 + 65536 + (t % 3) * KV_STAGE_B;
        uint32_t sV = sK + 8192;

        // ---- S = Q.K^T (2 terms) ----
        float s[4][4];
        #pragma unroll
        for (int i = 0; i < 4; i++) { s[i][0]=s[i][1]=s[i][2]=s[i][3]=0.f; }

        #pragma unroll
        for (int kt = 0; kt < 8; kt++) {
            uint32_t ah4[4], al4[4];
            {
                int c16 = kt * 2 + aq_cx;
                uint32_t off = aq_base + (uint32_t)(((c16 ^ aq_r7)) << 4);
                ldsm4(ah4, sQh + off);
                ldsm4(al4, sQl + off);
            }
            #pragma unroll
            for (int np = 0; np < 2; np++) {
                int row = np * 16 + bk_row;
                int c16 = kt * 2 + bk_cx;
                uint32_t off = (uint32_t)(row * 256) + (uint32_t)(((c16 ^ (row & 7))) << 4);
                uint32_t bh4[4];
                ldsm4(bh4, sK + off);
                mma_f16(s[2*np],   ah4, bh4);
                mma_f16(s[2*np+1], ah4, bh4 + 2);
                mma_f16(s[2*np],   al4, bh4);
                mma_f16(s[2*np+1], al4, bh4 + 2);
            }
        }

        // ---- online softmax (rows r1 = lane>>2 and r1+8) ----
        float m1 = s[0][0], m2 = s[0][2];
        #pragma unroll
        for (int i = 0; i < 4; i++) {
            m1 = fmaxf(m1, fmaxf(s[i][0], s[i][1]));
            m2 = fmaxf(m2, fmaxf(s[i][2], s[i][3]));
        }
        m1 = fmaxf(m1, __shfl_xor_sync(0xffffffffu, m1, 1));
        m1 = fmaxf(m1, __shfl_xor_sync(0xffffffffu, m1, 2));
        m2 = fmaxf(m2, __shfl_xor_sync(0xffffffffu, m2, 1));
        m2 = fmaxf(m2, __shfl_xor_sync(0xffffffffu, m2, 2));
        float mn1 = fmaxf(mr1, m1), mn2 = fmaxf(mr2, m2);
        float a1 = __expf(mr1 - mn1), a2 = __expf(mr2 - mn2);
        mr1 = mn1; mr2 = mn2;
        float l1 = 0.f, l2 = 0.f;
        #pragma unroll
        for (int i = 0; i < 4; i++) {
            s[i][0] = __expf(s[i][0] - mn1); s[i][1] = __expf(s[i][1] - mn1);
            s[i][2] = __expf(s[i][2] - mn2); s[i][3] = __expf(s[i][3] - mn2);
            l1 += s[i][0] + s[i][1];
            l2 += s[i][2] + s[i][3];
        }
        l1 += __shfl_xor_sync(0xffffffffu, l1, 1);
        l1 += __shfl_xor_sync(0xffffffffu, l1, 2);
        l2 += __shfl_xor_sync(0xffffffffu, l2, 1);
        l2 += __shfl_xor_sync(0xffffffffu, l2, 2);
        lr1 = lr1 * a1 + l1;
        lr2 = lr2 * a2 + l2;
        #pragma unroll
        for (int nt = 0; nt < 16; nt++) {
            o[nt][0] *= a1; o[nt][1] *= a1; o[nt][2] *= a2; o[nt][3] *= a2;
        }

        // ---- pack P -> fp16 hi/lo A-fragments ----
        uint32_t ph[2][4], pl[2][4];
        #pragma unroll
        for (int k2 = 0; k2 < 2; k2++) {
            ph[k2][0] = pack_hl(s[2*k2][0],   s[2*k2][1],   pl[k2][0]);
            ph[k2][1] = pack_hl(s[2*k2][2],   s[2*k2][3],   pl[k2][1]);
            ph[k2][2] = pack_hl(s[2*k2+1][0], s[2*k2+1][1], pl[k2][2]);
            ph[k2][3] = pack_hl(s[2*k2+1][2], s[2*k2+1][3], pl[k2][3]);
        }

        // ---- O += P.V (2 terms), V via ldmatrix.trans ----
        #pragma unroll
        for (int k2 = 0; k2 < 2; k2++) {
            #pragma unroll
            for (int np = 0; np < 8; np++) {
                int row = k2 * 16 + bv_row;
                int c16 = np * 2 + bv_cx;
                uint32_t off = (uint32_t)(row * 256) + (uint32_t)(((c16 ^ (row & 7))) << 4);
                uint32_t v4[4];
                ldsm4t(v4, sV + off);
                mma_f16(o[2*np],   ph[k2], v4);
                mma_f16(o[2*np+1], ph[k2], v4 + 2);
                mma_f16(o[2*np],   pl[k2], v4);
                mma_f16(o[2*np+1], pl[k2], v4 + 2);
            }
        }
    }

    // epilogue: normalize, write fp16 hi/lo
    float i1 = 1.f / lr1, i2 = 1.f / lr2;
    int r1 = lane >> 2, c2 = (lane & 3) * 2;
    size_t row1 = (size_t)b * S_LEN + q0 + wid * 16 + r1;
    size_t row2 = row1 + 8;
    #pragma unroll
    for (int nt = 0; nt < 16; nt++) {
        int col = h * HD + nt * 8 + c2;
        uint32_t lo, hi;
        hi = pack_hl(o[nt][0] * i1, o[nt][1] * i1, lo);
        *(uint32_t*)(Oh + row1 * DIMM + col) = hi;
        *(uint32_t*)(Ol + row1 * DIMM + col) = lo;
        hi = pack_hl(o[nt][2] * i2, o[nt][3] * i2, lo);
        *(uint32_t*)(Oh + row2 * DIMM + col) = hi;
        *(uint32_t*)(Ol + row2 * DIMM + col) = lo;
    }
}

// ---------------------------------------------------------------------------
extern "C" void kernel_launch(void* const* d_in, const int* in_sizes, int n_in,
                              void* d_out, int out_size)
{
    const float* x     = (const float*)d_in[0];   // [2,2048,2048]
    const float* w_qkv = (const float*)d_in[1];   // [2048,6144]
    const float* w_out = (const float*)d_in[2];   // [2048,2048]
    float* out = (float*)d_out;                   // [2,2048,2048]

    __half *xh, *xl, *wqh, *woh, *ah, *al, *qh, *ql, *kh, *vh;
    cudaGetSymbolAddress((void**)&xh, g_xh);
    cudaGetSymbolAddress((void**)&xl, g_xl);
    cudaGetSymbolAddress((void**)&wqh, g_wqT_h);
    cudaGetSymbolAddress((void**)&woh, g_woT_h);
    cudaGetSymbolAddress((void**)&ah, g_ah);
    cudaGetSymbolAddress((void**)&al, g_al);
    cudaGetSymbolAddress((void**)&qh, g_qh);
    cudaGetSymbolAddress((void**)&ql, g_ql);
    cudaGetSymbolAddress((void**)&kh, g_kh);
    cudaGetSymbolAddress((void**)&vh, g_vh);

    const int SMEM2 = NSTAGE * 3 * TILE_B;   // 98304 (2-term)
    const int SMEM1 = NSTAGE * 2 * TILE_B;   // 65536 (1-term)
    cudaFuncSetAttribute(gemm_mma<2, true>,
                         cudaFuncAttributeMaxDynamicSharedMemorySize, SMEM2);
    cudaFuncSetAttribute(gemm_mma<1, true>,
                         cudaFuncAttributeMaxDynamicSharedMemorySize, SMEM1);
    cudaFuncSetAttribute(gemm_mma<2, false>,
                         cudaFuncAttributeMaxDynamicSharedMemorySize, SMEM2);
    cudaFuncSetAttribute(attn_mma,
                         cudaFuncAttributeMaxDynamicSharedMemorySize, ATT_SMEM);

    // split x -> fp16 hi/lo
    {
        int n4 = (MROWS * DIMM) / 4;
        split_kernel<<<(n4 + 255) / 256, 256>>>(x, xh, xl, n4);
    }
    // transpose weights -> fp16 hi only
    {
        dim3 tb(32, 8);
        transpose_half<<<dim3(QKV_W / 32, DIMM / 32), tb>>>(w_qkv, wqh, DIMM, QKV_W);
        transpose_half<<<dim3(DIMM / 32, DIMM / 32), tb>>>(w_out, woh, DIMM, DIMM);
    }
    // 1a) Q projection (2-term, full precision into hi/lo, scaled)
    gemm_mma<2, true><<<dim3(2048 / 128, MROWS / 128), 256, SMEM2>>>(
        xh, xl, wqh, nullptr, qh, ql, nullptr, nullptr,
        0, MROWS, 2048, DIMM);
    // 1b) K/V projection (1-term — outputs are fp16-quantized anyway)
    gemm_mma<1, true><<<dim3(4096 / 128, MROWS / 128), 256, SMEM1>>>(
        xh, nullptr, wqh + (size_t)2048 * DIMM, nullptr,
        nullptr, nullptr, kh, vh,
        2048, MROWS, 4096, DIMM);

    // 2) Attention -> writes ah/al
    {
        dim3 grid(S_LEN / 128, NHEADS, BATCH);
        attn_mma<<<grid, 256, ATT_SMEM>>>(qh, ql, kh, vh, ah, al);
    }

    // 3) Output projection -> fp32 out (2-term)
    gemm_mma<2, false><<<dim3(DIMM / 128, MROWS / 128), 256, SMEM2>>>(
        ah, al, woh, out, nullptr, nullptr, nullptr, nullptr,
        0, MROWS, DIMM, DIMM);
}

// round 11
// speedup vs baseline: 6.1699x; 1.2031x over previous
#include <cuda_runtime.h>
#include <cuda_fp16.h>
#include <math_constants.h>
#include <cstdint>
#include <cstddef>

#define S_LEN  2048
#define DIMM   2048
#define NHEADS 16
#define HD     128
#define QKV_W  6144
#define BATCH  2
#define MROWS  (BATCH * S_LEN)   // 4096
#define SCALE_F 0.08838834764831845f

// ---------------------------------------------------------------------------
// Scratch (__device__ globals: allocation-free rule)
// ---------------------------------------------------------------------------
__device__ __half  g_xh[(size_t)MROWS * DIMM];
__device__ __half  g_xl[(size_t)MROWS * DIMM];
__device__ __half  g_wqT_h[(size_t)QKV_W * DIMM];   // [6144,2048] K-major (B^T), hi only
__device__ __half  g_woT_h[(size_t)DIMM * DIMM];    // [2048,2048] K-major, hi only
__device__ __half  g_ah[(size_t)MROWS * DIMM];      // attention out (fp16)
// per-(b,h) attention operands [b][h][s][128]
#define HSD ((size_t)BATCH * NHEADS * S_LEN * HD)
__device__ __half  g_qh[HSD];
__device__ __half  g_ql[HSD];
__device__ __half  g_kh[HSD];   // hi only
__device__ __half  g_vh[HSD];   // hi only

// ---------------------------------------------------------------------------
// helpers
// ---------------------------------------------------------------------------
__device__ __forceinline__ uint32_t smem_u32(const void* p) {
    uint32_t a;
    asm("{ .reg .u64 t; cvta.to.shared.u64 t, %1; cvt.u32.u64 %0, t; }"
        : "=r"(a) : "l"(p));
    return a;
}
__device__ __forceinline__ void cp16(uint32_t dst, const void* src) {
    asm volatile("cp.async.cg.shared.global [%0], [%1], 16;"
                 :: "r"(dst), "l"(src) : "memory");
}
__device__ __forceinline__ void cp_commit() {
    asm volatile("cp.async.commit_group;" ::: "memory");
}
__device__ __forceinline__ void cp_wait1() {
    asm volatile("cp.async.wait_group 1;" ::: "memory");
}
__device__ __forceinline__ void cp_wait2() {
    asm volatile("cp.async.wait_group 2;" ::: "memory");
}
__device__ __forceinline__ void mma_f16(float* d, const uint32_t* a,
                                        const uint32_t* b) {
    asm volatile(
        "mma.sync.aligned.m16n8k16.row.col.f32.f16.f16.f32 "
        "{%0,%1,%2,%3}, {%4,%5,%6,%7}, {%8,%9}, {%0,%1,%2,%3};"
        : "+f"(d[0]), "+f"(d[1]), "+f"(d[2]), "+f"(d[3])
        : "r"(a[0]), "r"(a[1]), "r"(a[2]), "r"(a[3]), "r"(b[0]), "r"(b[1]));
}
__device__ __forceinline__ void ldsm4(uint32_t* r, uint32_t addr) {
    asm volatile("ldmatrix.sync.aligned.m8n8.x4.shared.b16 {%0,%1,%2,%3}, [%4];"
                 : "=r"(r[0]), "=r"(r[1]), "=r"(r[2]), "=r"(r[3]) : "r"(addr));
}
__device__ __forceinline__ void ldsm4t(uint32_t* r, uint32_t addr) {
    asm volatile("ldmatrix.sync.aligned.m8n8.x4.trans.shared.b16 {%0,%1,%2,%3}, [%4];"
                 : "=r"(r[0]), "=r"(r[1]), "=r"(r[2]), "=r"(r[3]) : "r"(addr));
}
// pack two floats into fp16x2 hi; residuals into fp16x2 lo
__device__ __forceinline__ uint32_t pack_hl(float x, float y, uint32_t& lo) {
    __half hx = __float2half_rn(x), hy = __float2half_rn(y);
    float rx = x - __half2float(hx), ry = y - __half2float(hy);
    unsigned short lx = __half_as_ushort(__float2half_rn(rx));
    unsigned short ly = __half_as_ushort(__float2half_rn(ry));
    lo = ((uint32_t)ly << 16) | lx;
    return ((uint32_t)__half_as_ushort(hy) << 16) | __half_as_ushort(hx);
}
__device__ __forceinline__ uint32_t pack_h(float x, float y) {
    return ((uint32_t)__half_as_ushort(__float2half_rn(y)) << 16)
         | (uint32_t)__half_as_ushort(__float2half_rn(x));
}

// ---------------------------------------------------------------------------
// Conversion kernels
// ---------------------------------------------------------------------------
__global__ void split_kernel(const float* __restrict__ in,
                             __half* __restrict__ hi,
                             __half* __restrict__ lo, int n4)
{
    int i = blockIdx.x * blockDim.x + threadIdx.x;
    if (i >= n4) return;
    float4 v = ((const float4*)in)[i];
    uint32_t lo0, lo1;
    uint32_t h0 = pack_hl(v.x, v.y, lo0);
    uint32_t h1 = pack_hl(v.z, v.w, lo1);
    ((uint32_t*)hi)[i * 2]     = h0;
    ((uint32_t*)hi)[i * 2 + 1] = h1;
    ((uint32_t*)lo)[i * 2]     = lo0;
    ((uint32_t*)lo)[i * 2 + 1] = lo1;
}

// in [R,C] fp32 -> out [C,R] fp16 (hi only)
__global__ void transpose_half(const float* __restrict__ in,
                               __half* __restrict__ oh, int R, int C)
{
    __shared__ float t[32][33];
    int bx = blockIdx.x * 32, by = blockIdx.y * 32;
    int x = threadIdx.x, y = threadIdx.y;           // 32 x 8
    #pragma unroll
    for (int i = 0; i < 32; i += 8)
        t[y + i][x] = in[(size_t)(by + y + i) * C + bx + x];
    __syncthreads();
    #pragma unroll
    for (int i = 0; i < 32; i += 8) {
        float v = t[x][y + i];
        oh[(size_t)(bx + y + i) * R + by + x] = __float2half_rn(v);
    }
}

// ---------------------------------------------------------------------------
// mma.sync fp16 GEMM: C = A @ B^T.
// TERMS=2: D ~= Ah*Bh + Al*Bh.   TERMS=1: D ~= Ah*Bh.
// 128x128 CTA tile, BK=32, 256 thr, 8 warps 4x2 (warp tile 32x64).
// 4-stage cp.async pipeline, single sync/chunk, 2 CTAs/SM.
// SPLIT_OUT epilogue routes cols (nbase+...) to Q(hi/lo,scaled) / K(hi) / V(hi).
// ---------------------------------------------------------------------------
#define ROWB 64
#define TILE_B (128 * ROWB)        // 8192
#define NSTAGE 4

__device__ __forceinline__ uint32_t swoff(int row, int c16) {
    return (uint32_t)(row * ROWB + (((c16 + (row >> 1)) & 3) << 4));
}

template <int TERMS, bool SPLIT_OUT>
__global__ __launch_bounds__(256, 2) void gemm_mma(
    const __half* __restrict__ Ah, const __half* __restrict__ Al,
    const __half* __restrict__ Bh,
    float* __restrict__ C,
    __half* __restrict__ QH, __half* __restrict__ QL,
    __half* __restrict__ KH, __half* __restrict__ VH,
    int nbase, int M, int N, int K)
{
    constexpr int STAGEB = (TERMS + 1) * TILE_B;   // Ah [, Al], Bh
    extern __shared__ char smem[];
    const uint32_t smem_base = smem_u32(smem);
    const int tid  = threadIdx.x;
    const int wid  = tid >> 5;
    const int lane = tid & 31;
    const int wm   = wid & 3;          // 0..3  (m dir, 32 rows)
    const int wn   = wid >> 2;         // 0..1  (n dir, 64 cols)
    const int bm = blockIdx.y * 128;
    const int bn = blockIdx.x * 128;

    const int lr = tid >> 1;            // load row 0..127
    const int lcb = (tid & 1) * 2;      // chunk base 0 or 2
    const int r0 = lane >> 2;
    const int c0 = (lane & 3) * 2;

    const int a_row_l = lane & 15;
    const int a_cx    = lane >> 4;
    const int b_row_l = (lane & 7) + ((lane >> 4) << 3);
    const int b_cx    = (lane >> 3) & 1;

    float acc[2][8][4];
    #pragma unroll
    for (int mt = 0; mt < 2; mt++)
        #pragma unroll
        for (int nt = 0; nt < 8; nt++)
            #pragma unroll
            for (int j = 0; j < 4; j++) acc[mt][nt][j] = 0.0f;

    const int NC = K / 32;

    auto issue_tile = [&](const __half* src, int row0, int k0,
                          uint32_t dstbase) {
        const char* g = (const char*)(src + (size_t)(row0 + lr) * K + k0);
        cp16(dstbase + swoff(lr, lcb),     g + lcb * 16);
        cp16(dstbase + swoff(lr, lcb + 1), g + lcb * 16 + 16);
    };
    auto issue_stage = [&](int c) {
        uint32_t base = smem_base + (c % NSTAGE) * STAGEB;
        int k0 = c * 32;
        issue_tile(Ah, bm, k0, base);
        if constexpr (TERMS == 2) issue_tile(Al, bm, k0, base + TILE_B);
        issue_tile(Bh, bn, k0, base + (TERMS == 2 ? 2 : 1) * TILE_B);
    };

    issue_stage(0); cp_commit();
    issue_stage(1); cp_commit();
    issue_stage(2); cp_commit();

    for (int c = 0; c < NC; c++) {
        cp_wait2();            // stage c complete
        __syncthreads();
        if (c + 3 < NC) issue_stage(c + 3);
        cp_commit();

        const uint32_t sb  = smem_base + (c % NSTAGE) * STAGEB;
        const uint32_t sAh = sb;
        const uint32_t sAl = sb + TILE_B;
        const uint32_t sBh = sb + (TERMS == 2 ? 2 : 1) * TILE_B;

        #pragma unroll
        for (int kss = 0; kss < 2; kss++) {
            const int ks = kss ^ (wid & 1);    // warp-staggered phases
            uint32_t ah[2][4], bx[8][2];

            // B fragments (64 n-cols per warp)
            #pragma unroll
            for (int np = 0; np < 4; np++) {
                int row = wn * 64 + np * 16 + b_row_l;
                uint32_t th[4];
                ldsm4(th, sBh + swoff(row, ks * 2 + b_cx));
                bx[np * 2][0] = th[0]; bx[np * 2][1] = th[1];
                bx[np * 2 + 1][0] = th[2]; bx[np * 2 + 1][1] = th[3];
            }
            // pass 1: Ah * Bh
            #pragma unroll
            for (int mt = 0; mt < 2; mt++) {
                int row = wm * 32 + mt * 16 + a_row_l;
                ldsm4(ah[mt], sAh + swoff(row, ks * 2 + a_cx));
            }
            #pragma unroll
            for (int mt = 0; mt < 2; mt++)
                #pragma unroll
                for (int nt = 0; nt < 8; nt++)
                    mma_f16(acc[mt][nt], ah[mt], bx[nt]);

            // pass 2: Al * Bh (reuse bx)
            if constexpr (TERMS == 2) {
                uint32_t al[2][4];
                #pragma unroll
                for (int mt = 0; mt < 2; mt++) {
                    int row = wm * 32 + mt * 16 + a_row_l;
                    ldsm4(al[mt], sAl + swoff(row, ks * 2 + a_cx));
                }
                #pragma unroll
                for (int mt = 0; mt < 2; mt++)
                    #pragma unroll
                    for (int nt = 0; nt < 8; nt++)
                        mma_f16(acc[mt][nt], al[mt], bx[nt]);
            }
        }
    }

    // epilogue
    if (!SPLIT_OUT) {
        #pragma unroll
        for (int mt = 0; mt < 2; mt++) {
            int row = bm + wm * 32 + mt * 16 + r0;
            #pragma unroll
            for (int nt = 0; nt < 8; nt++) {
                int col = bn + wn * 64 + nt * 8 + c0;
                float* p0 = C + (size_t)row * N + col;
                float* p1 = p0 + 8 * (size_t)N;
                *(float2*)p0 = make_float2(acc[mt][nt][0], acc[mt][nt][1]);
                *(float2*)p1 = make_float2(acc[mt][nt][2], acc[mt][nt][3]);
            }
        }
    } else {
        const int gcol = nbase + bn;        // global qkv column of tile start
        const int sec = gcol >> 11;         // 0=Q, 1=K, 2=V
        const int hh  = (gcol >> 7) & 15;
        #pragma unroll
        for (int mt = 0; mt < 2; mt++) {
            int row = bm + wm * 32 + mt * 16 + r0;
            #pragma unroll
            for (int nt = 0; nt < 8; nt++) {
                int d = (wn * 64 + nt * 8 + c0) & 127;
                #pragma unroll
                for (int half = 0; half < 2; half++) {
                    int rr = row + half * 8;
                    int bb = rr >> 11, ss = rr & 2047;
                    size_t dst = (((size_t)(bb * NHEADS + hh)) * S_LEN + ss) * HD + d;
                    float v0 = acc[mt][nt][half * 2];
                    float v1 = acc[mt][nt][half * 2 + 1];
                    if (sec == 0) {
                        uint32_t lo, hi;
                        hi = pack_hl(v0 * SCALE_F, v1 * SCALE_F, lo);
                        *(uint32_t*)(QH + dst) = hi;
                        *(uint32_t*)(QL + dst) = lo;
                    } else if (sec == 1) {
                        *(uint32_t*)(KH + dst) = pack_h(v0, v1);
                    } else {
                        *(uint32_t*)(VH + dst) = pack_h(v0, v1);
                    }
                }
            }
        }
    }
}

// ---------------------------------------------------------------------------
// Tensor-core flash attention, fp16. QK is 2-term (Qh+Ql vs Kh); PV is 1-term
// (Ph*Vh — output is fp16-quantized for the 1-term out-proj anyway).
// 1 CTA per (b,h,128 queries), 8 warps x 16 query rows, BKV=32, 3-stage K/V.
// smem 112KB -> 2 CTAs/SM. Writes fp16 O (hi only).
// ---------------------------------------------------------------------------
#define BKV 32
#define KV_STAGE_B 16384           // Kh 8KB + Vh 8KB
#define ATT_SMEM (65536 + 3 * KV_STAGE_B)   // 114688

__global__ __launch_bounds__(256, 2) void attn_mma(
    const __half* __restrict__ Qh, const __half* __restrict__ Ql,
    const __half* __restrict__ Kh, const __half* __restrict__ Vh,
    __half* __restrict__ Oh)
{
    extern __shared__ char smem[];
    const uint32_t sb0 = smem_u32(smem);
    const uint32_t sQh = sb0, sQl = sb0 + 32768;
    const int tid = threadIdx.x, wid = tid >> 5, lane = tid & 31;
    const int q0 = blockIdx.x * 128, h = blockIdx.y, b = blockIdx.z;

    const size_t hb = ((size_t)(b * NHEADS + h)) * S_LEN * HD;
    const __half* gqh = Qh + hb + (size_t)q0 * HD;
    const __half* gql = Ql + hb + (size_t)q0 * HD;
    const __half* gkh = Kh + hb;
    const __half* gvh = Vh + hb;

    // Q (128 rows x 256B), hi + lo
    {
        int r = tid >> 1, cb = (tid & 1) * 8;
        const char* g0 = (const char*)(gqh + (size_t)r * HD);
        const char* g1 = (const char*)(gql + (size_t)r * HD);
        uint32_t d0 = sQh + r * 256, d1 = sQl + r * 256;
        #pragma unroll
        for (int j = 0; j < 8; j++) {
            int c = cb + j;
            uint32_t sw = (uint32_t)((c ^ (r & 7)) << 4);
            cp16(d0 + sw, g0 + c * 16);
            cp16(d1 + sw, g1 + c * 16);
        }
    }
    auto ld_stage = [&](int t) {
        uint32_t base = sb0 + 65536 + (t % 3) * KV_STAGE_B;
        int s0 = t * BKV;
        int r = tid >> 3;          // 0..31
        int cb = (tid & 7) * 2;    // 0..14
        const char* gk = (const char*)(gkh + (size_t)(s0 + r) * HD);
        const char* gv = (const char*)(gvh + (size_t)(s0 + r) * HD);
        uint32_t dr = base + r * 256;
        #pragma unroll
        for (int j = 0; j < 2; j++) {
            int c = cb + j;
            uint32_t sw = (uint32_t)((c ^ (r & 7)) << 4);
            cp16(dr + sw,        gk + c * 16);
            cp16(dr + 8192 + sw, gv + c * 16);
        }
    };

    ld_stage(0); cp_commit();      // Q rides in group 0
    ld_stage(1); cp_commit();

    const int aq_row = wid * 16 + (lane & 15);
    const uint32_t aq_base = (uint32_t)(aq_row * 256);
    const int aq_r7 = aq_row & 7;
    const int aq_cx = lane >> 4;
    const int bk_row = (lane & 7) + ((lane >> 4) << 3);
    const int bk_cx = (lane >> 3) & 1;
    const int bv_row = (lane & 7) + (((lane >> 3) & 1) << 3);
    const int bv_cx = lane >> 4;

    float o[16][4];
    #pragma unroll
    for (int nt = 0; nt < 16; nt++) { o[nt][0]=o[nt][1]=o[nt][2]=o[nt][3]=0.f; }
    float mr1 = -CUDART_INF_F, mr2 = -CUDART_INF_F, lr1 = 0.f, lr2 = 0.f;

    const int NT = S_LEN / BKV;    // 64
    for (int t = 0; t < NT; t++) {
        cp_wait1();
        __syncthreads();
        if (t + 2 < NT) ld_stage(t + 2);
        cp_commit();

        uint32_t sK = sb0 + 65536 + (t % 3) * KV_STAGE_B;
        uint32_t sV = sK + 8192;

        // ---- S = Q.K^T (2 terms) ----
        float s[4][4];
        #pragma unroll
        for (int i = 0; i < 4; i++) { s[i][0]=s[i][1]=s[i][2]=s[i][3]=0.f; }

        #pragma unroll
        for (int kt = 0; kt < 8; kt++) {
            uint32_t ah4[4], al4[4];
            {
                int c16 = kt * 2 + aq_cx;
                uint32_t off = aq_base + (uint32_t)(((c16 ^ aq_r7)) << 4);
                ldsm4(ah4, sQh + off);
                ldsm4(al4, sQl + off);
            }
            #pragma unroll
            for (int np = 0; np < 2; np++) {
                int row = np * 16 + bk_row;
                int c16 = kt * 2 + bk_cx;
                uint32_t off = (uint32_t)(row * 256) + (uint32_t)(((c16 ^ (row & 7))) << 4);
                uint32_t bh4[4];
                ldsm4(bh4, sK + off);
                mma_f16(s[2*np],   ah4, bh4);
                mma_f16(s[2*np+1], ah4, bh4 + 2);
                mma_f16(s[2*np],   al4, bh4);
                mma_f16(s[2*np+1], al4, bh4 + 2);
            }
        }

        // ---- online softmax (rows r1 = lane>>2 and r1+8) ----
        float m1 = s[0][0], m2 = s[0][2];
        #pragma unroll
        for (int i = 0; i < 4; i++) {
            m1 = fmaxf(m1, fmaxf(s[i][0], s[i][1]));
            m2 = fmaxf(m2, fmaxf(s[i][2], s[i][3]));
        }
        m1 = fmaxf(m1, __shfl_xor_sync(0xffffffffu, m1, 1));
        m1 = fmaxf(m1, __shfl_xor_sync(0xffffffffu, m1, 2));
        m2 = fmaxf(m2, __shfl_xor_sync(0xffffffffu, m2, 1));
        m2 = fmaxf(m2, __shfl_xor_sync(0xffffffffu, m2, 2));
        float mn1 = fmaxf(mr1, m1), mn2 = fmaxf(mr2, m2);
        float a1 = __expf(mr1 - mn1), a2 = __expf(mr2 - mn2);
        mr1 = mn1; mr2 = mn2;
        float l1 = 0.f, l2 = 0.f;
        #pragma unroll
        for (int i = 0; i < 4; i++) {
            s[i][0] = __expf(s[i][0] - mn1); s[i][1] = __expf(s[i][1] - mn1);
            s[i][2] = __expf(s[i][2] - mn2); s[i][3] = __expf(s[i][3] - mn2);
            l1 += s[i][0] + s[i][1];
            l2 += s[i][2] + s[i][3];
        }
        l1 += __shfl_xor_sync(0xffffffffu, l1, 1);
        l1 += __shfl_xor_sync(0xffffffffu, l1, 2);
        l2 += __shfl_xor_sync(0xffffffffu, l2, 1);
        l2 += __shfl_xor_sync(0xffffffffu, l2, 2);
        lr1 = lr1 * a1 + l1;
        lr2 = lr2 * a2 + l2;
        #pragma unroll
        for (int nt = 0; nt < 16; nt++) {
            o[nt][0] *= a1; o[nt][1] *= a1; o[nt][2] *= a2; o[nt][3] *= a2;
        }

        // ---- pack P -> fp16 A-fragments (hi only) ----
        uint32_t ph[2][4];
        #pragma unroll
        for (int k2 = 0; k2 < 2; k2++) {
            ph[k2][0] = pack_h(s[2*k2][0],   s[2*k2][1]);
            ph[k2][1] = pack_h(s[2*k2][2],   s[2*k2][3]);
            ph[k2][2] = pack_h(s[2*k2+1][0], s[2*k2+1][1]);
            ph[k2][3] = pack_h(s[2*k2+1][2], s[2*k2+1][3]);
        }

        // ---- O += P.V (1 term), V via ldmatrix.trans ----
        #pragma unroll
        for (int k2 = 0; k2 < 2; k2++) {
            #pragma unroll
            for (int np = 0; np < 8; np++) {
                int row = k2 * 16 + bv_row;
                int c16 = np * 2 + bv_cx;
                uint32_t off = (uint32_t)(row * 256) + (uint32_t)(((c16 ^ (row & 7))) << 4);
                uint32_t v4[4];
                ldsm4t(v4, sV + off);
                mma_f16(o[2*np],   ph[k2], v4);
                mma_f16(o[2*np+1], ph[k2], v4 + 2);
            }
        }
    }

    // epilogue: normalize, write fp16
    float i1 = 1.f / lr1, i2 = 1.f / lr2;
    int r1 = lane >> 2, c2 = (lane & 3) * 2;
    size_t row1 = (size_t)b * S_LEN + q0 + wid * 16 + r1;
    size_t row2 = row1 + 8;
    #pragma unroll
    for (int nt = 0; nt < 16; nt++) {
        int col = h * HD + nt * 8 + c2;
        *(uint32_t*)(Oh + row1 * DIMM + col) = pack_h(o[nt][0] * i1, o[nt][1] * i1);
        *(uint32_t*)(Oh + row2 * DIMM + col) = pack_h(o[nt][2] * i2, o[nt][3] * i2);
    }
}

// ---------------------------------------------------------------------------
extern "C" void kernel_launch(void* const* d_in, const int* in_sizes, int n_in,
                              void* d_out, int out_size)
{
    const float* x     = (const float*)d_in[0];   // [2,2048,2048]
    const float* w_qkv = (const float*)d_in[1];   // [2048,6144]
    const float* w_out = (const float*)d_in[2];   // [2048,2048]
    float* out = (float*)d_out;                   // [2,2048,2048]

    __half *xh, *xl, *wqh, *woh, *ah, *qh, *ql, *kh, *vh;
    cudaGetSymbolAddress((void**)&xh, g_xh);
    cudaGetSymbolAddress((void**)&xl, g_xl);
    cudaGetSymbolAddress((void**)&wqh, g_wqT_h);
    cudaGetSymbolAddress((void**)&woh, g_woT_h);
    cudaGetSymbolAddress((void**)&ah, g_ah);
    cudaGetSymbolAddress((void**)&qh, g_qh);
    cudaGetSymbolAddress((void**)&ql, g_ql);
    cudaGetSymbolAddress((void**)&kh, g_kh);
    cudaGetSymbolAddress((void**)&vh, g_vh);

    const int SMEM2 = NSTAGE * 3 * TILE_B;   // 98304 (2-term)
    const int SMEM1 = NSTAGE * 2 * TILE_B;   // 65536 (1-term)
    cudaFuncSetAttribute(gemm_mma<2, true>,
                         cudaFuncAttributeMaxDynamicSharedMemorySize, SMEM2);
    cudaFuncSetAttribute(gemm_mma<1, true>,
                         cudaFuncAttributeMaxDynamicSharedMemorySize, SMEM1);
    cudaFuncSetAttribute(gemm_mma<1, false>,
                         cudaFuncAttributeMaxDynamicSharedMemorySize, SMEM1);
    cudaFuncSetAttribute(attn_mma,
                         cudaFuncAttributeMaxDynamicSharedMemorySize, ATT_SMEM);

    // split x -> fp16 hi/lo
    {
        int n4 = (MROWS * DIMM) / 4;
        split_kernel<<<(n4 + 255) / 256, 256>>>(x, xh, xl, n4);
    }
    // transpose weights -> fp16 hi only
    {
        dim3 tb(32, 8);
        transpose_half<<<dim3(QKV_W / 32, DIMM / 32), tb>>>(w_qkv, wqh, DIMM, QKV_W);
        transpose_half<<<dim3(DIMM / 32, DIMM / 32), tb>>>(w_out, woh, DIMM, DIMM);
    }
    // 1a) Q projection (2-term, full precision into hi/lo, scaled)
    gemm_mma<2, true><<<dim3(2048 / 128, MROWS / 128), 256, SMEM2>>>(
        xh, xl, wqh, nullptr, qh, ql, nullptr, nullptr,
        0, MROWS, 2048, DIMM);
    // 1b) K/V projection (1-term — outputs are fp16-quantized anyway)
    gemm_mma<1, true><<<dim3(4096 / 128, MROWS / 128), 256, SMEM1>>>(
        xh, nullptr, wqh + (size_t)2048 * DIMM, nullptr,
        nullptr, nullptr, kh, vh,
        2048, MROWS, 4096, DIMM);

    // 2) Attention -> writes fp16 O
    {
        dim3 grid(S_LEN / 128, NHEADS, BATCH);
        attn_mma<<<grid, 256, ATT_SMEM>>>(qh, ql, kh, vh, ah);
    }

    // 3) Output projection -> fp32 out (1-term: O is fp16-quantized anyway)
    gemm_mma<1, false><<<dim3(DIMM / 128, MROWS / 128), 256, SMEM1>>>(
        ah, nullptr, woh, out, nullptr, nullptr, nullptr, nullptr,
        0, MROWS, DIMM, DIMM);
}